// round 1
// baseline (speedup 1.0000x reference)
#include <cuda_runtime.h>

// ---------------------------------------------------------------------------
// SWMSA: Swin shifted-window multi-head self-attention
//   B=32, H=W=56, E=256, NH=8, HD=32, WS=7, WD=49, NW=64, SS=3
// Kernel 1: per-(batch,window) attention (all heads), writes shift-reversed
//           per-head outputs into g_mid (B, H*W, E).
// Kernel 2: out = g_mid @ proj_w + proj_b   (100352 x 256 x 256 SGEMM)
// ---------------------------------------------------------------------------

#define BATCH   32
#define HWPIX   3136
#define EDIM    256
#define NHEADS  8
#define HDIM    32
#define WD      49
#define SCALE   0.17677669529663687f   // 1/sqrt(32)

// scratch for attention output (pre-projection), 102.76 MB static global
__device__ float g_mid[(size_t)BATCH * HWPIX * EDIM];

// shared memory layout for attention kernel (float offsets)
#define OFF_W    0        // 32*96 = 3072
#define OFF_B    3072     // 96
#define OFF_RPB  3168     // 169*8 = 1352
#define OFF_XH   4520     // 49*36 = 1764
#define OFF_Q    6284     // 1764
#define OFF_K    8048     // 1764
#define OFF_V    9812     // 1764
#define OFF_S    11576    // 49*52 = 2548
#define OFF_PIX  14124    // 49 ints
#define OFF_REG  14173    // 49 ints
#define SMEM_FLOATS 14224
#define SMEM_BYTES  (SMEM_FLOATS * 4)

__global__ void __launch_bounds__(256, 4)
swin_attn_kernel(const float* __restrict__ x,
                 const float* __restrict__ qkv_w,
                 const float* __restrict__ qkv_b,
                 const float* __restrict__ rpb_table)
{
    extern __shared__ float sm[];
    float* w_s  = sm + OFF_W;
    float* b_s  = sm + OFF_B;
    float* rpb  = sm + OFF_RPB;
    float* xh   = sm + OFF_XH;
    float* qs   = sm + OFF_Q;
    float* ks   = sm + OFF_K;
    float* vs   = sm + OFF_V;
    float* ss   = sm + OFF_S;
    int*   pix  = (int*)(sm + OFF_PIX);
    int*   regi = (int*)(sm + OFF_REG);

    const int tid = threadIdx.x;
    const int bi  = blockIdx.x;
    const int b   = bi >> 6;        // batch
    const int w   = bi & 63;        // window id
    const int wr  = w >> 3, wc = w & 7;

    // ---- stage 0: weights / tables / pixel + region LUTs ----
    for (int i = tid; i < 768; i += 256)
        ((float4*)w_s)[i] = ((const float4*)qkv_w)[i];
    if (tid < 24)
        ((float4*)b_s)[tid] = ((const float4*)qkv_b)[tid];
    for (int i = tid; i < 338; i += 256)
        ((float4*)rpb)[i] = ((const float4*)rpb_table)[i];
    if (tid < WD) {
        int tr = tid / 7, tc = tid - tr * 7;
        int hh = wr * 7 + tr, ww = wc * 7 + tc;       // unshifted window coords
        int sh = hh + 3; if (sh >= 56) sh -= 56;      // cyclic shift source pixel
        int sw = ww + 3; if (sw >= 56) sw -= 56;
        pix[tid] = sh * 56 + sw;
        int rh = (hh < 49) ? 0 : ((hh < 53) ? 1 : 2); // region id (mask)
        int rw = (ww < 49) ? 0 : ((ww < 53) ? 1 : 2);
        regi[tid] = rh * 3 + rw;
    }
    __syncthreads();

    const float* xb = x + (size_t)b * HWPIX * EDIM;
    float*       ob = g_mid + (size_t)b * HWPIX * EDIM;

    for (int h = 0; h < NHEADS; h++) {
        // ---- stage A: load per-head x slice (49 x 32), pad-36 rows ----
        for (int i4 = tid; i4 < 392; i4 += 256) {
            int t  = i4 >> 3;
            int d4 = (i4 & 7) << 2;
            float4 v4 = *(const float4*)&xb[pix[t] * EDIM + h * HDIM + d4];
            *(float4*)&xh[t * 36 + d4] = v4;
        }
        __syncthreads();

        // ---- stage B: qkv = xh @ W (32x96) + b ; 49*24 float4-column groups ----
        for (int idx = tid; idx < 1176; idx += 256) {
            int t  = idx / 24;
            int jq = idx - t * 24;
            int j  = jq << 2;
            float4 acc = *(const float4*)&b_s[j];
            #pragma unroll
            for (int d4 = 0; d4 < 32; d4 += 4) {
                float4 xv = *(const float4*)&xh[t * 36 + d4];
                const float* wp = &w_s[d4 * 96 + j];
                float4 w0 = *(const float4*)(wp);
                float4 w1 = *(const float4*)(wp + 96);
                float4 w2 = *(const float4*)(wp + 192);
                float4 w3 = *(const float4*)(wp + 288);
                acc.x = fmaf(xv.x, w0.x, acc.x);
                acc.y = fmaf(xv.x, w0.y, acc.y);
                acc.z = fmaf(xv.x, w0.z, acc.z);
                acc.w = fmaf(xv.x, w0.w, acc.w);
                acc.x = fmaf(xv.y, w1.x, acc.x);
                acc.y = fmaf(xv.y, w1.y, acc.y);
                acc.z = fmaf(xv.y, w1.z, acc.z);
                acc.w = fmaf(xv.y, w1.w, acc.w);
                acc.x = fmaf(xv.z, w2.x, acc.x);
                acc.y = fmaf(xv.z, w2.y, acc.y);
                acc.z = fmaf(xv.z, w2.z, acc.z);
                acc.w = fmaf(xv.z, w2.w, acc.w);
                acc.x = fmaf(xv.w, w3.x, acc.x);
                acc.y = fmaf(xv.w, w3.y, acc.y);
                acc.z = fmaf(xv.w, w3.z, acc.z);
                acc.w = fmaf(xv.w, w3.w, acc.w);
            }
            float* dst;
            int jl;
            if (j < 32)      { dst = qs; jl = j; }
            else if (j < 64) { dst = ks; jl = j - 32; }
            else             { dst = vs; jl = j - 64; }
            *(float4*)&dst[t * 36 + jl] = acc;
        }
        __syncthreads();

        // ---- stage C: scores = q k^T * scale + bias + mask ----
        for (int o = tid; o < 2401; o += 256) {
            int i = o / 49;
            int j = o - i * 49;
            float acc = 0.f;
            #pragma unroll
            for (int d4 = 0; d4 < 32; d4 += 4) {
                float4 qv = *(const float4*)&qs[i * 36 + d4];
                float4 kv = *(const float4*)&ks[j * 36 + d4];
                acc = fmaf(qv.x, kv.x, acc);
                acc = fmaf(qv.y, kv.y, acc);
                acc = fmaf(qv.z, kv.z, acc);
                acc = fmaf(qv.w, kv.w, acc);
            }
            int ri = i / 7, ci = i - ri * 7;
            int rj = j / 7, cj = j - rj * 7;
            int bidx = ((ri - rj + 6) * 13 + (ci - cj + 6)) * 8 + h;
            float mval = (regi[i] != regi[j]) ? -100.0f : 0.0f;
            ss[i * 52 + j] = fmaf(acc, SCALE, rpb[bidx] + mval);
        }
        __syncthreads();

        // ---- stage D: row softmax (one warp per row, rows strided by 8) ----
        {
            int warp = tid >> 5, lane = tid & 31;
            for (int i = warp; i < WD; i += 8) {
                float v0 = ss[i * 52 + lane];
                float v1 = (lane < 17) ? ss[i * 52 + 32 + lane] : -1e30f;
                float m = fmaxf(v0, v1);
                #pragma unroll
                for (int o = 16; o; o >>= 1)
                    m = fmaxf(m, __shfl_xor_sync(0xffffffffu, m, o));
                float e0 = __expf(v0 - m);
                float e1 = (lane < 17) ? __expf(v1 - m) : 0.f;
                float s2 = e0 + e1;
                #pragma unroll
                for (int o = 16; o; o >>= 1)
                    s2 += __shfl_xor_sync(0xffffffffu, s2, o);
                float inv = __frcp_rn(s2);
                ss[i * 52 + lane] = e0 * inv;
                if (lane < 17) ss[i * 52 + 32 + lane] = e1 * inv;
            }
        }
        __syncthreads();

        // ---- stage E: o = attn @ v, store shift-reversed to g_mid ----
        for (int i4 = tid; i4 < 392; i4 += 256) {
            int t  = i4 >> 3;
            int d4 = (i4 & 7) << 2;
            float4 acc = make_float4(0.f, 0.f, 0.f, 0.f);
            #pragma unroll 7
            for (int j = 0; j < WD; j++) {
                float  sv = ss[t * 52 + j];
                float4 vv = *(const float4*)&vs[j * 36 + d4];
                acc.x = fmaf(sv, vv.x, acc.x);
                acc.y = fmaf(sv, vv.y, acc.y);
                acc.z = fmaf(sv, vv.z, acc.z);
                acc.w = fmaf(sv, vv.w, acc.w);
            }
            *(float4*)&ob[pix[t] * EDIM + h * HDIM + d4] = acc;
        }
        __syncthreads();
    }
}

// ---------------------------------------------------------------------------
// Projection SGEMM: out[M,N] = g_mid[M,K] @ proj_w[K,N] + proj_b
//   M = 100352, K = N = 256.  Block tile 128x64, 256 threads, 8x4 per thread.
// ---------------------------------------------------------------------------
__global__ void __launch_bounds__(256)
swin_proj_kernel(const float* __restrict__ Wp,
                 const float* __restrict__ pb,
                 float* __restrict__ out)
{
    __shared__ float As[16 * 128];   // transposed: As[k][m]
    __shared__ float Bs[16 * 64];    // Bs[k][n]

    const int tid = threadIdx.x;
    const int tx  = tid & 15;        // n-group
    const int ty  = tid >> 4;        // m-group
    const int rowBase = blockIdx.x * 128;
    const int nBase   = blockIdx.y * 64;
    const int n0      = nBase + tx * 4;
    const float* A = g_mid;

    float acc[8][4];
    #pragma unroll
    for (int i = 0; i < 8; i++)
        #pragma unroll
        for (int j = 0; j < 4; j++)
            acc[i][j] = 0.f;

    for (int k0 = 0; k0 < 256; k0 += 16) {
        // load A tile 128x16 (transposed into As[k][m])
        #pragma unroll
        for (int l = 0; l < 2; l++) {
            int flat = tid + l * 256;
            int m    = flat >> 2;
            int kc   = (flat & 3) << 2;
            float4 av = *(const float4*)&A[(size_t)(rowBase + m) * 256 + k0 + kc];
            As[(kc + 0) * 128 + m] = av.x;
            As[(kc + 1) * 128 + m] = av.y;
            As[(kc + 2) * 128 + m] = av.z;
            As[(kc + 3) * 128 + m] = av.w;
        }
        // load B tile 16x64
        {
            int kk = tid >> 4;
            int nc = (tid & 15) << 2;
            *(float4*)&Bs[kk * 64 + nc] =
                *(const float4*)&Wp[(size_t)(k0 + kk) * 256 + nBase + nc];
        }
        __syncthreads();

        #pragma unroll
        for (int kk = 0; kk < 16; kk++) {
            float4 a0 = *(const float4*)&As[kk * 128 + ty * 8];
            float4 a1 = *(const float4*)&As[kk * 128 + ty * 8 + 4];
            float4 b0 = *(const float4*)&Bs[kk * 64 + tx * 4];
            float av[8] = {a0.x, a0.y, a0.z, a0.w, a1.x, a1.y, a1.z, a1.w};
            #pragma unroll
            for (int i = 0; i < 8; i++) {
                acc[i][0] = fmaf(av[i], b0.x, acc[i][0]);
                acc[i][1] = fmaf(av[i], b0.y, acc[i][1]);
                acc[i][2] = fmaf(av[i], b0.z, acc[i][2]);
                acc[i][3] = fmaf(av[i], b0.w, acc[i][3]);
            }
        }
        __syncthreads();
    }

    float4 bv = *(const float4*)&pb[n0];
    #pragma unroll
    for (int i = 0; i < 8; i++) {
        float4 r;
        r.x = acc[i][0] + bv.x;
        r.y = acc[i][1] + bv.y;
        r.z = acc[i][2] + bv.z;
        r.w = acc[i][3] + bv.w;
        *(float4*)&out[(size_t)(rowBase + ty * 8 + i) * 256 + n0] = r;
    }
}

extern "C" void kernel_launch(void* const* d_in, const int* in_sizes, int n_in,
                              void* d_out, int out_size)
{
    (void)in_sizes; (void)n_in; (void)out_size;
    const float* x      = (const float*)d_in[0];
    const float* qkv_w  = (const float*)d_in[1];
    const float* qkv_b  = (const float*)d_in[2];
    const float* proj_w = (const float*)d_in[3];
    const float* proj_b = (const float*)d_in[4];
    const float* rpb    = (const float*)d_in[5];
    float* out = (float*)d_out;

    cudaFuncSetAttribute(swin_attn_kernel,
                         cudaFuncAttributeMaxDynamicSharedMemorySize, SMEM_BYTES);

    swin_attn_kernel<<<BATCH * 64, 256, SMEM_BYTES>>>(x, qkv_w, qkv_b, rpb);
    swin_proj_kernel<<<dim3(100352 / 128, 4), 256>>>(proj_w, proj_b, out);
}

// round 2
// speedup vs baseline: 1.4169x; 1.4169x over previous
#include <cuda_runtime.h>
#include <cstdint>

// ---------------------------------------------------------------------------
// SWMSA: B=32, H=W=56, E=256, NH=8, HD=32, WS=7, WD=49, NW=64, SS=3
// K1: per-(batch,window) attention, register-blocked fp32, -> g_mid
// K2: out = g_mid @ proj_w + proj_b via tf32 mma.sync (100352x256x256)
// ---------------------------------------------------------------------------

#define BATCH   32
#define HWPIX   3136
#define EDIM    256
#define WD      49
#define SCALE   0.17677669529663687f   // 1/sqrt(32)

__device__ float g_mid[(size_t)BATCH * HWPIX * EDIM];

// shared layout (float offsets) for attention kernel
#define OFF_W    0        // 32*96
#define OFF_B    3072     // 96
#define OFF_RPB  3168     // 169*8
#define OFF_XH   4520     // 49*36
#define OFF_Q    6284     // 49*36
#define OFF_K    8048     // 49*36
#define OFF_V    9812     // 49*36
#define OFF_S    11576    // 49*52
#define OFF_PIX  14124    // 49 ints
#define OFF_LIN  14173    // 49 ints
#define OFF_REG  14222    // 49 ints
#define SMEM_FLOATS 14271
#define SMEM_BYTES  (SMEM_FLOATS * 4)

#define FMA4(acc, s, v)                      \
    acc.x = fmaf(s, v.x, acc.x);             \
    acc.y = fmaf(s, v.y, acc.y);             \
    acc.z = fmaf(s, v.z, acc.z);             \
    acc.w = fmaf(s, v.w, acc.w)

__device__ __forceinline__ float dot4acc(float4 a, float4 b, float s) {
    s = fmaf(a.x, b.x, s);
    s = fmaf(a.y, b.y, s);
    s = fmaf(a.z, b.z, s);
    s = fmaf(a.w, b.w, s);
    return s;
}

__global__ void __launch_bounds__(256, 3)
swin_attn_kernel(const float* __restrict__ x,
                 const float* __restrict__ qkv_w,
                 const float* __restrict__ qkv_b,
                 const float* __restrict__ rpb_table)
{
    extern __shared__ float sm[];
    float* w_s  = sm + OFF_W;
    float* b_s  = sm + OFF_B;
    float* rpb  = sm + OFF_RPB;
    float* xh   = sm + OFF_XH;
    float* qs   = sm + OFF_Q;
    float* ks   = sm + OFF_K;
    float* vs   = sm + OFF_V;
    float* ss   = sm + OFF_S;
    int*   pix  = (int*)(sm + OFF_PIX);
    int*   lin  = (int*)(sm + OFF_LIN);
    int*   regi = (int*)(sm + OFF_REG);

    const int tid = threadIdx.x;
    const int bi  = blockIdx.x;
    const int b   = bi >> 6;
    const int w   = bi & 63;
    const int wr  = w >> 3, wc = w & 7;

    // ---- stage 0: weights / tables / LUTs ----
    for (int i = tid; i < 768; i += 256)
        ((float4*)w_s)[i] = ((const float4*)qkv_w)[i];
    if (tid < 24)
        ((float4*)b_s)[tid] = ((const float4*)qkv_b)[tid];
    for (int i = tid; i < 338; i += 256)
        ((float4*)rpb)[i] = ((const float4*)rpb_table)[i];
    if (tid < WD) {
        int tr = tid / 7, tc = tid - tr * 7;
        int hh = wr * 7 + tr, ww = wc * 7 + tc;
        int sh = hh + 3; if (sh >= 56) sh -= 56;
        int sw = ww + 3; if (sw >= 56) sw -= 56;
        pix[tid] = sh * 56 + sw;
        lin[tid] = tr * 13 + tc;
        int rh = (hh < 49) ? 0 : ((hh < 53) ? 1 : 2);
        int rw = (ww < 49) ? 0 : ((ww < 53) ? 1 : 2);
        regi[tid] = rh * 3 + rw;
    }
    __syncthreads();

    const float* xb = x + (size_t)b * HWPIX * EDIM;
    float*       ob = g_mid + (size_t)b * HWPIX * EDIM;

    for (int h = 0; h < 8; h++) {
        // ---- stage A: load per-head x slice (49 x 32), pad-36 rows ----
        for (int i4 = tid; i4 < 392; i4 += 256) {
            int t  = i4 >> 3;
            int d4 = (i4 & 7) << 2;
            float4 v4 = *(const float4*)&xb[pix[t] * EDIM + (h << 5) + d4];
            *(float4*)&xh[t * 36 + d4] = v4;
        }
        __syncthreads();

        // ---- stage B: qkv = xh @ W + b, 2-token x 2-col4 register blocks ----
        for (int it = tid; it < 300; it += 256) {
            int tp = it / 12, cg = it - tp * 12;
            int t0 = tp, t1 = tp + 25;       // t1==49 -> junk row (stores guarded)
            int j  = cg << 3;
            float4 bias0 = *(const float4*)&b_s[j];
            float4 bias1 = *(const float4*)&b_s[j + 4];
            float4 a00 = bias0, a01 = bias1, a10 = bias0, a11 = bias1;
            #pragma unroll
            for (int d4 = 0; d4 < 32; d4 += 4) {
                float4 x0 = *(const float4*)&xh[t0 * 36 + d4];
                float4 x1 = *(const float4*)&xh[t1 * 36 + d4];
                float xs0[4] = {x0.x, x0.y, x0.z, x0.w};
                float xs1[4] = {x1.x, x1.y, x1.z, x1.w};
                #pragma unroll
                for (int dd = 0; dd < 4; dd++) {
                    const float* wp = &w_s[(d4 + dd) * 96 + j];
                    float4 wa = *(const float4*)wp;
                    float4 wb = *(const float4*)(wp + 4);
                    FMA4(a00, xs0[dd], wa);
                    FMA4(a01, xs0[dd], wb);
                    FMA4(a10, xs1[dd], wa);
                    FMA4(a11, xs1[dd], wb);
                }
            }
            float* dst; int jl;
            if (j < 32)      { dst = qs; jl = j; }
            else if (j < 64) { dst = ks; jl = j - 32; }
            else             { dst = vs; jl = j - 64; }
            *(float4*)&dst[t0 * 36 + jl]     = a00;
            *(float4*)&dst[t0 * 36 + jl + 4] = a01;
            if (t1 < WD) {
                *(float4*)&dst[t1 * 36 + jl]     = a10;
                *(float4*)&dst[t1 * 36 + jl + 4] = a11;
            }
        }
        __syncthreads();

        // ---- stage C: scores = q k^T * scale + bias + mask, 2x2 blocks ----
        for (int it = tid; it < 625; it += 256) {
            int ip = it / 25, jp = it - ip * 25;
            int i0 = ip, i1 = ip + 25, j0 = jp, j1 = jp + 25;
            float s00 = 0.f, s01 = 0.f, s10 = 0.f, s11 = 0.f;
            #pragma unroll
            for (int d4 = 0; d4 < 32; d4 += 4) {
                float4 q0 = *(const float4*)&qs[i0 * 36 + d4];
                float4 q1 = *(const float4*)&qs[i1 * 36 + d4];
                float4 k0 = *(const float4*)&ks[j0 * 36 + d4];
                float4 k1 = *(const float4*)&ks[j1 * 36 + d4];
                s00 = dot4acc(q0, k0, s00);
                s01 = dot4acc(q0, k1, s01);
                s10 = dot4acc(q1, k0, s10);
                s11 = dot4acc(q1, k1, s11);
            }
            int li0 = lin[i0], gi0 = regi[i0];
            int lj0 = lin[j0], gj0 = regi[j0];
            ss[i0 * 52 + j0] = fmaf(s00, SCALE,
                rpb[(li0 - lj0 + 84) * 8 + h] + ((gi0 != gj0) ? -100.0f : 0.0f));
            if (j1 < WD) {
                int lj1 = lin[j1], gj1 = regi[j1];
                ss[i0 * 52 + j1] = fmaf(s01, SCALE,
                    rpb[(li0 - lj1 + 84) * 8 + h] + ((gi0 != gj1) ? -100.0f : 0.0f));
            }
            if (i1 < WD) {
                int li1 = lin[i1], gi1 = regi[i1];
                ss[i1 * 52 + j0] = fmaf(s10, SCALE,
                    rpb[(li1 - lj0 + 84) * 8 + h] + ((gi1 != gj0) ? -100.0f : 0.0f));
                if (j1 < WD) {
                    int lj1 = lin[j1], gj1 = regi[j1];
                    ss[i1 * 52 + j1] = fmaf(s11, SCALE,
                        rpb[(li1 - lj1 + 84) * 8 + h] + ((gi1 != gj1) ? -100.0f : 0.0f));
                }
            }
        }
        __syncthreads();

        // ---- stage D: row softmax (one warp per row) ----
        {
            int warp = tid >> 5, lane = tid & 31;
            for (int i = warp; i < WD; i += 8) {
                float v0 = ss[i * 52 + lane];
                float v1 = (lane < 17) ? ss[i * 52 + 32 + lane] : -1e30f;
                float m = fmaxf(v0, v1);
                #pragma unroll
                for (int o = 16; o; o >>= 1)
                    m = fmaxf(m, __shfl_xor_sync(0xffffffffu, m, o));
                float e0 = __expf(v0 - m);
                float e1 = (lane < 17) ? __expf(v1 - m) : 0.f;
                float s2 = e0 + e1;
                #pragma unroll
                for (int o = 16; o; o >>= 1)
                    s2 += __shfl_xor_sync(0xffffffffu, s2, o);
                float inv = __frcp_rn(s2);
                ss[i * 52 + lane] = e0 * inv;
                if (lane < 17) ss[i * 52 + 32 + lane] = e1 * inv;
            }
        }
        __syncthreads();

        // ---- stage E: o = attn @ v, 2-token blocks, shift-reversed store ----
        for (int it = tid; it < 200; it += 256) {
            int tp = it >> 3, c = it & 7;
            int t0 = tp, t1 = tp + 25, d4 = c << 2;
            float4 a0 = make_float4(0.f, 0.f, 0.f, 0.f);
            float4 a1 = make_float4(0.f, 0.f, 0.f, 0.f);
            #pragma unroll 7
            for (int j = 0; j < WD; j++) {
                float  s0 = ss[t0 * 52 + j];
                float  s1 = ss[t1 * 52 + j];   // t1==49 reads LUT region: junk, discarded
                float4 vv = *(const float4*)&vs[j * 36 + d4];
                FMA4(a0, s0, vv);
                FMA4(a1, s1, vv);
            }
            *(float4*)&ob[pix[t0] * EDIM + (h << 5) + d4] = a0;
            if (t1 < WD)
                *(float4*)&ob[pix[t1] * EDIM + (h << 5) + d4] = a1;
        }
        __syncthreads();
    }
}

// ---------------------------------------------------------------------------
// Projection: out[M,N] = g_mid[M,256] @ proj_w[256,256] + proj_b
// tf32 mma.sync, block tile 128x64, 8 warps (4m x 2n), warp tile 32x32.
// cp.async double-buffered K-chunks of 32.
// ---------------------------------------------------------------------------

__device__ __forceinline__ void cpasync16(uint32_t s, const void* g) {
    asm volatile("cp.async.cg.shared.global [%0], [%1], 16;\n"
                 :: "r"(s), "l"(g) : "memory");
}
__device__ __forceinline__ uint32_t f2tf32(float f) {
    uint32_t u;
    asm("cvt.rna.tf32.f32 %0, %1;" : "=r"(u) : "f"(f));
    return u;
}
__device__ __forceinline__ void mma_tf32(float* c, const uint32_t* a, const uint32_t* b) {
    asm volatile(
        "mma.sync.aligned.m16n8k8.row.col.f32.tf32.tf32.f32 "
        "{%0,%1,%2,%3}, {%4,%5,%6,%7}, {%8,%9}, {%0,%1,%2,%3};\n"
        : "+f"(c[0]), "+f"(c[1]), "+f"(c[2]), "+f"(c[3])
        : "r"(a[0]), "r"(a[1]), "r"(a[2]), "r"(a[3]), "r"(b[0]), "r"(b[1]));
}

// smem floats: A tile 128x36, B tile 32x72, double buffered
#define PJ_ABUF   4608                  // 128*36
#define PJ_STRIDE 6912                  // 4608 + 32*72
#define PJ_SMEM_BYTES (PJ_STRIDE * 2 * 4)

__global__ void __launch_bounds__(256)
swin_proj_kernel(const float* __restrict__ Wp,
                 const float* __restrict__ pb,
                 float* __restrict__ out)
{
    extern __shared__ float psm[];
    const int tid  = threadIdx.x;
    const int lane = tid & 31;
    const int warp = tid >> 5;
    const int mW = (warp >> 1) << 5;   // 0..96
    const int nW = (warp & 1) << 5;    // 0,32
    const int rowBase = blockIdx.y << 7;
    const int nBase   = blockIdx.x << 6;
    const float* A = g_mid;
    const uint32_t sbase = (uint32_t)__cvta_generic_to_shared(psm);

    float acc[2][4][4];
    #pragma unroll
    for (int mt = 0; mt < 2; mt++)
        #pragma unroll
        for (int nt = 0; nt < 4; nt++)
            #pragma unroll
            for (int i = 0; i < 4; i++)
                acc[mt][nt][i] = 0.f;

    // prologue: load chunk 0 into buffer 0
    {
        #pragma unroll
        for (int l = 0; l < 4; l++) {
            int idx = tid + (l << 8);
            int row = idx >> 3, c4 = (idx & 7) << 2;
            cpasync16(sbase + ((row * 36 + c4) << 2),
                      &A[(size_t)(rowBase + row) * 256 + c4]);
        }
        #pragma unroll
        for (int l = 0; l < 2; l++) {
            int idx = tid + (l << 8);
            int row = idx >> 4, c4 = (idx & 15) << 2;
            cpasync16(sbase + ((PJ_ABUF + row * 72 + c4) << 2),
                      &Wp[(size_t)row * 256 + nBase + c4]);
        }
        asm volatile("cp.async.commit_group;\n" ::: "memory");
    }

    for (int kc = 0; kc < 8; kc++) {
        int buf = kc & 1;
        asm volatile("cp.async.wait_group 0;\n" ::: "memory");
        __syncthreads();
        if (kc < 7) {
            int fb = (buf ^ 1) * PJ_STRIDE;
            int k0 = (kc + 1) << 5;
            #pragma unroll
            for (int l = 0; l < 4; l++) {
                int idx = tid + (l << 8);
                int row = idx >> 3, c4 = (idx & 7) << 2;
                cpasync16(sbase + ((fb + row * 36 + c4) << 2),
                          &A[(size_t)(rowBase + row) * 256 + k0 + c4]);
            }
            #pragma unroll
            for (int l = 0; l < 2; l++) {
                int idx = tid + (l << 8);
                int row = idx >> 4, c4 = (idx & 15) << 2;
                cpasync16(sbase + ((fb + PJ_ABUF + row * 72 + c4) << 2),
                          &Wp[(size_t)(k0 + row) * 256 + nBase + c4]);
            }
            asm volatile("cp.async.commit_group;\n" ::: "memory");
        }

        const float* As = psm + buf * PJ_STRIDE;
        const float* Bs = As + PJ_ABUF;
        const int r  = lane >> 2;
        const int cc = lane & 3;
        #pragma unroll
        for (int ks = 0; ks < 32; ks += 8) {
            uint32_t a[2][4], bb[4][2];
            #pragma unroll
            for (int mt = 0; mt < 2; mt++) {
                int rb = mW + (mt << 4) + r;
                a[mt][0] = f2tf32(As[rb * 36 + ks + cc]);
                a[mt][1] = f2tf32(As[(rb + 8) * 36 + ks + cc]);
                a[mt][2] = f2tf32(As[rb * 36 + ks + cc + 4]);
                a[mt][3] = f2tf32(As[(rb + 8) * 36 + ks + cc + 4]);
            }
            #pragma unroll
            for (int nt = 0; nt < 4; nt++) {
                int n = nW + (nt << 3) + r;
                bb[nt][0] = f2tf32(Bs[(ks + cc) * 72 + n]);
                bb[nt][1] = f2tf32(Bs[(ks + cc + 4) * 72 + n]);
            }
            #pragma unroll
            for (int mt = 0; mt < 2; mt++)
                #pragma unroll
                for (int nt = 0; nt < 4; nt++)
                    mma_tf32(acc[mt][nt], a[mt], bb[nt]);
        }
        __syncthreads();
    }

    // epilogue
    #pragma unroll
    for (int mt = 0; mt < 2; mt++) {
        int row = rowBase + mW + (mt << 4) + (lane >> 2);
        #pragma unroll
        for (int nt = 0; nt < 4; nt++) {
            int col = nBase + nW + (nt << 3) + ((lane & 3) << 1);
            float b0 = pb[col], b1 = pb[col + 1];
            float2 v0 = make_float2(acc[mt][nt][0] + b0, acc[mt][nt][1] + b1);
            float2 v1 = make_float2(acc[mt][nt][2] + b0, acc[mt][nt][3] + b1);
            *(float2*)&out[(size_t)row * 256 + col]       = v0;
            *(float2*)&out[(size_t)(row + 8) * 256 + col] = v1;
        }
    }
}

extern "C" void kernel_launch(void* const* d_in, const int* in_sizes, int n_in,
                              void* d_out, int out_size)
{
    (void)in_sizes; (void)n_in; (void)out_size;
    const float* x      = (const float*)d_in[0];
    const float* qkv_w  = (const float*)d_in[1];
    const float* qkv_b  = (const float*)d_in[2];
    const float* proj_w = (const float*)d_in[3];
    const float* proj_b = (const float*)d_in[4];
    const float* rpb    = (const float*)d_in[5];
    float* out = (float*)d_out;

    cudaFuncSetAttribute(swin_attn_kernel,
                         cudaFuncAttributeMaxDynamicSharedMemorySize, SMEM_BYTES);
    cudaFuncSetAttribute(swin_proj_kernel,
                         cudaFuncAttributeMaxDynamicSharedMemorySize, PJ_SMEM_BYTES);

    swin_attn_kernel<<<BATCH * 64, 256, SMEM_BYTES>>>(x, qkv_w, qkv_b, rpb);
    swin_proj_kernel<<<dim3(4, 784), 256, PJ_SMEM_BYTES>>>(proj_w, proj_b, out);
}

// round 3
// speedup vs baseline: 2.4877x; 1.7557x over previous
#include <cuda_runtime.h>
#include <cstdint>

// ---------------------------------------------------------------------------
// SWMSA: B=32, H=W=56, E=256, NH=8, HD=32, WS=7, WD=49, NW=64, SS=3
// K1: per-(batch,window) attention via tf32 mma.sync (tokens padded 49->64)
// K2: out = g_mid @ proj_w + proj_b via tf32 mma.sync (100352x256x256)
// ---------------------------------------------------------------------------

#define BATCH   32
#define HWPIX   3136
#define EDIM    256
#define WD      49
#define SCALE   0.17677669529663687f   // 1/sqrt(32)

__device__ float g_mid[(size_t)BATCH * HWPIX * EDIM];

__device__ __forceinline__ uint32_t f2tf32(float f) {
    uint32_t u;
    asm("cvt.rna.tf32.f32 %0, %1;" : "=r"(u) : "f"(f));
    return u;
}
__device__ __forceinline__ float tf32f(float f) {
    return __uint_as_float(f2tf32(f));
}
__device__ __forceinline__ void mma_tf32(float* c, const uint32_t* a, const uint32_t* b) {
    asm volatile(
        "mma.sync.aligned.m16n8k8.row.col.f32.tf32.tf32.f32 "
        "{%0,%1,%2,%3}, {%4,%5,%6,%7}, {%8,%9}, {%0,%1,%2,%3};\n"
        : "+f"(c[0]), "+f"(c[1]), "+f"(c[2]), "+f"(c[3])
        : "r"(a[0]), "r"(a[1]), "r"(a[2]), "r"(a[3]), "r"(b[0]), "r"(b[1]));
}

// ---------------- attention kernel ----------------
// smem layout (float offsets)
#define OFF_W    0        // 32 x 100 (k-major qkv weights, tf32)
#define OFF_B    3200     // 96
#define OFF_RPB  3296     // 169*8
#define OFF_X    4648     // 64 x 36  (tf32, rows 49..63 zero)
#define OFF_QKV  6952     // 64 x 100 (Q 0..31 scaled | K 32..63 | V 64..95, tf32)
#define OFF_S    13352    // 64 x 68  (raw scores -> probs tf32, pad cols zeroed)
#define OFF_PIX  17704
#define OFF_LIN  17753
#define OFF_REG  17802
#define SMEM_FLOATS 17856
#define SMEM_BYTES  (SMEM_FLOATS * 4)

__global__ void __launch_bounds__(256)
swin_attn_kernel(const float* __restrict__ x,
                 const float* __restrict__ qkv_w,
                 const float* __restrict__ qkv_b,
                 const float* __restrict__ rpb_table)
{
    extern __shared__ float sm[];
    float* w_s  = sm + OFF_W;
    float* b_s  = sm + OFF_B;
    float* rpb  = sm + OFF_RPB;
    float* xh   = sm + OFF_X;
    float* qkv  = sm + OFF_QKV;
    float* ss   = sm + OFF_S;
    int*   pix  = (int*)(sm + OFF_PIX);
    int*   lin  = (int*)(sm + OFF_LIN);
    int*   regi = (int*)(sm + OFF_REG);

    const int tid  = threadIdx.x;
    const int warp = tid >> 5;
    const int lane = tid & 31;
    const int bi   = blockIdx.x;
    const int b    = bi >> 6;
    const int w    = bi & 63;
    const int wr   = w >> 3, wc = w & 7;

    // ---- init: weights (tf32, k-major stride 100), bias, rpb, LUTs, X pad ----
    for (int i = tid; i < 3072; i += 256) {
        int d = i / 96, n = i - d * 96;
        w_s[d * 100 + n] = tf32f(qkv_w[i]);
    }
    if (tid < 96) b_s[tid] = qkv_b[tid];
    for (int i = tid; i < 338; i += 256)
        ((float4*)rpb)[i] = ((const float4*)rpb_table)[i];
    for (int i = tid; i < 540; i += 256)
        xh[49 * 36 + i] = 0.0f;                 // zero X pad rows 49..63
    if (tid < WD) {
        int tr = tid / 7, tc = tid - tr * 7;
        int hh = wr * 7 + tr, ww = wc * 7 + tc;
        int sh = hh + 3; if (sh >= 56) sh -= 56;
        int sw = ww + 3; if (sw >= 56) sw -= 56;
        pix[tid] = sh * 56 + sw;
        lin[tid] = tr * 13 + tc;
        int rh = (hh < 49) ? 0 : ((hh < 53) ? 1 : 2);
        int rw = (ww < 49) ? 0 : ((ww < 53) ? 1 : 2);
        regi[tid] = rh * 3 + rw;
    }
    __syncthreads();

    const float* xb = x + (size_t)b * HWPIX * EDIM;
    float*       ob = g_mid + (size_t)b * HWPIX * EDIM;

    const int mt = warp >> 1;        // m-tile 0..3 (rows mt*16 .. +15)
    const int nh = warp & 1;         // n-half
    const int r  = lane >> 2;        // 0..7
    const int cc = lane & 3;         // 0..3
    const int rowA = (mt << 4) + r;

    for (int h = 0; h < 8; h++) {
        // ---- A: load per-head x slice (49x32), round to tf32 ----
        for (int i4 = tid; i4 < 392; i4 += 256) {
            int t = i4 >> 3, d4 = (i4 & 7) << 2;
            float4 v = *(const float4*)&xb[pix[t] * EDIM + (h << 5) + d4];
            v.x = tf32f(v.x); v.y = tf32f(v.y);
            v.z = tf32f(v.z); v.w = tf32f(v.w);
            *(float4*)&xh[t * 36 + d4] = v;
        }
        __syncthreads();

        // ---- B: QKV(64x96) = X(64x32) @ W(32x96) + bias ----
        {
            uint32_t a[4][4];
            #pragma unroll
            for (int ks = 0; ks < 4; ks++) {
                const float* xp = &xh[rowA * 36 + (ks << 3) + cc];
                a[ks][0] = __float_as_uint(xp[0]);
                a[ks][1] = __float_as_uint(xp[8 * 36]);
                a[ks][2] = __float_as_uint(xp[4]);
                a[ks][3] = __float_as_uint(xp[8 * 36 + 4]);
            }
            #pragma unroll
            for (int nt = 0; nt < 6; nt++) {
                int n0 = nh * 48 + (nt << 3);
                float bias0 = b_s[n0 + (cc << 1)];
                float bias1 = b_s[n0 + (cc << 1) + 1];
                float c[4] = {bias0, bias1, bias0, bias1};
                #pragma unroll
                for (int ks = 0; ks < 4; ks++) {
                    uint32_t bb[2];
                    bb[0] = __float_as_uint(w_s[((ks << 3) + cc) * 100 + n0 + r]);
                    bb[1] = __float_as_uint(w_s[((ks << 3) + cc + 4) * 100 + n0 + r]);
                    mma_tf32(c, a[ks], bb);
                }
                float sc = (n0 < 32) ? SCALE : 1.0f;   // fold 1/sqrt(hd) into Q
                float2 v01 = make_float2(tf32f(c[0] * sc), tf32f(c[1] * sc));
                float2 v23 = make_float2(tf32f(c[2] * sc), tf32f(c[3] * sc));
                *(float2*)&qkv[rowA * 100 + n0 + (cc << 1)]       = v01;
                *(float2*)&qkv[(rowA + 8) * 100 + n0 + (cc << 1)] = v23;
            }
        }
        __syncthreads();

        // ---- C: S(64x64) = Q(64x32) @ K^T ----
        {
            uint32_t a[4][4];
            #pragma unroll
            for (int ks = 0; ks < 4; ks++) {
                const float* qp = &qkv[rowA * 100 + (ks << 3) + cc];
                a[ks][0] = __float_as_uint(qp[0]);
                a[ks][1] = __float_as_uint(qp[800]);
                a[ks][2] = __float_as_uint(qp[4]);
                a[ks][3] = __float_as_uint(qp[804]);
            }
            #pragma unroll
            for (int nt = 0; nt < 4; nt++) {
                int n0 = (nh << 5) + (nt << 3);
                float c[4] = {0.f, 0.f, 0.f, 0.f};
                #pragma unroll
                for (int ks = 0; ks < 4; ks++) {
                    uint32_t bb[2];
                    bb[0] = __float_as_uint(qkv[(n0 + r) * 100 + 32 + (ks << 3) + cc]);
                    bb[1] = __float_as_uint(qkv[(n0 + r) * 100 + 36 + (ks << 3) + cc]);
                    mma_tf32(c, a[ks], bb);
                }
                *(float2*)&ss[rowA * 68 + n0 + (cc << 1)]       = make_float2(c[0], c[1]);
                *(float2*)&ss[(rowA + 8) * 68 + n0 + (cc << 1)] = make_float2(c[2], c[3]);
            }
        }
        __syncthreads();

        // ---- D: softmax rows (+bias+mask), write tf32 probs, zero pad cols ----
        for (int i = warp; i < WD; i += 8) {
            int   li = lin[i], gi = regi[i];
            float v0 = ss[i * 68 + lane]
                     + rpb[(li - lin[lane] + 84) * 8 + h]
                     + ((regi[lane] != gi) ? -100.0f : 0.0f);
            float v1 = -1e30f;
            if (lane < 17) {
                int j1 = 32 + lane;
                v1 = ss[i * 68 + j1]
                   + rpb[(li - lin[j1] + 84) * 8 + h]
                   + ((regi[j1] != gi) ? -100.0f : 0.0f);
            }
            float m = fmaxf(v0, v1);
            #pragma unroll
            for (int o = 16; o; o >>= 1)
                m = fmaxf(m, __shfl_xor_sync(0xffffffffu, m, o));
            float e0 = __expf(v0 - m);
            float e1 = (lane < 17) ? __expf(v1 - m) : 0.f;
            float s2 = e0 + e1;
            #pragma unroll
            for (int o = 16; o; o >>= 1)
                s2 += __shfl_xor_sync(0xffffffffu, s2, o);
            float inv = __frcp_rn(s2);
            ss[i * 68 + lane] = tf32f(e0 * inv);
            ss[i * 68 + 32 + lane] = (lane < 17) ? tf32f(e1 * inv) : 0.0f;
        }
        __syncthreads();

        // ---- E: O(64x32) = P(64x64) @ V(64x32), store shift-reversed ----
        {
            uint32_t a[8][4];
            #pragma unroll
            for (int ks = 0; ks < 8; ks++) {
                const float* sp = &ss[rowA * 68 + (ks << 3) + cc];
                a[ks][0] = __float_as_uint(sp[0]);
                a[ks][1] = __float_as_uint(sp[8 * 68]);
                a[ks][2] = __float_as_uint(sp[4]);
                a[ks][3] = __float_as_uint(sp[8 * 68 + 4]);
            }
            #pragma unroll
            for (int nt = 0; nt < 2; nt++) {
                int n0 = (nh << 4) + (nt << 3);
                float c[4] = {0.f, 0.f, 0.f, 0.f};
                #pragma unroll
                for (int ks = 0; ks < 8; ks++) {
                    uint32_t bb[2];
                    bb[0] = __float_as_uint(qkv[((ks << 3) + cc) * 100 + 64 + n0 + r]);
                    bb[1] = __float_as_uint(qkv[((ks << 3) + cc + 4) * 100 + 64 + n0 + r]);
                    mma_tf32(c, a[ks], bb);
                }
                int colg = (h << 5) + n0 + (cc << 1);
                int t0 = rowA, t1 = rowA + 8;
                if (t0 < WD)
                    *(float2*)&ob[pix[t0] * EDIM + colg] = make_float2(c[0], c[1]);
                if (t1 < WD)
                    *(float2*)&ob[pix[t1] * EDIM + colg] = make_float2(c[2], c[3]);
            }
        }
        // no sync: next stage A only writes X, which E does not touch;
        // the barrier after A(h+1) orders E(h) before B(h+1).
        __syncthreads();   // still need X-write vs B(h)-read ordering on first entry? A(h+1) writes xh while B(h) already done (C/D barriers passed). Safe to keep single barrier inside A loop instead; keep this one for simplicity of proof.
    }
}

// ---------------------------------------------------------------------------
// Projection: out[M,N] = g_mid[M,256] @ proj_w[256,256] + proj_b (unchanged R2)
// ---------------------------------------------------------------------------
__device__ __forceinline__ void cpasync16(uint32_t s, const void* g) {
    asm volatile("cp.async.cg.shared.global [%0], [%1], 16;\n"
                 :: "r"(s), "l"(g) : "memory");
}

#define PJ_ABUF   4608                  // 128*36
#define PJ_STRIDE 6912                  // 4608 + 32*72
#define PJ_SMEM_BYTES (PJ_STRIDE * 2 * 4)

__global__ void __launch_bounds__(256)
swin_proj_kernel(const float* __restrict__ Wp,
                 const float* __restrict__ pb,
                 float* __restrict__ out)
{
    extern __shared__ float psm[];
    const int tid  = threadIdx.x;
    const int lane = tid & 31;
    const int warp = tid >> 5;
    const int mW = (warp >> 1) << 5;
    const int nW = (warp & 1) << 5;
    const int rowBase = blockIdx.y << 7;
    const int nBase   = blockIdx.x << 6;
    const float* A = g_mid;
    const uint32_t sbase = (uint32_t)__cvta_generic_to_shared(psm);

    float acc[2][4][4];
    #pragma unroll
    for (int mt = 0; mt < 2; mt++)
        #pragma unroll
        for (int nt = 0; nt < 4; nt++)
            #pragma unroll
            for (int i = 0; i < 4; i++)
                acc[mt][nt][i] = 0.f;

    {
        #pragma unroll
        for (int l = 0; l < 4; l++) {
            int idx = tid + (l << 8);
            int row = idx >> 3, c4 = (idx & 7) << 2;
            cpasync16(sbase + ((row * 36 + c4) << 2),
                      &A[(size_t)(rowBase + row) * 256 + c4]);
        }
        #pragma unroll
        for (int l = 0; l < 2; l++) {
            int idx = tid + (l << 8);
            int row = idx >> 4, c4 = (idx & 15) << 2;
            cpasync16(sbase + ((PJ_ABUF + row * 72 + c4) << 2),
                      &Wp[(size_t)row * 256 + nBase + c4]);
        }
        asm volatile("cp.async.commit_group;\n" ::: "memory");
    }

    for (int kc = 0; kc < 8; kc++) {
        int buf = kc & 1;
        asm volatile("cp.async.wait_group 0;\n" ::: "memory");
        __syncthreads();
        if (kc < 7) {
            int fb = (buf ^ 1) * PJ_STRIDE;
            int k0 = (kc + 1) << 5;
            #pragma unroll
            for (int l = 0; l < 4; l++) {
                int idx = tid + (l << 8);
                int row = idx >> 3, c4 = (idx & 7) << 2;
                cpasync16(sbase + ((fb + row * 36 + c4) << 2),
                          &A[(size_t)(rowBase + row) * 256 + k0 + c4]);
            }
            #pragma unroll
            for (int l = 0; l < 2; l++) {
                int idx = tid + (l << 8);
                int row = idx >> 4, c4 = (idx & 15) << 2;
                cpasync16(sbase + ((fb + PJ_ABUF + row * 72 + c4) << 2),
                          &Wp[(size_t)(k0 + row) * 256 + nBase + c4]);
            }
            asm volatile("cp.async.commit_group;\n" ::: "memory");
        }

        const float* As = psm + buf * PJ_STRIDE;
        const float* Bs = As + PJ_ABUF;
        const int r  = lane >> 2;
        const int cc = lane & 3;
        #pragma unroll
        for (int ks = 0; ks < 32; ks += 8) {
            uint32_t a[2][4], bb[4][2];
            #pragma unroll
            for (int mt = 0; mt < 2; mt++) {
                int rb = mW + (mt << 4) + r;
                a[mt][0] = f2tf32(As[rb * 36 + ks + cc]);
                a[mt][1] = f2tf32(As[(rb + 8) * 36 + ks + cc]);
                a[mt][2] = f2tf32(As[rb * 36 + ks + cc + 4]);
                a[mt][3] = f2tf32(As[(rb + 8) * 36 + ks + cc + 4]);
            }
            #pragma unroll
            for (int nt = 0; nt < 4; nt++) {
                int n = nW + (nt << 3) + r;
                bb[nt][0] = f2tf32(Bs[(ks + cc) * 72 + n]);
                bb[nt][1] = f2tf32(Bs[(ks + cc + 4) * 72 + n]);
            }
            #pragma unroll
            for (int mt = 0; mt < 2; mt++)
                #pragma unroll
                for (int nt = 0; nt < 4; nt++)
                    mma_tf32(acc[mt][nt], a[mt], bb[nt]);
        }
        __syncthreads();
    }

    #pragma unroll
    for (int mt = 0; mt < 2; mt++) {
        int row = rowBase + mW + (mt << 4) + (lane >> 2);
        #pragma unroll
        for (int nt = 0; nt < 4; nt++) {
            int col = nBase + nW + (nt << 3) + ((lane & 3) << 1);
            float b0 = pb[col], b1 = pb[col + 1];
            float2 v0 = make_float2(acc[mt][nt][0] + b0, acc[mt][nt][1] + b1);
            float2 v1 = make_float2(acc[mt][nt][2] + b0, acc[mt][nt][3] + b1);
            *(float2*)&out[(size_t)row * 256 + col]       = v0;
            *(float2*)&out[(size_t)(row + 8) * 256 + col] = v1;
        }
    }
}

extern "C" void kernel_launch(void* const* d_in, const int* in_sizes, int n_in,
                              void* d_out, int out_size)
{
    (void)in_sizes; (void)n_in; (void)out_size;
    const float* x      = (const float*)d_in[0];
    const float* qkv_w  = (const float*)d_in[1];
    const float* qkv_b  = (const float*)d_in[2];
    const float* proj_w = (const float*)d_in[3];
    const float* proj_b = (const float*)d_in[4];
    const float* rpb    = (const float*)d_in[5];
    float* out = (float*)d_out;

    cudaFuncSetAttribute(swin_attn_kernel,
                         cudaFuncAttributeMaxDynamicSharedMemorySize, SMEM_BYTES);
    cudaFuncSetAttribute(swin_proj_kernel,
                         cudaFuncAttributeMaxDynamicSharedMemorySize, PJ_SMEM_BYTES);

    swin_attn_kernel<<<BATCH * 64, 256, SMEM_BYTES>>>(x, qkv_w, qkv_b, rpb);
    swin_proj_kernel<<<dim3(4, 784), 256, PJ_SMEM_BYTES>>>(proj_w, proj_b, out);
}

// round 4
// speedup vs baseline: 2.5209x; 1.0134x over previous
#include <cuda_runtime.h>
#include <cstdint>

// ---------------------------------------------------------------------------
// SWMSA: B=32, H=W=56, E=256, NH=8, HD=32, WS=7, WD=49, NW=64, SS=3
// K0: prep (round weights to tf32, build rpb bias matrix)
// K1: per-(batch,window) attention via tf32 mma.sync (tokens padded 49->64)
// K2: out = g_mid @ g_wp + proj_b via tf32 mma.sync (100352x256x256)
// ---------------------------------------------------------------------------

#define BATCH   32
#define HWPIX   3136
#define EDIM    256
#define WD      49
#define SCALE   0.17677669529663687f   // 1/sqrt(32)

__device__ float g_mid[(size_t)BATCH * HWPIX * EDIM];   // tf32-rounded attn out
__device__ float g_wp[65536];                           // proj_w tf32-rounded
__device__ float g_qkvw[3072];                          // qkv_w tf32-rounded
__device__ float g_rpbmat[8 * 64 * 64];                 // bias[h][i][j], pad 0

__device__ __forceinline__ uint32_t f2tf32(float f) {
    uint32_t u;
    asm("cvt.rna.tf32.f32 %0, %1;" : "=r"(u) : "f"(f));
    return u;
}
__device__ __forceinline__ float tf32f(float f) {
    return __uint_as_float(f2tf32(f));
}
__device__ __forceinline__ void mma_tf32(float* c, const uint32_t* a, const uint32_t* b) {
    asm volatile(
        "mma.sync.aligned.m16n8k8.row.col.f32.tf32.tf32.f32 "
        "{%0,%1,%2,%3}, {%4,%5,%6,%7}, {%8,%9}, {%0,%1,%2,%3};\n"
        : "+f"(c[0]), "+f"(c[1]), "+f"(c[2]), "+f"(c[3])
        : "r"(a[0]), "r"(a[1]), "r"(a[2]), "r"(a[3]), "r"(b[0]), "r"(b[1]));
}

// ---------------- prep kernel ----------------
__global__ void __launch_bounds__(256)
swin_prep_kernel(const float* __restrict__ qkv_w,
                 const float* __restrict__ proj_w,
                 const float* __restrict__ rpb_table)
{
    int idx = blockIdx.x * 256 + threadIdx.x;   // grid 256 -> 65536
    if (idx < 3072) g_qkvw[idx] = tf32f(qkv_w[idx]);
    g_wp[idx] = tf32f(proj_w[idx]);
    if (idx < 32768) {
        int h = idx >> 12, rem = idx & 4095, i = rem >> 6, j = rem & 63;
        float v = 0.f;
        if (i < WD && j < WD) {
            int li = (i / 7) * 13 + (i % 7);
            int lj = (j / 7) * 13 + (j % 7);
            v = rpb_table[(li - lj + 84) * 8 + h];
        }
        g_rpbmat[idx] = v;
    }
}

// ---------------- attention kernel ----------------
// smem (float offsets): bias 0..95 | X 96 (64x36) | QKV 2400 (64x100)
//                       S 8800 (64x68) | pix 13152 (64 ints) | regb 13216 (64B)
#define OFF_B    0
#define OFF_X    96
#define OFF_QKV  2400
#define OFF_S    8800
#define OFF_PIX  13152
#define OFF_REGB 13216
#define SMEM_FLOATS 13232
#define SMEM_BYTES  (SMEM_FLOATS * 4)

__global__ void __launch_bounds__(256, 4)
swin_attn_kernel(const float* __restrict__ x,
                 const float* __restrict__ qkv_b)
{
    extern __shared__ float sm[];
    float* b_s  = sm + OFF_B;
    float* xh   = sm + OFF_X;
    float* qkv  = sm + OFF_QKV;
    float* ss   = sm + OFF_S;
    int*   pix  = (int*)(sm + OFF_PIX);
    unsigned char* regb = (unsigned char*)(sm + OFF_REGB);

    const int tid  = threadIdx.x;
    const int warp = tid >> 5;
    const int lane = tid & 31;
    const int bi   = blockIdx.x;
    const int b    = bi >> 6;
    const int w    = bi & 63;
    const int wr   = w >> 3, wc = w & 7;

    // ---- init ----
    if (tid < 96) b_s[tid] = qkv_b[tid];
    for (int i = tid; i < 540; i += 256)
        xh[49 * 36 + i] = 0.0f;                 // zero X pad rows 49..63
    if (tid < 64) {
        int p = 0; unsigned char rg = 0;
        if (tid < WD) {
            int tr = tid / 7, tc = tid - tr * 7;
            int hh = wr * 7 + tr, ww = wc * 7 + tc;
            int sh = hh + 3; if (sh >= 56) sh -= 56;
            int sw = ww + 3; if (sw >= 56) sw -= 56;
            p = sh * 56 + sw;
            int rh = (hh < 49) ? 0 : ((hh < 53) ? 1 : 2);
            int rw = (ww < 49) ? 0 : ((ww < 53) ? 1 : 2);
            rg = (unsigned char)(rh * 3 + rw);
        }
        pix[tid] = p;
        regb[tid] = rg;
    }
    __syncthreads();

    const float* xb = x + (size_t)b * HWPIX * EDIM;
    float*       ob = g_mid + (size_t)b * HWPIX * EDIM;

    const int mt = warp >> 1;        // m-tile 0..3
    const int nh = warp & 1;         // n-half
    const int r  = lane >> 2;        // 0..7
    const int cc = lane & 3;         // 0..3
    const int rowA = (mt << 4) + r;

    for (int h = 0; h < 8; h++) {
        // ---- A: load per-head x slice (49x32), round to tf32 ----
        for (int i4 = tid; i4 < 392; i4 += 256) {
            int t = i4 >> 3, d4 = (i4 & 7) << 2;
            float4 v = *(const float4*)&xb[pix[t] * EDIM + (h << 5) + d4];
            v.x = tf32f(v.x); v.y = tf32f(v.y);
            v.z = tf32f(v.z); v.w = tf32f(v.w);
            *(float4*)&xh[t * 36 + d4] = v;
        }
        __syncthreads();

        // ---- B: QKV(64x96) = X(64x32) @ W(32x96) + bias ----
        {
            uint32_t a[4][4];
            #pragma unroll
            for (int ks = 0; ks < 4; ks++) {
                const float* xp = &xh[rowA * 36 + (ks << 3) + cc];
                a[ks][0] = __float_as_uint(xp[0]);
                a[ks][1] = __float_as_uint(xp[8 * 36]);
                a[ks][2] = __float_as_uint(xp[4]);
                a[ks][3] = __float_as_uint(xp[8 * 36 + 4]);
            }
            #pragma unroll
            for (int nt = 0; nt < 6; nt++) {
                int n0 = nh * 48 + (nt << 3);
                float bias0 = b_s[n0 + (cc << 1)];
                float bias1 = b_s[n0 + (cc << 1) + 1];
                float c[4] = {bias0, bias1, bias0, bias1};
                #pragma unroll
                for (int ks = 0; ks < 4; ks++) {
                    uint32_t bb[2];
                    bb[0] = __float_as_uint(g_qkvw[((ks << 3) + cc) * 96 + n0 + r]);
                    bb[1] = __float_as_uint(g_qkvw[((ks << 3) + cc + 4) * 96 + n0 + r]);
                    mma_tf32(c, a[ks], bb);
                }
                float sc = (n0 < 32) ? SCALE : 1.0f;   // fold 1/sqrt(hd) into Q
                float2 v01 = make_float2(tf32f(c[0] * sc), tf32f(c[1] * sc));
                float2 v23 = make_float2(tf32f(c[2] * sc), tf32f(c[3] * sc));
                *(float2*)&qkv[rowA * 100 + n0 + (cc << 1)]       = v01;
                *(float2*)&qkv[(rowA + 8) * 100 + n0 + (cc << 1)] = v23;
            }
        }
        __syncthreads();

        // ---- C: S(64x64) = Q(64x32) @ K^T ----
        {
            uint32_t a[4][4];
            #pragma unroll
            for (int ks = 0; ks < 4; ks++) {
                const float* qp = &qkv[rowA * 100 + (ks << 3) + cc];
                a[ks][0] = __float_as_uint(qp[0]);
                a[ks][1] = __float_as_uint(qp[800]);
                a[ks][2] = __float_as_uint(qp[4]);
                a[ks][3] = __float_as_uint(qp[804]);
            }
            #pragma unroll
            for (int nt = 0; nt < 4; nt++) {
                int n0 = (nh << 5) + (nt << 3);
                float c[4] = {0.f, 0.f, 0.f, 0.f};
                #pragma unroll
                for (int ks = 0; ks < 4; ks++) {
                    uint32_t bb[2];
                    bb[0] = __float_as_uint(qkv[(n0 + r) * 100 + 32 + (ks << 3) + cc]);
                    bb[1] = __float_as_uint(qkv[(n0 + r) * 100 + 36 + (ks << 3) + cc]);
                    mma_tf32(c, a[ks], bb);
                }
                *(float2*)&ss[rowA * 68 + n0 + (cc << 1)]       = make_float2(c[0], c[1]);
                *(float2*)&ss[(rowA + 8) * 68 + n0 + (cc << 1)] = make_float2(c[2], c[3]);
            }
        }
        __syncthreads();

        // ---- D: one-pass softmax, 4 threads per row ----
        {
            int rr = tid >> 2, p = tid & 3;
            float* srow = &ss[rr * 68 + (p << 4)];
            const float4* brow =
                (const float4*)&g_rpbmat[(h << 12) + (rr << 6) + (p << 4)];
            uint4 rj = ((const uint4*)regb)[p];
            unsigned grx = (unsigned)regb[rr] * 0x01010101u;
            unsigned rw[4] = {rj.x, rj.y, rj.z, rj.w};

            float v[16];
            #pragma unroll
            for (int q4 = 0; q4 < 4; q4++) {
                float4 s4 = *(float4*)&srow[q4 << 2];
                float4 b4 = brow[q4];
                unsigned eq = __vcmpeq4(rw[q4], grx);   // 0xFF per equal byte
                int j0 = (p << 4) + (q4 << 2);
                v[(q4 << 2) + 0] = (j0 + 0 < WD)
                    ? s4.x + b4.x + ((eq & 0x000000ffu) ? 0.f : -100.f) : -1e30f;
                v[(q4 << 2) + 1] = (j0 + 1 < WD)
                    ? s4.y + b4.y + ((eq & 0x0000ff00u) ? 0.f : -100.f) : -1e30f;
                v[(q4 << 2) + 2] = (j0 + 2 < WD)
                    ? s4.z + b4.z + ((eq & 0x00ff0000u) ? 0.f : -100.f) : -1e30f;
                v[(q4 << 2) + 3] = (j0 + 3 < WD)
                    ? s4.w + b4.w + ((eq & 0xff000000u) ? 0.f : -100.f) : -1e30f;
            }
            float m = v[0];
            #pragma unroll
            for (int i = 1; i < 16; i++) m = fmaxf(m, v[i]);
            m = fmaxf(m, __shfl_xor_sync(0xffffffffu, m, 1));
            m = fmaxf(m, __shfl_xor_sync(0xffffffffu, m, 2));
            float sum = 0.f;
            #pragma unroll
            for (int i = 0; i < 16; i++) { v[i] = __expf(v[i] - m); sum += v[i]; }
            sum += __shfl_xor_sync(0xffffffffu, sum, 1);
            sum += __shfl_xor_sync(0xffffffffu, sum, 2);
            float inv = __frcp_rn(sum);
            #pragma unroll
            for (int q4 = 0; q4 < 4; q4++) {
                int j0 = (p << 4) + (q4 << 2);
                float4 o4;
                o4.x = (j0 + 0 < WD) ? tf32f(v[(q4 << 2) + 0] * inv) : 0.f;
                o4.y = (j0 + 1 < WD) ? tf32f(v[(q4 << 2) + 1] * inv) : 0.f;
                o4.z = (j0 + 2 < WD) ? tf32f(v[(q4 << 2) + 2] * inv) : 0.f;
                o4.w = (j0 + 3 < WD) ? tf32f(v[(q4 << 2) + 3] * inv) : 0.f;
                *(float4*)&srow[q4 << 2] = o4;
            }
        }
        __syncthreads();

        // ---- E: O(64x32) = P(64x64) @ V(64x32), store shift-reversed ----
        // (no trailing barrier: post-A barrier of next head orders E vs B')
        {
            #pragma unroll
            for (int nt = 0; nt < 2; nt++) {
                int n0 = (nh << 4) + (nt << 3);
                float c[4] = {0.f, 0.f, 0.f, 0.f};
                #pragma unroll
                for (int ks = 0; ks < 8; ks++) {
                    const float* sp = &ss[rowA * 68 + (ks << 3) + cc];
                    uint32_t a[4], bb[2];
                    a[0] = __float_as_uint(sp[0]);
                    a[1] = __float_as_uint(sp[8 * 68]);
                    a[2] = __float_as_uint(sp[4]);
                    a[3] = __float_as_uint(sp[8 * 68 + 4]);
                    bb[0] = __float_as_uint(qkv[((ks << 3) + cc) * 100 + 64 + n0 + r]);
                    bb[1] = __float_as_uint(qkv[((ks << 3) + cc + 4) * 100 + 64 + n0 + r]);
                    mma_tf32(c, a, bb);
                }
                int colg = (h << 5) + n0 + (cc << 1);
                int t0 = rowA, t1 = rowA + 8;
                if (t0 < WD)
                    *(float2*)&ob[pix[t0] * EDIM + colg] =
                        make_float2(tf32f(c[0]), tf32f(c[1]));
                if (t1 < WD)
                    *(float2*)&ob[pix[t1] * EDIM + colg] =
                        make_float2(tf32f(c[2]), tf32f(c[3]));
            }
        }
    }
}

// ---------------------------------------------------------------------------
// Projection: out[M,N] = g_mid[M,256] @ g_wp[256,256] + proj_b
// All operands pre-rounded tf32 -> no cvt in fragment path.
// ---------------------------------------------------------------------------
__device__ __forceinline__ void cpasync16(uint32_t s, const void* g) {
    asm volatile("cp.async.cg.shared.global [%0], [%1], 16;\n"
                 :: "r"(s), "l"(g) : "memory");
}

#define PJ_ABUF   4608                  // 128*36
#define PJ_STRIDE 6912                  // 4608 + 32*72
#define PJ_SMEM_BYTES (PJ_STRIDE * 2 * 4)

__global__ void __launch_bounds__(256)
swin_proj_kernel(const float* __restrict__ pb,
                 float* __restrict__ out)
{
    extern __shared__ float psm[];
    const int tid  = threadIdx.x;
    const int lane = tid & 31;
    const int warp = tid >> 5;
    const int mW = (warp >> 1) << 5;
    const int nW = (warp & 1) << 5;
    const int rowBase = blockIdx.y << 7;
    const int nBase   = blockIdx.x << 6;
    const float* A = g_mid;
    const float* Wp = g_wp;
    const uint32_t sbase = (uint32_t)__cvta_generic_to_shared(psm);

    float acc[2][4][4];
    #pragma unroll
    for (int mt = 0; mt < 2; mt++)
        #pragma unroll
        for (int nt = 0; nt < 4; nt++)
            #pragma unroll
            for (int i = 0; i < 4; i++)
                acc[mt][nt][i] = 0.f;

    {
        #pragma unroll
        for (int l = 0; l < 4; l++) {
            int idx = tid + (l << 8);
            int row = idx >> 3, c4 = (idx & 7) << 2;
            cpasync16(sbase + ((row * 36 + c4) << 2),
                      &A[(size_t)(rowBase + row) * 256 + c4]);
        }
        #pragma unroll
        for (int l = 0; l < 2; l++) {
            int idx = tid + (l << 8);
            int row = idx >> 4, c4 = (idx & 15) << 2;
            cpasync16(sbase + ((PJ_ABUF + row * 72 + c4) << 2),
                      &Wp[(size_t)row * 256 + nBase + c4]);
        }
        asm volatile("cp.async.commit_group;\n" ::: "memory");
    }

    for (int kc = 0; kc < 8; kc++) {
        int buf = kc & 1;
        asm volatile("cp.async.wait_group 0;\n" ::: "memory");
        __syncthreads();
        if (kc < 7) {
            int fb = (buf ^ 1) * PJ_STRIDE;
            int k0 = (kc + 1) << 5;
            #pragma unroll
            for (int l = 0; l < 4; l++) {
                int idx = tid + (l << 8);
                int row = idx >> 3, c4 = (idx & 7) << 2;
                cpasync16(sbase + ((fb + row * 36 + c4) << 2),
                          &A[(size_t)(rowBase + row) * 256 + k0 + c4]);
            }
            #pragma unroll
            for (int l = 0; l < 2; l++) {
                int idx = tid + (l << 8);
                int row = idx >> 4, c4 = (idx & 15) << 2;
                cpasync16(sbase + ((fb + PJ_ABUF + row * 72 + c4) << 2),
                          &Wp[(size_t)(k0 + row) * 256 + nBase + c4]);
            }
            asm volatile("cp.async.commit_group;\n" ::: "memory");
        }

        const float* As = psm + buf * PJ_STRIDE;
        const float* Bs = As + PJ_ABUF;
        const int r  = lane >> 2;
        const int cc = lane & 3;
        #pragma unroll
        for (int ks = 0; ks < 32; ks += 8) {
            uint32_t a[2][4], bb[4][2];
            #pragma unroll
            for (int mt = 0; mt < 2; mt++) {
                int rb = mW + (mt << 4) + r;
                a[mt][0] = __float_as_uint(As[rb * 36 + ks + cc]);
                a[mt][1] = __float_as_uint(As[(rb + 8) * 36 + ks + cc]);
                a[mt][2] = __float_as_uint(As[rb * 36 + ks + cc + 4]);
                a[mt][3] = __float_as_uint(As[(rb + 8) * 36 + ks + cc + 4]);
            }
            #pragma unroll
            for (int nt = 0; nt < 4; nt++) {
                int n = nW + (nt << 3) + r;
                bb[nt][0] = __float_as_uint(Bs[(ks + cc) * 72 + n]);
                bb[nt][1] = __float_as_uint(Bs[(ks + cc + 4) * 72 + n]);
            }
            #pragma unroll
            for (int mt = 0; mt < 2; mt++)
                #pragma unroll
                for (int nt = 0; nt < 4; nt++)
                    mma_tf32(acc[mt][nt], a[mt], bb[nt]);
        }
        __syncthreads();
    }

    #pragma unroll
    for (int mt = 0; mt < 2; mt++) {
        int row = rowBase + mW + (mt << 4) + (lane >> 2);
        #pragma unroll
        for (int nt = 0; nt < 4; nt++) {
            int col = nBase + nW + (nt << 3) + ((lane & 3) << 1);
            float b0 = pb[col], b1 = pb[col + 1];
            float2 v0 = make_float2(acc[mt][nt][0] + b0, acc[mt][nt][1] + b1);
            float2 v1 = make_float2(acc[mt][nt][2] + b0, acc[mt][nt][3] + b1);
            *(float2*)&out[(size_t)row * 256 + col]       = v0;
            *(float2*)&out[(size_t)(row + 8) * 256 + col] = v1;
        }
    }
}

extern "C" void kernel_launch(void* const* d_in, const int* in_sizes, int n_in,
                              void* d_out, int out_size)
{
    (void)in_sizes; (void)n_in; (void)out_size;
    const float* x      = (const float*)d_in[0];
    const float* qkv_w  = (const float*)d_in[1];
    const float* qkv_b  = (const float*)d_in[2];
    const float* proj_w = (const float*)d_in[3];
    const float* proj_b = (const float*)d_in[4];
    const float* rpb    = (const float*)d_in[5];
    float* out = (float*)d_out;

    cudaFuncSetAttribute(swin_attn_kernel,
                         cudaFuncAttributeMaxDynamicSharedMemorySize, SMEM_BYTES);
    cudaFuncSetAttribute(swin_proj_kernel,
                         cudaFuncAttributeMaxDynamicSharedMemorySize, PJ_SMEM_BYTES);

    swin_prep_kernel<<<256, 256>>>(qkv_w, proj_w, rpb);
    swin_attn_kernel<<<BATCH * 64, 256, SMEM_BYTES>>>(x, qkv_b);
    swin_proj_kernel<<<dim3(4, 784), 256, PJ_SMEM_BYTES>>>(proj_b, out);
}

// round 5
// speedup vs baseline: 3.7183x; 1.4749x over previous
#include <cuda_runtime.h>
#include <cuda_fp16.h>
#include <cstdint>

// ---------------------------------------------------------------------------
// SWMSA: B=32, H=W=56, E=256, NH=8, HD=32, WS=7, WD=49, NW=64, SS=3
// fp16 mma.sync m16n8k16 pipeline (fp32 accum everywhere).
// K0: prep (fp16 weight transposes, rpb bias matrix)
// K1: per-(batch,window) attention (tokens padded 49->64) -> g_mid (fp16)
// K2: out = g_mid @ proj_w + proj_b (100352x256x256)
// ---------------------------------------------------------------------------

#define BATCH   32
#define HWPIX   3136
#define EDIM    256
#define WD      49
#define SCALE   0.17677669529663687f   // 1/sqrt(32)

__device__ __half g_mid[(size_t)BATCH * HWPIX * EDIM];  // attn out, fp16
__device__ __half g_wpT[65536];                         // proj_w^T fp16 [n][k]
__device__ __half g_qkvwT[3072];                        // qkv_w^T fp16 [n][k]
__device__ float  g_rpbmat[8 * 64 * 64];                // bias[h][i][j], pad 0

__device__ __forceinline__ void mma_f16(float* c, const uint32_t* a, const uint32_t* b) {
    asm volatile(
        "mma.sync.aligned.m16n8k16.row.col.f32.f16.f16.f32 "
        "{%0,%1,%2,%3}, {%4,%5,%6,%7}, {%8,%9}, {%0,%1,%2,%3};\n"
        : "+f"(c[0]), "+f"(c[1]), "+f"(c[2]), "+f"(c[3])
        : "r"(a[0]), "r"(a[1]), "r"(a[2]), "r"(a[3]), "r"(b[0]), "r"(b[1]));
}
__device__ __forceinline__ uint32_t h2u(__half2 h) { return *(uint32_t*)&h; }

// ---------------- prep kernel ----------------
__global__ void __launch_bounds__(256)
swin_prep_kernel(const float* __restrict__ qkv_w,
                 const float* __restrict__ proj_w,
                 const float* __restrict__ rpb_table)
{
    int idx = blockIdx.x * 256 + threadIdx.x;   // grid 256 -> 65536
    if (idx < 3072) {
        int n = idx >> 5, k = idx & 31;         // qkv_w (32,96) -> [n][k]
        g_qkvwT[idx] = __float2half(qkv_w[k * 96 + n]);
    }
    {
        int n = idx >> 8, k = idx & 255;        // proj_w (256,256) -> [n][k]
        g_wpT[idx] = __float2half(proj_w[k * 256 + n]);
    }
    if (idx < 32768) {
        int h = idx >> 12, rem = idx & 4095, i = rem >> 6, j = rem & 63;
        float v = 0.f;
        if (i < WD && j < WD) {
            int li = (i / 7) * 13 + (i % 7);
            int lj = (j / 7) * 13 + (j % 7);
            v = rpb_table[(li - lj + 84) * 8 + h];
        }
        g_rpbmat[idx] = v;
    }
}

// ---------------- attention kernel ----------------
// smem float-word offsets:
#define OFF_B    0        // 96 fp32 bias
#define OFF_S    96       // 64x68 fp32 scores
#define OFF_XH   4448     // X  fp16 64 rows x 40 halves (20 words)
#define OFF_Q    5728     // Q  fp16 64 x 40
#define OFF_K    7008     // K  fp16 64 x 40
#define OFF_VT   8288     // V^T fp16 32 rows x 72 halves (36 words)
#define OFF_P    9440     // P  fp16 64 x 72 halves (36 words)
#define OFF_PIX  11744    // 64 ints
#define OFF_REGB 11808    // 64 bytes
#define SMEM_FLOATS 11824
#define SMEM_BYTES  (SMEM_FLOATS * 4)

__global__ void __launch_bounds__(256, 4)
swin_attn_kernel(const float* __restrict__ x,
                 const float* __restrict__ qkv_b)
{
    extern __shared__ float sm[];
    float*    b_s = sm + OFF_B;
    float*    ss  = sm + OFF_S;
    uint32_t* xw  = (uint32_t*)(sm + OFF_XH);
    uint32_t* qw  = (uint32_t*)(sm + OFF_Q);
    uint32_t* kw  = (uint32_t*)(sm + OFF_K);
    uint32_t* vw  = (uint32_t*)(sm + OFF_VT);
    uint32_t* pwb = (uint32_t*)(sm + OFF_P);
    __half*   vh  = (__half*)vw;
    int*      pix = (int*)(sm + OFF_PIX);
    unsigned char* regb = (unsigned char*)(sm + OFF_REGB);

    const int tid  = threadIdx.x;
    const int warp = tid >> 5;
    const int lane = tid & 31;
    const int bi   = blockIdx.x;
    const int b    = bi >> 6;
    const int w    = bi & 63;
    const int wr   = w >> 3, wc = w & 7;

    // ---- init ----
    if (tid < 96) b_s[tid] = qkv_b[tid];
    for (int i = tid; i < 300; i += 256)
        xw[980 + i] = 0u;                        // zero X pad rows 49..63
    if (tid < 64) {
        int p = 0; unsigned char rg = 0;
        if (tid < WD) {
            int tr = tid / 7, tc = tid - tr * 7;
            int hh = wr * 7 + tr, ww = wc * 7 + tc;
            int sh = hh + 3; if (sh >= 56) sh -= 56;
            int sw = ww + 3; if (sw >= 56) sw -= 56;
            p = sh * 56 + sw;
            int rh = (hh < 49) ? 0 : ((hh < 53) ? 1 : 2);
            int rw = (ww < 49) ? 0 : ((ww < 53) ? 1 : 2);
            rg = (unsigned char)(rh * 3 + rw);
        }
        pix[tid] = p;
        regb[tid] = rg;
    }
    __syncthreads();

    const float* xb = x + (size_t)b * HWPIX * EDIM;
    __half*      ob = g_mid + (size_t)b * HWPIX * EDIM;

    const int mt = warp >> 1;        // m-tile 0..3
    const int nh = warp & 1;         // n-half
    const int r  = lane >> 2;        // 0..7
    const int cc = lane & 3;         // 0..3
    const int rowA = (mt << 4) + r;

    for (int h = 0; h < 8; h++) {
        // ---- A: load per-head x slice (49x32) fp32 -> fp16 smem ----
        for (int i4 = tid; i4 < 392; i4 += 256) {
            int t = i4 >> 3, d4 = (i4 & 7) << 2;
            float4 v = *(const float4*)&xb[pix[t] * EDIM + (h << 5) + d4];
            uint32_t lo = h2u(__floats2half2_rn(v.x, v.y));
            uint32_t hi = h2u(__floats2half2_rn(v.z, v.w));
            xw[t * 20 + (d4 >> 1)]     = lo;
            xw[t * 20 + (d4 >> 1) + 1] = hi;
        }
        __syncthreads();

        // ---- B: QKV(64x96) = X(64x32) @ W^T + bias; V stored transposed ----
        {
            uint32_t a[2][4];
            #pragma unroll
            for (int kk = 0; kk < 2; kk++) {
                const uint32_t* xp = xw + rowA * 20 + (kk << 3) + cc;
                a[kk][0] = xp[0];
                a[kk][1] = xp[160];
                a[kk][2] = xp[4];
                a[kk][3] = xp[164];
            }
            const uint32_t* wtw = (const uint32_t*)g_qkvwT;
            #pragma unroll
            for (int nt = 0; nt < 6; nt++) {
                int n0 = nh * 48 + (nt << 3);
                int c2 = cc << 1;
                float b0f = b_s[n0 + c2], b1f = b_s[n0 + c2 + 1];
                float c[4] = {b0f, b1f, b0f, b1f};
                #pragma unroll
                for (int kk = 0; kk < 2; kk++) {
                    const uint32_t* wp = wtw + (n0 + r) * 16 + (kk << 3) + cc;
                    uint32_t bb[2] = {wp[0], wp[4]};
                    mma_f16(c, a[kk], bb);
                }
                if (n0 < 64) {
                    float sc = (n0 < 32) ? SCALE : 1.0f;
                    uint32_t* dst = (n0 < 32) ? qw : kw;
                    int off = ((n0 & 31) >> 1) + cc;
                    dst[rowA * 20 + off]       = h2u(__floats2half2_rn(c[0] * sc, c[1] * sc));
                    dst[(rowA + 8) * 20 + off] = h2u(__floats2half2_rn(c[2] * sc, c[3] * sc));
                } else {
                    int d0 = n0 - 64 + c2;
                    vh[d0 * 72 + rowA]           = __float2half(c[0]);
                    vh[(d0 + 1) * 72 + rowA]     = __float2half(c[1]);
                    vh[d0 * 72 + rowA + 8]       = __float2half(c[2]);
                    vh[(d0 + 1) * 72 + rowA + 8] = __float2half(c[3]);
                }
            }
        }
        __syncthreads();

        // ---- C: S(64x64) = Q(64x32) @ K^T ----
        {
            uint32_t a[2][4];
            #pragma unroll
            for (int kk = 0; kk < 2; kk++) {
                const uint32_t* qp = qw + rowA * 20 + (kk << 3) + cc;
                a[kk][0] = qp[0];
                a[kk][1] = qp[160];
                a[kk][2] = qp[4];
                a[kk][3] = qp[164];
            }
            #pragma unroll
            for (int nt = 0; nt < 4; nt++) {
                int n0 = (nh << 5) + (nt << 3);
                float c[4] = {0.f, 0.f, 0.f, 0.f};
                #pragma unroll
                for (int kk = 0; kk < 2; kk++) {
                    const uint32_t* kp = kw + (n0 + r) * 20 + (kk << 3) + cc;
                    uint32_t bb[2] = {kp[0], kp[4]};
                    mma_f16(c, a[kk], bb);
                }
                *(float2*)&ss[rowA * 68 + n0 + (cc << 1)]       = make_float2(c[0], c[1]);
                *(float2*)&ss[(rowA + 8) * 68 + n0 + (cc << 1)] = make_float2(c[2], c[3]);
            }
        }
        __syncthreads();

        // ---- D: one-pass softmax (+bias+mask), write P fp16 ----
        {
            int rr = tid >> 2, p = tid & 3;
            float* srow = &ss[rr * 68 + (p << 4)];
            const float4* brow =
                (const float4*)&g_rpbmat[(h << 12) + (rr << 6) + (p << 4)];
            uint4 rj = ((const uint4*)regb)[p];
            unsigned grx = (unsigned)regb[rr] * 0x01010101u;
            unsigned rw4[4] = {rj.x, rj.y, rj.z, rj.w};

            float v[16];
            #pragma unroll
            for (int q4 = 0; q4 < 4; q4++) {
                float4 s4 = *(float4*)&srow[q4 << 2];
                float4 b4 = brow[q4];
                unsigned eq = __vcmpeq4(rw4[q4], grx);
                int j0 = (p << 4) + (q4 << 2);
                v[(q4 << 2) + 0] = (j0 + 0 < WD)
                    ? s4.x + b4.x + ((eq & 0x000000ffu) ? 0.f : -100.f) : -1e30f;
                v[(q4 << 2) + 1] = (j0 + 1 < WD)
                    ? s4.y + b4.y + ((eq & 0x0000ff00u) ? 0.f : -100.f) : -1e30f;
                v[(q4 << 2) + 2] = (j0 + 2 < WD)
                    ? s4.z + b4.z + ((eq & 0x00ff0000u) ? 0.f : -100.f) : -1e30f;
                v[(q4 << 2) + 3] = (j0 + 3 < WD)
                    ? s4.w + b4.w + ((eq & 0xff000000u) ? 0.f : -100.f) : -1e30f;
            }
            float m = v[0];
            #pragma unroll
            for (int i = 1; i < 16; i++) m = fmaxf(m, v[i]);
            m = fmaxf(m, __shfl_xor_sync(0xffffffffu, m, 1));
            m = fmaxf(m, __shfl_xor_sync(0xffffffffu, m, 2));
            float sum = 0.f;
            #pragma unroll
            for (int i = 0; i < 16; i++) { v[i] = __expf(v[i] - m); sum += v[i]; }
            sum += __shfl_xor_sync(0xffffffffu, sum, 1);
            sum += __shfl_xor_sync(0xffffffffu, sum, 2);
            float inv = __frcp_rn(sum);
            uint32_t* prow = pwb + rr * 36 + (p << 3);
            #pragma unroll
            for (int q = 0; q < 8; q++)
                prow[q] = h2u(__floats2half2_rn(v[(q << 1)] * inv,
                                                v[(q << 1) + 1] * inv));
        }
        __syncthreads();

        // ---- E: O(64x32) = P(64x64) @ V(64x32) via V^T, shift-reversed ----
        // (no trailing barrier: next head's post-A barrier orders E vs B')
        {
            uint32_t a[4][4];
            #pragma unroll
            for (int kk = 0; kk < 4; kk++) {
                const uint32_t* pp = pwb + rowA * 36 + (kk << 3) + cc;
                a[kk][0] = pp[0];
                a[kk][1] = pp[288];
                a[kk][2] = pp[4];
                a[kk][3] = pp[292];
            }
            #pragma unroll
            for (int nt = 0; nt < 2; nt++) {
                int n0 = (nh << 4) + (nt << 3);
                float c[4] = {0.f, 0.f, 0.f, 0.f};
                #pragma unroll
                for (int kk = 0; kk < 4; kk++) {
                    const uint32_t* vp = vw + (n0 + r) * 36 + (kk << 3) + cc;
                    uint32_t bb[2] = {vp[0], vp[4]};
                    mma_f16(c, a[kk], bb);
                }
                int colg = (h << 5) + n0 + (cc << 1);
                if (rowA < WD)
                    *(uint32_t*)&ob[pix[rowA] * EDIM + colg] =
                        h2u(__floats2half2_rn(c[0], c[1]));
                if (rowA + 8 < WD)
                    *(uint32_t*)&ob[pix[rowA + 8] * EDIM + colg] =
                        h2u(__floats2half2_rn(c[2], c[3]));
            }
        }
    }
}

// ---------------------------------------------------------------------------
// Projection: out[M,N] = g_mid(fp16)[M,256] @ g_wpT^T + proj_b
// fp16 m16n8k16, block tile 128x64, cp.async double-buffered K-chunks of 32.
// ---------------------------------------------------------------------------
__device__ __forceinline__ void cpasync16(uint32_t s, const void* g) {
    asm volatile("cp.async.cg.shared.global [%0], [%1], 16;\n"
                 :: "r"(s), "l"(g) : "memory");
}

#define PJ_AW       2560                 // A tile words (128 rows x 20)
#define PJ_STRIDEW  3840                 // + B tile (64 x 20)
#define PJ_SMEM_BYTES (PJ_STRIDEW * 2 * 4)

__global__ void __launch_bounds__(256)
swin_proj_kernel(const float* __restrict__ pb,
                 float* __restrict__ out)
{
    extern __shared__ uint32_t pjw[];
    const int tid  = threadIdx.x;
    const int lane = tid & 31;
    const int warp = tid >> 5;
    const int mW = (warp >> 1) << 5;
    const int nW = (warp & 1) << 5;
    const int rowBase = blockIdx.y << 7;
    const int nBase   = blockIdx.x << 6;
    const __half* A16 = g_mid;
    const __half* B16 = g_wpT;
    const uint32_t sbase = (uint32_t)__cvta_generic_to_shared(pjw);

    float acc[2][4][4];
    #pragma unroll
    for (int mt = 0; mt < 2; mt++)
        #pragma unroll
        for (int nt = 0; nt < 4; nt++)
            #pragma unroll
            for (int i = 0; i < 4; i++)
                acc[mt][nt][i] = 0.f;

    // prologue: chunk 0 -> buffer 0
    {
        #pragma unroll
        for (int l = 0; l < 2; l++) {
            int idx = tid + (l << 8);
            int row = idx >> 2, c16 = idx & 3;
            cpasync16(sbase + ((row * 20 + (c16 << 2)) << 2),
                      &A16[(size_t)(rowBase + row) * 256 + (c16 << 3)]);
        }
        {
            int row = tid >> 2, c16 = tid & 3;
            cpasync16(sbase + ((PJ_AW + row * 20 + (c16 << 2)) << 2),
                      &B16[(size_t)(nBase + row) * 256 + (c16 << 3)]);
        }
        asm volatile("cp.async.commit_group;\n" ::: "memory");
    }

    const int r  = lane >> 2;
    const int cc = lane & 3;

    for (int kc = 0; kc < 8; kc++) {
        int buf = kc & 1;
        asm volatile("cp.async.wait_group 0;\n" ::: "memory");
        __syncthreads();
        if (kc < 7) {
            int fb = (buf ^ 1) * PJ_STRIDEW;
            int k0 = (kc + 1) << 5;
            #pragma unroll
            for (int l = 0; l < 2; l++) {
                int idx = tid + (l << 8);
                int row = idx >> 2, c16 = idx & 3;
                cpasync16(sbase + ((fb + row * 20 + (c16 << 2)) << 2),
                          &A16[(size_t)(rowBase + row) * 256 + k0 + (c16 << 3)]);
            }
            {
                int row = tid >> 2, c16 = tid & 3;
                cpasync16(sbase + ((fb + PJ_AW + row * 20 + (c16 << 2)) << 2),
                          &B16[(size_t)(nBase + row) * 256 + k0 + (c16 << 3)]);
            }
            asm volatile("cp.async.commit_group;\n" ::: "memory");
        }

        const uint32_t* As = pjw + buf * PJ_STRIDEW;
        const uint32_t* Bs = As + PJ_AW;
        #pragma unroll
        for (int kk = 0; kk < 2; kk++) {
            uint32_t a[2][4], bb[4][2];
            #pragma unroll
            for (int mt2 = 0; mt2 < 2; mt2++) {
                int rb = mW + (mt2 << 4) + r;
                const uint32_t* ap = As + rb * 20 + (kk << 3) + cc;
                a[mt2][0] = ap[0];
                a[mt2][1] = ap[160];
                a[mt2][2] = ap[4];
                a[mt2][3] = ap[164];
            }
            #pragma unroll
            for (int nt = 0; nt < 4; nt++) {
                int n = nW + (nt << 3) + r;
                const uint32_t* bp = Bs + n * 20 + (kk << 3) + cc;
                bb[nt][0] = bp[0];
                bb[nt][1] = bp[4];
            }
            #pragma unroll
            for (int mt2 = 0; mt2 < 2; mt2++)
                #pragma unroll
                for (int nt = 0; nt < 4; nt++)
                    mma_f16(acc[mt2][nt], a[mt2], bb[nt]);
        }
        __syncthreads();
    }

    #pragma unroll
    for (int mt2 = 0; mt2 < 2; mt2++) {
        int row = rowBase + mW + (mt2 << 4) + (lane >> 2);
        #pragma unroll
        for (int nt = 0; nt < 4; nt++) {
            int col = nBase + nW + (nt << 3) + ((lane & 3) << 1);
            float b0 = pb[col], b1 = pb[col + 1];
            float2 v0 = make_float2(acc[mt2][nt][0] + b0, acc[mt2][nt][1] + b1);
            float2 v1 = make_float2(acc[mt2][nt][2] + b0, acc[mt2][nt][3] + b1);
            *(float2*)&out[(size_t)row * 256 + col]       = v0;
            *(float2*)&out[(size_t)(row + 8) * 256 + col] = v1;
        }
    }
}

extern "C" void kernel_launch(void* const* d_in, const int* in_sizes, int n_in,
                              void* d_out, int out_size)
{
    (void)in_sizes; (void)n_in; (void)out_size;
    const float* x      = (const float*)d_in[0];
    const float* qkv_w  = (const float*)d_in[1];
    const float* qkv_b  = (const float*)d_in[2];
    const float* proj_w = (const float*)d_in[3];
    const float* proj_b = (const float*)d_in[4];
    const float* rpb    = (const float*)d_in[5];
    float* out = (float*)d_out;

    cudaFuncSetAttribute(swin_attn_kernel,
                         cudaFuncAttributeMaxDynamicSharedMemorySize, SMEM_BYTES);
    cudaFuncSetAttribute(swin_proj_kernel,
                         cudaFuncAttributeMaxDynamicSharedMemorySize, PJ_SMEM_BYTES);

    swin_prep_kernel<<<256, 256>>>(qkv_w, proj_w, rpb);
    swin_attn_kernel<<<BATCH * 64, 256, SMEM_BYTES>>>(x, qkv_b);
    swin_proj_kernel<<<dim3(4, 784), 256, PJ_SMEM_BYTES>>>(proj_b, out);
}

// round 6
// speedup vs baseline: 4.7162x; 1.2684x over previous
#include <cuda_runtime.h>
#include <cuda_fp16.h>
#include <cstdint>

// ---------------------------------------------------------------------------
// SWMSA: B=32, H=W=56, E=256, NH=8, HD=32, WS=7, WD=49, NW=64, SS=3
// R6: flash-style attention — one 512-thread block per (batch,window),
//     2 warps per head, Q/S/P register-resident, K/V via pair smem + ldmatrix,
//     2 barriers per block. Proj unchanged (fp16 mma, cp.async).
// ---------------------------------------------------------------------------

#define BATCH 32
#define HWPIX 3136
#define EDIM  256
#define WD    49
#define SCALE 0.17677669529663687f   // 1/sqrt(32)

__device__ __half g_mid[(size_t)BATCH * HWPIX * EDIM];  // attn out, fp16
__device__ __half g_wpT[65536];                         // proj_w^T fp16 [n][k]
__device__ __half g_qkvwT[3072];                        // qkv_w^T fp16 [n][k]
__device__ __half g_bias[4 * 8 * 64 * 64];              // (bias+mask)[cls][h][i][j]

__device__ __forceinline__ void mma_f16(float* c, const uint32_t* a, const uint32_t* b) {
    asm volatile(
        "mma.sync.aligned.m16n8k16.row.col.f32.f16.f16.f32 "
        "{%0,%1,%2,%3}, {%4,%5,%6,%7}, {%8,%9}, {%0,%1,%2,%3};\n"
        : "+f"(c[0]), "+f"(c[1]), "+f"(c[2]), "+f"(c[3])
        : "r"(a[0]), "r"(a[1]), "r"(a[2]), "r"(a[3]), "r"(b[0]), "r"(b[1]));
}
__device__ __forceinline__ uint32_t h2u(__half2 h) { return *(uint32_t*)&h; }
__device__ __forceinline__ uint32_t packh2(float x, float y) {
    return h2u(__floats2half2_rn(x, y));
}
__device__ __forceinline__ void ldsm4(uint32_t& r0, uint32_t& r1, uint32_t& r2,
                                      uint32_t& r3, uint32_t addr) {
    asm volatile("ldmatrix.sync.aligned.m8n8.x4.shared.b16 {%0,%1,%2,%3}, [%4];"
                 : "=r"(r0), "=r"(r1), "=r"(r2), "=r"(r3) : "r"(addr));
}
__device__ __forceinline__ void ldsm4t(uint32_t& r0, uint32_t& r1, uint32_t& r2,
                                       uint32_t& r3, uint32_t addr) {
    asm volatile("ldmatrix.sync.aligned.m8n8.x4.trans.shared.b16 {%0,%1,%2,%3}, [%4];"
                 : "=r"(r0), "=r"(r1), "=r"(r2), "=r"(r3) : "r"(addr));
}

// ---------------- prep kernel ----------------
__global__ void __launch_bounds__(256)
swin_prep_kernel(const float* __restrict__ qkv_w,
                 const float* __restrict__ proj_w,
                 const float* __restrict__ rpb_table)
{
    int idx = blockIdx.x * 256 + threadIdx.x;   // grid 512 -> 131072
    if (idx < 3072) {
        int n = idx >> 5, k = idx & 31;
        g_qkvwT[idx] = __float2half(qkv_w[k * 96 + n]);
    }
    if (idx < 65536) {
        int n = idx >> 8, k = idx & 255;
        g_wpT[idx] = __float2half(proj_w[k * 256 + n]);
    }
    {
        int cls = idx >> 15, h = (idx >> 12) & 7, i = (idx >> 6) & 63, j = idx & 63;
        float v = -30000.0f;
        if (i < WD && j < WD) {
            int tri = i / 7, tci = i - tri * 7;
            int trj = j / 7, tcj = j - trj * 7;
            int li = tri * 13 + tci, lj = trj * 13 + tcj;
            v = rpb_table[(li - lj + 84) * 8 + h];
            int bot = cls & 1, rgt = (cls >> 1) & 1;
            int ri = (bot ? (tri < 4 ? 1 : 2) : 0) * 3 + (rgt ? (tci < 4 ? 1 : 2) : 0);
            int rj = (bot ? (trj < 4 ? 1 : 2) : 0) * 3 + (rgt ? (tcj < 4 ? 1 : 2) : 0);
            if (ri != rj) v -= 100.0f;
        }
        g_bias[idx] = __float2half(v);
    }
}

// ---------------- attention kernel ----------------
// smem word offsets: X (64 rows x 132 words, fp16 pairs) | per-pair K,V | pix | qkv bias
#define XROW    132
#define OFF_X   0
#define OFF_KV  8448               // 8 pairs x 2560 words (K 64x20, V 64x20)
#define OFF_PIX 28928              // 64 ints
#define OFF_QB  28992              // 96 floats
#define AT_SMEM_WORDS 29088
#define AT_SMEM_BYTES (AT_SMEM_WORDS * 4)

__global__ void __launch_bounds__(512)
swin_attn_kernel(const float* __restrict__ x,
                 const float* __restrict__ qkv_b)
{
    extern __shared__ uint32_t smw[];
    const int tid  = threadIdx.x;
    const int warp = tid >> 5;
    const int lane = tid & 31;
    const int bi   = blockIdx.x;
    const int b    = bi >> 6;
    const int w    = bi & 63;
    const int wr   = w >> 3, wc = w & 7;
    const int cls  = (wr == 7 ? 1 : 0) | (wc == 7 ? 2 : 0);

    const float* xb = x + (size_t)b * HWPIX * EDIM;
    __half*      ob = g_mid + (size_t)b * HWPIX * EDIM;

    float* qb  = (float*)(smw + OFF_QB);
    int*   pixs = (int*)(smw + OFF_PIX);

    // ---- init: qkv bias, pix LUT, X pad rows ----
    if (tid < 96) qb[tid] = qkv_b[tid];
    if (tid < 64) {
        int p = 0;
        if (tid < WD) {
            int tr = tid / 7, tc = tid - tr * 7;
            int sh = wr * 7 + tr + 3; if (sh >= 56) sh -= 56;
            int sw = wc * 7 + tc + 3; if (sw >= 56) sw -= 56;
            p = sh * 56 + sw;
        }
        pixs[tid] = p;
    }
    for (int i = tid; i < 15 * XROW; i += 512)
        smw[OFF_X + 49 * XROW + i] = 0u;        // zero X pad rows 49..63

    // ---- X load: 49 rows x 256 floats -> fp16 smem (pix computed inline) ----
    for (int i = tid; i < 3136; i += 512) {
        int t  = i >> 6;
        int c4 = (i & 63) << 2;
        int tr = t / 7, tc = t - tr * 7;
        int sh = wr * 7 + tr + 3; if (sh >= 56) sh -= 56;
        int sw = wc * 7 + tc + 3; if (sw >= 56) sw -= 56;
        float4 v = *(const float4*)&xb[(sh * 56 + sw) * EDIM + c4];
        smw[OFF_X + t * XROW + (c4 >> 1)]     = packh2(v.x, v.y);
        smw[OFF_X + t * XROW + (c4 >> 1) + 1] = packh2(v.z, v.w);
    }
    __syncthreads();

    // ---- per-warp role: pair = head, wm = token half ----
    const int h  = warp >> 1;
    const int wm = warp & 1;
    const int tb = wm << 5;              // token base 0 or 32
    const int r  = lane >> 2;            // 0..7
    const int cc = lane & 3;             // 0..3

    const uint32_t sb  = (uint32_t)__cvta_generic_to_shared(smw);
    const uint32_t sbK = sb + ((OFF_KV + h * 2560) << 2);
    const uint32_t sbV = sbK + (1280 << 2);
    uint32_t* Ksm = smw + OFF_KV + h * 2560;
    uint32_t* Vsm = Ksm + 1280;
    const uint32_t* Wt = (const uint32_t*)g_qkvwT;

    // ---- X A-frags for this warp's 32 tokens (hd 0..31) ----
    uint32_t xa[2][2][4];
    #pragma unroll
    for (int mt = 0; mt < 2; mt++)
        #pragma unroll
        for (int kt = 0; kt < 2; kt++) {
            uint32_t addr = sb +
                (((tb + (mt << 4) + (lane & 15)) * XROW +
                  (h << 4) + (kt << 3) + ((lane >> 4) << 2)) << 2);
            ldsm4(xa[mt][kt][0], xa[mt][kt][1], xa[mt][kt][2], xa[mt][kt][3], addr);
        }

    // ---- Q (regs), K,V (pair smem) ----
    uint32_t qf[2][2][4];
    #pragma unroll
    for (int mt = 0; mt < 2; mt++) {
        #pragma unroll
        for (int nt = 0; nt < 4; nt++) {
            int n0 = nt << 3;
            // Q
            {
                float b0 = qb[n0 + (cc << 1)], b1 = qb[n0 + (cc << 1) + 1];
                float c[4] = {b0, b1, b0, b1};
                #pragma unroll
                for (int kt = 0; kt < 2; kt++) {
                    uint32_t bb[2] = {Wt[(n0 + r) * 16 + (kt << 3) + cc],
                                      Wt[(n0 + r) * 16 + (kt << 3) + cc + 4]};
                    mma_f16(c, xa[mt][kt], bb);
                }
                int kt2 = nt >> 1;
                if ((nt & 1) == 0) {
                    qf[mt][kt2][0] = packh2(c[0] * SCALE, c[1] * SCALE);
                    qf[mt][kt2][1] = packh2(c[2] * SCALE, c[3] * SCALE);
                } else {
                    qf[mt][kt2][2] = packh2(c[0] * SCALE, c[1] * SCALE);
                    qf[mt][kt2][3] = packh2(c[2] * SCALE, c[3] * SCALE);
                }
            }
            int tok0 = tb + (mt << 4) + r;
            // K
            {
                float b0 = qb[32 + n0 + (cc << 1)], b1 = qb[32 + n0 + (cc << 1) + 1];
                float c[4] = {b0, b1, b0, b1};
                #pragma unroll
                for (int kt = 0; kt < 2; kt++) {
                    uint32_t bb[2] = {Wt[(32 + n0 + r) * 16 + (kt << 3) + cc],
                                      Wt[(32 + n0 + r) * 16 + (kt << 3) + cc + 4]};
                    mma_f16(c, xa[mt][kt], bb);
                }
                Ksm[tok0 * 20 + (nt << 2) + cc]       = packh2(c[0], c[1]);
                Ksm[(tok0 + 8) * 20 + (nt << 2) + cc] = packh2(c[2], c[3]);
            }
            // V
            {
                float b0 = qb[64 + n0 + (cc << 1)], b1 = qb[64 + n0 + (cc << 1) + 1];
                float c[4] = {b0, b1, b0, b1};
                #pragma unroll
                for (int kt = 0; kt < 2; kt++) {
                    uint32_t bb[2] = {Wt[(64 + n0 + r) * 16 + (kt << 3) + cc],
                                      Wt[(64 + n0 + r) * 16 + (kt << 3) + cc + 4]};
                    mma_f16(c, xa[mt][kt], bb);
                }
                Vsm[tok0 * 20 + (nt << 2) + cc]       = packh2(c[0], c[1]);
                Vsm[(tok0 + 8) * 20 + (nt << 2) + cc] = packh2(c[2], c[3]);
            }
        }
    }

    // pair barrier: K/V visible to both warps of this head
    asm volatile("bar.sync %0, 64;" :: "r"(h + 8) : "memory");

    const __half2* tb2 = (const __half2*)g_bias;

    #pragma unroll
    for (int mt = 0; mt < 2; mt++) {
        // ---- S = Q K^T (8 n-tiles x fp32x4) ----
        float sacc[8][4];
        #pragma unroll
        for (int nt = 0; nt < 8; nt++)
            #pragma unroll
            for (int i = 0; i < 4; i++) sacc[nt][i] = 0.f;

        #pragma unroll
        for (int g = 0; g < 4; g++)
            #pragma unroll
            for (int kt = 0; kt < 2; kt++) {
                uint32_t r0, r1, r2, r3;
                uint32_t addr = sbK +
                    ((((g << 4) + (lane & 15)) * 20 + (kt << 3) + ((lane >> 4) << 2)) << 2);
                ldsm4(r0, r1, r2, r3, addr);
                uint32_t blo[2] = {r0, r2};
                uint32_t bhi[2] = {r1, r3};
                mma_f16(sacc[(g << 1)],     qf[mt][kt], blo);
                mma_f16(sacc[(g << 1) + 1], qf[mt][kt], bhi);
            }

        // ---- softmax (rows q0, q0+8; quad of lanes covers a row) ----
        int q0 = tb + (mt << 4) + r;
        int base0 = ((((cls << 3) + h) << 6) + q0) << 5;   // half2 units
        int base1 = base0 + (8 << 5);
        #pragma unroll
        for (int nt = 0; nt < 8; nt++) {
            float2 b0 = __half22float2(tb2[base0 + (nt << 2) + cc]);
            float2 b1 = __half22float2(tb2[base1 + (nt << 2) + cc]);
            sacc[nt][0] += b0.x; sacc[nt][1] += b0.y;
            sacc[nt][2] += b1.x; sacc[nt][3] += b1.y;
        }
        float m0 = -1e30f, m1 = -1e30f;
        #pragma unroll
        for (int nt = 0; nt < 8; nt++) {
            m0 = fmaxf(m0, fmaxf(sacc[nt][0], sacc[nt][1]));
            m1 = fmaxf(m1, fmaxf(sacc[nt][2], sacc[nt][3]));
        }
        m0 = fmaxf(m0, __shfl_xor_sync(0xffffffffu, m0, 1));
        m0 = fmaxf(m0, __shfl_xor_sync(0xffffffffu, m0, 2));
        m1 = fmaxf(m1, __shfl_xor_sync(0xffffffffu, m1, 1));
        m1 = fmaxf(m1, __shfl_xor_sync(0xffffffffu, m1, 2));
        float s0 = 0.f, s1 = 0.f;
        #pragma unroll
        for (int nt = 0; nt < 8; nt++) {
            sacc[nt][0] = __expf(sacc[nt][0] - m0); s0 += sacc[nt][0];
            sacc[nt][1] = __expf(sacc[nt][1] - m0); s0 += sacc[nt][1];
            sacc[nt][2] = __expf(sacc[nt][2] - m1); s1 += sacc[nt][2];
            sacc[nt][3] = __expf(sacc[nt][3] - m1); s1 += sacc[nt][3];
        }
        s0 += __shfl_xor_sync(0xffffffffu, s0, 1);
        s0 += __shfl_xor_sync(0xffffffffu, s0, 2);
        s1 += __shfl_xor_sync(0xffffffffu, s1, 1);
        s1 += __shfl_xor_sync(0xffffffffu, s1, 2);
        float inv0 = __frcp_rn(s0), inv1 = __frcp_rn(s1);

        uint32_t pf[4][4];
        #pragma unroll
        for (int nt = 0; nt < 8; nt++) {
            int kt2 = nt >> 1;
            uint32_t plo = packh2(sacc[nt][0] * inv0, sacc[nt][1] * inv0);
            uint32_t phi = packh2(sacc[nt][2] * inv1, sacc[nt][3] * inv1);
            if ((nt & 1) == 0) { pf[kt2][0] = plo; pf[kt2][1] = phi; }
            else               { pf[kt2][2] = plo; pf[kt2][3] = phi; }
        }

        // ---- O = P V ----
        float oacc[4][4];
        #pragma unroll
        for (int nt = 0; nt < 4; nt++)
            #pragma unroll
            for (int i = 0; i < 4; i++) oacc[nt][i] = 0.f;

        #pragma unroll
        for (int kt2 = 0; kt2 < 4; kt2++)
            #pragma unroll
            for (int vh2 = 0; vh2 < 2; vh2++) {
                uint32_t r0, r1, r2, r3;
                uint32_t addr = sbV +
                    ((((kt2 << 4) + (lane & 15)) * 20 + (vh2 << 3) + ((lane >> 4) << 2)) << 2);
                ldsm4t(r0, r1, r2, r3, addr);
                uint32_t blo[2] = {r0, r1};
                uint32_t bhi[2] = {r2, r3};
                mma_f16(oacc[(vh2 << 1)],     pf[kt2], blo);
                mma_f16(oacc[(vh2 << 1) + 1], pf[kt2], bhi);
            }

        // ---- store shift-reversed ----
        #pragma unroll
        for (int ntv = 0; ntv < 4; ntv++) {
            int col = (h << 5) + (ntv << 3) + (cc << 1);
            if (q0 < WD)
                *(uint32_t*)&ob[pixs[q0] * EDIM + col] = packh2(oacc[ntv][0], oacc[ntv][1]);
            if (q0 + 8 < WD)
                *(uint32_t*)&ob[pixs[q0 + 8] * EDIM + col] = packh2(oacc[ntv][2], oacc[ntv][3]);
        }
    }
}

// ---------------------------------------------------------------------------
// Projection: out[M,N] = g_mid(fp16)[M,256] @ g_wpT^T + proj_b (unchanged R5)
// ---------------------------------------------------------------------------
__device__ __forceinline__ void cpasync16(uint32_t s, const void* g) {
    asm volatile("cp.async.cg.shared.global [%0], [%1], 16;\n"
                 :: "r"(s), "l"(g) : "memory");
}

#define PJ_AW       2560
#define PJ_STRIDEW  3840
#define PJ_SMEM_BYTES (PJ_STRIDEW * 2 * 4)

__global__ void __launch_bounds__(256)
swin_proj_kernel(const float* __restrict__ pb,
                 float* __restrict__ out)
{
    extern __shared__ uint32_t pjw[];
    const int tid  = threadIdx.x;
    const int lane = tid & 31;
    const int warp = tid >> 5;
    const int mW = (warp >> 1) << 5;
    const int nW = (warp & 1) << 5;
    const int rowBase = blockIdx.y << 7;
    const int nBase   = blockIdx.x << 6;
    const __half* A16 = g_mid;
    const __half* B16 = g_wpT;
    const uint32_t sbase = (uint32_t)__cvta_generic_to_shared(pjw);

    float acc[2][4][4];
    #pragma unroll
    for (int mt = 0; mt < 2; mt++)
        #pragma unroll
        for (int nt = 0; nt < 4; nt++)
            #pragma unroll
            for (int i = 0; i < 4; i++)
                acc[mt][nt][i] = 0.f;

    {
        #pragma unroll
        for (int l = 0; l < 2; l++) {
            int idx = tid + (l << 8);
            int row = idx >> 2, c16 = idx & 3;
            cpasync16(sbase + ((row * 20 + (c16 << 2)) << 2),
                      &A16[(size_t)(rowBase + row) * 256 + (c16 << 3)]);
        }
        {
            int row = tid >> 2, c16 = tid & 3;
            cpasync16(sbase + ((PJ_AW + row * 20 + (c16 << 2)) << 2),
                      &B16[(size_t)(nBase + row) * 256 + (c16 << 3)]);
        }
        asm volatile("cp.async.commit_group;\n" ::: "memory");
    }

    const int r  = lane >> 2;
    const int cc = lane & 3;

    for (int kc = 0; kc < 8; kc++) {
        int buf = kc & 1;
        asm volatile("cp.async.wait_group 0;\n" ::: "memory");
        __syncthreads();
        if (kc < 7) {
            int fb = (buf ^ 1) * PJ_STRIDEW;
            int k0 = (kc + 1) << 5;
            #pragma unroll
            for (int l = 0; l < 2; l++) {
                int idx = tid + (l << 8);
                int row = idx >> 2, c16 = idx & 3;
                cpasync16(sbase + ((fb + row * 20 + (c16 << 2)) << 2),
                          &A16[(size_t)(rowBase + row) * 256 + k0 + (c16 << 3)]);
            }
            {
                int row = tid >> 2, c16 = tid & 3;
                cpasync16(sbase + ((fb + PJ_AW + row * 20 + (c16 << 2)) << 2),
                          &B16[(size_t)(nBase + row) * 256 + k0 + (c16 << 3)]);
            }
            asm volatile("cp.async.commit_group;\n" ::: "memory");
        }

        const uint32_t* As = pjw + buf * PJ_STRIDEW;
        const uint32_t* Bs = As + PJ_AW;
        #pragma unroll
        for (int kk = 0; kk < 2; kk++) {
            uint32_t a[2][4], bb[4][2];
            #pragma unroll
            for (int mt2 = 0; mt2 < 2; mt2++) {
                int rb = mW + (mt2 << 4) + r;
                const uint32_t* ap = As + rb * 20 + (kk << 3) + cc;
                a[mt2][0] = ap[0];
                a[mt2][1] = ap[160];
                a[mt2][2] = ap[4];
                a[mt2][3] = ap[164];
            }
            #pragma unroll
            for (int nt = 0; nt < 4; nt++) {
                int n = nW + (nt << 3) + r;
                const uint32_t* bp = Bs + n * 20 + (kk << 3) + cc;
                bb[nt][0] = bp[0];
                bb[nt][1] = bp[4];
            }
            #pragma unroll
            for (int mt2 = 0; mt2 < 2; mt2++)
                #pragma unroll
                for (int nt = 0; nt < 4; nt++)
                    mma_f16(acc[mt2][nt], a[mt2], bb[nt]);
        }
        __syncthreads();
    }

    #pragma unroll
    for (int mt2 = 0; mt2 < 2; mt2++) {
        int row = rowBase + mW + (mt2 << 4) + (lane >> 2);
        #pragma unroll
        for (int nt = 0; nt < 4; nt++) {
            int col = nBase + nW + (nt << 3) + ((lane & 3) << 1);
            float b0 = pb[col], b1 = pb[col + 1];
            float2 v0 = make_float2(acc[mt2][nt][0] + b0, acc[mt2][nt][1] + b1);
            float2 v1 = make_float2(acc[mt2][nt][2] + b0, acc[mt2][nt][3] + b1);
            *(float2*)&out[(size_t)row * 256 + col]       = v0;
            *(float2*)&out[(size_t)(row + 8) * 256 + col] = v1;
        }
    }
}

extern "C" void kernel_launch(void* const* d_in, const int* in_sizes, int n_in,
                              void* d_out, int out_size)
{
    (void)in_sizes; (void)n_in; (void)out_size;
    const float* x      = (const float*)d_in[0];
    const float* qkv_w  = (const float*)d_in[1];
    const float* qkv_b  = (const float*)d_in[2];
    const float* proj_w = (const float*)d_in[3];
    const float* proj_b = (const float*)d_in[4];
    const float* rpb    = (const float*)d_in[5];
    float* out = (float*)d_out;

    cudaFuncSetAttribute(swin_attn_kernel,
                         cudaFuncAttributeMaxDynamicSharedMemorySize, AT_SMEM_BYTES);
    cudaFuncSetAttribute(swin_proj_kernel,
                         cudaFuncAttributeMaxDynamicSharedMemorySize, PJ_SMEM_BYTES);

    swin_prep_kernel<<<512, 256>>>(qkv_w, proj_w, rpb);
    swin_attn_kernel<<<BATCH * 64, 512, AT_SMEM_BYTES>>>(x, qkv_b);
    swin_proj_kernel<<<dim3(4, 784), 256, PJ_SMEM_BYTES>>>(proj_b, out);
}

// round 8
// speedup vs baseline: 4.9633x; 1.0524x over previous
#include <cuda_runtime.h>
#include <cuda_fp16.h>
#include <cstdint>

// ---------------------------------------------------------------------------
// SWMSA: B=32, H=W=56, E=256, NH=8, HD=32, WS=7, WD=49, NW=64, SS=3
// R8 = R7 with the bias-prefetch indexing bug fixed (half2 units, R6 layout).
//   - attention QKV weights staged in smem (ldmatrix B-frags, no LDG in chain)
//   - bias prefetched into regs before the S-mma chain
//   - proj: full-B staging + 2-deep cp.async pipeline over K=64 chunks
// ---------------------------------------------------------------------------

#define BATCH 32
#define HWPIX 3136
#define EDIM  256
#define WD    49
#define SCALE 0.17677669529663687f   // 1/sqrt(32)

__device__ __align__(16) __half g_mid[(size_t)BATCH * HWPIX * EDIM];
__device__ __align__(16) __half g_wpT[65536];    // proj_w^T fp16 [n][k]
__device__ __align__(16) __half g_qkvwT[3072];   // qkv_w^T fp16 [n][k]
__device__ __align__(16) __half g_bias[4 * 8 * 64 * 64];

__device__ __forceinline__ void mma_f16(float* c, const uint32_t* a, const uint32_t* b) {
    asm volatile(
        "mma.sync.aligned.m16n8k16.row.col.f32.f16.f16.f32 "
        "{%0,%1,%2,%3}, {%4,%5,%6,%7}, {%8,%9}, {%0,%1,%2,%3};\n"
        : "+f"(c[0]), "+f"(c[1]), "+f"(c[2]), "+f"(c[3])
        : "r"(a[0]), "r"(a[1]), "r"(a[2]), "r"(a[3]), "r"(b[0]), "r"(b[1]));
}
__device__ __forceinline__ uint32_t h2u(__half2 h) { return *(uint32_t*)&h; }
__device__ __forceinline__ uint32_t packh2(float x, float y) {
    return h2u(__floats2half2_rn(x, y));
}
__device__ __forceinline__ void ldsm4(uint32_t& r0, uint32_t& r1, uint32_t& r2,
                                      uint32_t& r3, uint32_t addr) {
    asm volatile("ldmatrix.sync.aligned.m8n8.x4.shared.b16 {%0,%1,%2,%3}, [%4];"
                 : "=r"(r0), "=r"(r1), "=r"(r2), "=r"(r3) : "r"(addr));
}
__device__ __forceinline__ void ldsm4t(uint32_t& r0, uint32_t& r1, uint32_t& r2,
                                       uint32_t& r3, uint32_t addr) {
    asm volatile("ldmatrix.sync.aligned.m8n8.x4.trans.shared.b16 {%0,%1,%2,%3}, [%4];"
                 : "=r"(r0), "=r"(r1), "=r"(r2), "=r"(r3) : "r"(addr));
}
__device__ __forceinline__ void cpasync16(uint32_t s, const void* g) {
    asm volatile("cp.async.cg.shared.global [%0], [%1], 16;\n"
                 :: "r"(s), "l"(g) : "memory");
}

// ---------------- prep kernel ----------------
__global__ void __launch_bounds__(256)
swin_prep_kernel(const float* __restrict__ qkv_w,
                 const float* __restrict__ proj_w,
                 const float* __restrict__ rpb_table)
{
    int idx = blockIdx.x * 256 + threadIdx.x;   // grid 512 -> 131072
    if (idx < 3072) {
        int n = idx >> 5, k = idx & 31;
        g_qkvwT[idx] = __float2half(qkv_w[k * 96 + n]);
    }
    if (idx < 65536) {
        int n = idx >> 8, k = idx & 255;
        g_wpT[idx] = __float2half(proj_w[k * 256 + n]);
    }
    {
        int cls = idx >> 15, h = (idx >> 12) & 7, i = (idx >> 6) & 63, j = idx & 63;
        float v = -30000.0f;
        if (i < WD && j < WD) {
            int tri = i / 7, tci = i - tri * 7;
            int trj = j / 7, tcj = j - trj * 7;
            int li = tri * 13 + tci, lj = trj * 13 + tcj;
            v = rpb_table[(li - lj + 84) * 8 + h];
            int bot = cls & 1, rgt = (cls >> 1) & 1;
            int ri = (bot ? (tri < 4 ? 1 : 2) : 0) * 3 + (rgt ? (tci < 4 ? 1 : 2) : 0);
            int rj = (bot ? (trj < 4 ? 1 : 2) : 0) * 3 + (rgt ? (tcj < 4 ? 1 : 2) : 0);
            if (ri != rj) v -= 100.0f;
        }
        g_bias[idx] = __float2half(v);
    }
}

// ---------------- attention kernel ----------------
#define XROW    132
#define OFF_X   0
#define OFF_KV  8448               // 8 heads x 2560 words (K 64x20, V 64x20)
#define OFF_PIX 28928              // 64 ints
#define OFF_QB  28992              // 96 floats
#define OFF_W   29088              // 96 rows x 20 words (qkv weights fp16)
#define AT_SMEM_WORDS 31008
#define AT_SMEM_BYTES (AT_SMEM_WORDS * 4)

__global__ void __launch_bounds__(512)
swin_attn_kernel(const float* __restrict__ x,
                 const float* __restrict__ qkv_b)
{
    extern __shared__ uint32_t smw[];
    const int tid  = threadIdx.x;
    const int warp = tid >> 5;
    const int lane = tid & 31;
    const int bi   = blockIdx.x;
    const int b    = bi >> 6;
    const int w    = bi & 63;
    const int wr   = w >> 3, wc = w & 7;
    const int cls  = (wr == 7 ? 1 : 0) | (wc == 7 ? 2 : 0);

    const float* xb = x + (size_t)b * HWPIX * EDIM;
    __half*      ob = g_mid + (size_t)b * HWPIX * EDIM;

    float* qb   = (float*)(smw + OFF_QB);
    int*   pixs = (int*)(smw + OFF_PIX);
    const uint32_t sb = (uint32_t)__cvta_generic_to_shared(smw);

    // ---- stage qkv weights into smem via cp.async ----
    for (int i = tid; i < 384; i += 512) {
        int row = i >> 2, c = i & 3;
        cpasync16(sb + ((OFF_W + row * 20 + (c << 2)) << 2),
                  (const char*)g_qkvwT + row * 64 + c * 16);
    }
    asm volatile("cp.async.commit_group;\n" ::: "memory");

    // ---- init: qkv bias, pix LUT, X pad rows ----
    if (tid < 96) qb[tid] = qkv_b[tid];
    if (tid < 64) {
        int p = 0;
        if (tid < WD) {
            int tr = tid / 7, tc = tid - tr * 7;
            int sh = wr * 7 + tr + 3; if (sh >= 56) sh -= 56;
            int sw = wc * 7 + tc + 3; if (sw >= 56) sw -= 56;
            p = sh * 56 + sw;
        }
        pixs[tid] = p;
    }
    for (int i = tid; i < 15 * XROW; i += 512)
        smw[OFF_X + 49 * XROW + i] = 0u;

    // ---- X load: 49 rows x 256 floats -> fp16 smem ----
    for (int i = tid; i < 3136; i += 512) {
        int t  = i >> 6;
        int c4 = (i & 63) << 2;
        int tr = t / 7, tc = t - tr * 7;
        int sh = wr * 7 + tr + 3; if (sh >= 56) sh -= 56;
        int sw = wc * 7 + tc + 3; if (sw >= 56) sw -= 56;
        float4 v = *(const float4*)&xb[(sh * 56 + sw) * EDIM + c4];
        smw[OFF_X + t * XROW + (c4 >> 1)]     = packh2(v.x, v.y);
        smw[OFF_X + t * XROW + (c4 >> 1) + 1] = packh2(v.z, v.w);
    }
    asm volatile("cp.async.wait_group 0;\n" ::: "memory");
    __syncthreads();

    // ---- per-warp role ----
    const int h  = warp >> 1;
    const int wm = warp & 1;
    const int tb = wm << 5;
    const int r  = lane >> 2;
    const int cc = lane & 3;

    const uint32_t sbK = sb + ((OFF_KV + h * 2560) << 2);
    const uint32_t sbV = sbK + (1280 << 2);
    const uint32_t sbW = sb + (OFF_W << 2);
    uint32_t* Ksm = smw + OFF_KV + h * 2560;
    uint32_t* Vsm = Ksm + 1280;

    // ---- X A-frags ----
    uint32_t xa[2][2][4];
    #pragma unroll
    for (int mt = 0; mt < 2; mt++)
        #pragma unroll
        for (int kt = 0; kt < 2; kt++) {
            uint32_t addr = sb +
                (((tb + (mt << 4) + (lane & 15)) * XROW +
                  (h << 4) + (kt << 3) + ((lane >> 4) << 2)) << 2);
            ldsm4(xa[mt][kt][0], xa[mt][kt][1], xa[mt][kt][2], xa[mt][kt][3], addr);
        }

    // ---- QKV via smem weights (ldmatrix B-frags) ----
    uint32_t qf[2][2][4];
    #pragma unroll
    for (int sec = 0; sec < 3; sec++) {
        uint32_t bf[2][2][4];
        #pragma unroll
        for (int g = 0; g < 2; g++)
            #pragma unroll
            for (int kt = 0; kt < 2; kt++) {
                uint32_t addr = sbW +
                    (((sec * 32 + (g << 4) + (lane & 15)) * 20 +
                      (kt << 3) + ((lane >> 4) << 2)) << 2);
                ldsm4(bf[g][kt][0], bf[g][kt][1], bf[g][kt][2], bf[g][kt][3], addr);
            }
        #pragma unroll
        for (int mt = 0; mt < 2; mt++) {
            int tok0 = tb + (mt << 4) + r;
            #pragma unroll
            for (int nt = 0; nt < 4; nt++) {
                int n0 = nt << 3;
                float b0 = qb[sec * 32 + n0 + (cc << 1)];
                float b1 = qb[sec * 32 + n0 + (cc << 1) + 1];
                float c[4] = {b0, b1, b0, b1};
                int g = nt >> 1, hi = nt & 1;
                #pragma unroll
                for (int kt = 0; kt < 2; kt++) {
                    uint32_t bb[2];
                    bb[0] = hi ? bf[g][kt][1] : bf[g][kt][0];
                    bb[1] = hi ? bf[g][kt][3] : bf[g][kt][2];
                    mma_f16(c, xa[mt][kt], bb);
                }
                if (sec == 0) {
                    int kt2 = nt >> 1;
                    if ((nt & 1) == 0) {
                        qf[mt][kt2][0] = packh2(c[0] * SCALE, c[1] * SCALE);
                        qf[mt][kt2][1] = packh2(c[2] * SCALE, c[3] * SCALE);
                    } else {
                        qf[mt][kt2][2] = packh2(c[0] * SCALE, c[1] * SCALE);
                        qf[mt][kt2][3] = packh2(c[2] * SCALE, c[3] * SCALE);
                    }
                } else if (sec == 1) {
                    Ksm[tok0 * 20 + (nt << 2) + cc]       = packh2(c[0], c[1]);
                    Ksm[(tok0 + 8) * 20 + (nt << 2) + cc] = packh2(c[2], c[3]);
                } else {
                    Vsm[tok0 * 20 + (nt << 2) + cc]       = packh2(c[0], c[1]);
                    Vsm[(tok0 + 8) * 20 + (nt << 2) + cc] = packh2(c[2], c[3]);
                }
            }
        }
    }

    asm volatile("bar.sync %0, 64;" :: "r"(h + 8) : "memory");

    const __half2* tb2 = (const __half2*)g_bias;

    #pragma unroll
    for (int mt = 0; mt < 2; mt++) {
        int q0 = tb + (mt << 4) + r;
        // ---- prefetch bias in regs (R6-proven indexing, half2 units) ----
        int base0 = ((((cls << 3) + h) << 6) + q0) << 5;
        int base1 = base0 + (8 << 5);
        __half2 bias_lo[8], bias_hi[8];
        #pragma unroll
        for (int nt = 0; nt < 8; nt++) {
            bias_lo[nt] = tb2[base0 + (nt << 2) + cc];
            bias_hi[nt] = tb2[base1 + (nt << 2) + cc];
        }

        // ---- S = Q K^T ----
        float sacc[8][4];
        #pragma unroll
        for (int nt = 0; nt < 8; nt++)
            #pragma unroll
            for (int i = 0; i < 4; i++) sacc[nt][i] = 0.f;

        #pragma unroll
        for (int g = 0; g < 4; g++)
            #pragma unroll
            for (int kt = 0; kt < 2; kt++) {
                uint32_t r0, r1, r2, r3;
                uint32_t addr = sbK +
                    ((((g << 4) + (lane & 15)) * 20 + (kt << 3) + ((lane >> 4) << 2)) << 2);
                ldsm4(r0, r1, r2, r3, addr);
                uint32_t blo[2] = {r0, r2};
                uint32_t bhi[2] = {r1, r3};
                mma_f16(sacc[(g << 1)],     qf[mt][kt], blo);
                mma_f16(sacc[(g << 1) + 1], qf[mt][kt], bhi);
            }

        // ---- softmax ----
        #pragma unroll
        for (int nt = 0; nt < 8; nt++) {
            float2 b0 = __half22float2(bias_lo[nt]);
            float2 b1 = __half22float2(bias_hi[nt]);
            sacc[nt][0] += b0.x; sacc[nt][1] += b0.y;
            sacc[nt][2] += b1.x; sacc[nt][3] += b1.y;
        }
        float m0 = -1e30f, m1 = -1e30f;
        #pragma unroll
        for (int nt = 0; nt < 8; nt++) {
            m0 = fmaxf(m0, fmaxf(sacc[nt][0], sacc[nt][1]));
            m1 = fmaxf(m1, fmaxf(sacc[nt][2], sacc[nt][3]));
        }
        m0 = fmaxf(m0, __shfl_xor_sync(0xffffffffu, m0, 1));
        m0 = fmaxf(m0, __shfl_xor_sync(0xffffffffu, m0, 2));
        m1 = fmaxf(m1, __shfl_xor_sync(0xffffffffu, m1, 1));
        m1 = fmaxf(m1, __shfl_xor_sync(0xffffffffu, m1, 2));
        float s0 = 0.f, s1 = 0.f;
        #pragma unroll
        for (int nt = 0; nt < 8; nt++) {
            sacc[nt][0] = __expf(sacc[nt][0] - m0); s0 += sacc[nt][0];
            sacc[nt][1] = __expf(sacc[nt][1] - m0); s0 += sacc[nt][1];
            sacc[nt][2] = __expf(sacc[nt][2] - m1); s1 += sacc[nt][2];
            sacc[nt][3] = __expf(sacc[nt][3] - m1); s1 += sacc[nt][3];
        }
        s0 += __shfl_xor_sync(0xffffffffu, s0, 1);
        s0 += __shfl_xor_sync(0xffffffffu, s0, 2);
        s1 += __shfl_xor_sync(0xffffffffu, s1, 1);
        s1 += __shfl_xor_sync(0xffffffffu, s1, 2);
        float inv0 = __frcp_rn(s0), inv1 = __frcp_rn(s1);

        uint32_t pf[4][4];
        #pragma unroll
        for (int nt = 0; nt < 8; nt++) {
            int kt2 = nt >> 1;
            uint32_t plo = packh2(sacc[nt][0] * inv0, sacc[nt][1] * inv0);
            uint32_t phi = packh2(sacc[nt][2] * inv1, sacc[nt][3] * inv1);
            if ((nt & 1) == 0) { pf[kt2][0] = plo; pf[kt2][1] = phi; }
            else               { pf[kt2][2] = plo; pf[kt2][3] = phi; }
        }

        // ---- O = P V ----
        float oacc[4][4];
        #pragma unroll
        for (int nt = 0; nt < 4; nt++)
            #pragma unroll
            for (int i = 0; i < 4; i++) oacc[nt][i] = 0.f;

        #pragma unroll
        for (int kt2 = 0; kt2 < 4; kt2++)
            #pragma unroll
            for (int vh2 = 0; vh2 < 2; vh2++) {
                uint32_t r0, r1, r2, r3;
                uint32_t addr = sbV +
                    ((((kt2 << 4) + (lane & 15)) * 20 + (vh2 << 3) + ((lane >> 4) << 2)) << 2);
                ldsm4t(r0, r1, r2, r3, addr);
                uint32_t blo[2] = {r0, r1};
                uint32_t bhi[2] = {r2, r3};
                mma_f16(oacc[(vh2 << 1)],     pf[kt2], blo);
                mma_f16(oacc[(vh2 << 1) + 1], pf[kt2], bhi);
            }

        // ---- store shift-reversed ----
        #pragma unroll
        for (int ntv = 0; ntv < 4; ntv++) {
            int col = (h << 5) + (ntv << 3) + (cc << 1);
            if (q0 < WD)
                *(uint32_t*)&ob[pixs[q0] * EDIM + col] = packh2(oacc[ntv][0], oacc[ntv][1]);
            if (q0 + 8 < WD)
                *(uint32_t*)&ob[pixs[q0 + 8] * EDIM + col] = packh2(oacc[ntv][2], oacc[ntv][3]);
        }
    }
}

// ---------------------------------------------------------------------------
// Projection: out[M,N] = g_mid(fp16)[M,256] @ g_wpT^T + proj_b
// Full B tile staged once; A double-buffered over 4 K-chunks of 64 with
// 2-deep cp.async lookahead (wait_group 1).
// ---------------------------------------------------------------------------
#define PJ_BOFF 0                       // 64 rows x 132 words
#define PJ_AOFF 8448                    // 2 bufs x (128 rows x 36 words)
#define PJ_SMEM_WORDS (8448 + 2 * 4608)
#define PJ_SMEM_BYTES (PJ_SMEM_WORDS * 4)

__global__ void __launch_bounds__(256)
swin_proj_kernel(const float* __restrict__ pb,
                 float* __restrict__ out)
{
    extern __shared__ uint32_t pjw[];
    const int tid  = threadIdx.x;
    const int lane = tid & 31;
    const int warp = tid >> 5;
    const int mW = (warp >> 1) << 5;
    const int nW = (warp & 1) << 5;
    const int rowBase = blockIdx.y << 7;
    const int nBase   = blockIdx.x << 6;
    const __half* A16 = g_mid;
    const __half* B16 = g_wpT;
    const uint32_t sbase = (uint32_t)__cvta_generic_to_shared(pjw);

    float acc[2][4][4];
    #pragma unroll
    for (int mt = 0; mt < 2; mt++)
        #pragma unroll
        for (int nt = 0; nt < 4; nt++)
            #pragma unroll
            for (int i = 0; i < 4; i++)
                acc[mt][nt][i] = 0.f;

    // group 0: full B + A chunk 0
    #pragma unroll
    for (int l = 0; l < 8; l++) {
        int idx = tid + (l << 8);
        int row = idx >> 5, c16 = idx & 31;
        cpasync16(sbase + ((PJ_BOFF + row * 132 + (c16 << 2)) << 2),
                  &B16[(size_t)(nBase + row) * 256 + (c16 << 3)]);
    }
    #pragma unroll
    for (int l = 0; l < 4; l++) {
        int idx = tid + (l << 8);
        int row = idx >> 3, c16 = idx & 7;
        cpasync16(sbase + ((PJ_AOFF + row * 36 + (c16 << 2)) << 2),
                  &A16[(size_t)(rowBase + row) * 256 + (c16 << 3)]);
    }
    asm volatile("cp.async.commit_group;\n" ::: "memory");
    // group 1: A chunk 1
    #pragma unroll
    for (int l = 0; l < 4; l++) {
        int idx = tid + (l << 8);
        int row = idx >> 3, c16 = idx & 7;
        cpasync16(sbase + ((PJ_AOFF + 4608 + row * 36 + (c16 << 2)) << 2),
                  &A16[(size_t)(rowBase + row) * 256 + 64 + (c16 << 3)]);
    }
    asm volatile("cp.async.commit_group;\n" ::: "memory");

    const int r  = lane >> 2;
    const int cc = lane & 3;

    for (int kc = 0; kc < 4; kc++) {
        int buf = kc & 1;
        if (kc < 3) asm volatile("cp.async.wait_group 1;\n" ::: "memory");
        else        asm volatile("cp.async.wait_group 0;\n" ::: "memory");
        __syncthreads();

        const uint32_t* As = pjw + PJ_AOFF + buf * 4608;
        const uint32_t* Bs = pjw + PJ_BOFF;
        #pragma unroll
        for (int kt = 0; kt < 4; kt++) {
            int bko = (kc << 5) + (kt << 3);
            uint32_t a[2][4], bb[4][2];
            #pragma unroll
            for (int mt2 = 0; mt2 < 2; mt2++) {
                int rb = mW + (mt2 << 4) + r;
                const uint32_t* ap = As + rb * 36 + (kt << 3) + cc;
                a[mt2][0] = ap[0];
                a[mt2][1] = ap[288];
                a[mt2][2] = ap[4];
                a[mt2][3] = ap[292];
            }
            #pragma unroll
            for (int nt = 0; nt < 4; nt++) {
                int n = nW + (nt << 3) + r;
                const uint32_t* bp = Bs + n * 132 + bko + cc;
                bb[nt][0] = bp[0];
                bb[nt][1] = bp[4];
            }
            #pragma unroll
            for (int mt2 = 0; mt2 < 2; mt2++)
                #pragma unroll
                for (int nt = 0; nt < 4; nt++)
                    mma_f16(acc[mt2][nt], a[mt2], bb[nt]);
        }
        __syncthreads();

        if (kc < 2) {
            int k0 = (kc + 2) << 6;
            #pragma unroll
            for (int l = 0; l < 4; l++) {
                int idx = tid + (l << 8);
                int row = idx >> 3, c16 = idx & 7;
                cpasync16(sbase + ((PJ_AOFF + buf * 4608 + row * 36 + (c16 << 2)) << 2),
                          &A16[(size_t)(rowBase + row) * 256 + k0 + (c16 << 3)]);
            }
            asm volatile("cp.async.commit_group;\n" ::: "memory");
        }
    }

    #pragma unroll
    for (int mt2 = 0; mt2 < 2; mt2++) {
        int row = rowBase + mW + (mt2 << 4) + (lane >> 2);
        #pragma unroll
        for (int nt = 0; nt < 4; nt++) {
            int col = nBase + nW + (nt << 3) + ((lane & 3) << 1);
            float b0 = pb[col], b1 = pb[col + 1];
            float2 v0 = make_float2(acc[mt2][nt][0] + b0, acc[mt2][nt][1] + b1);
            float2 v1 = make_float2(acc[mt2][nt][2] + b0, acc[mt2][nt][3] + b1);
            *(float2*)&out[(size_t)row * 256 + col]       = v0;
            *(float2*)&out[(size_t)(row + 8) * 256 + col] = v1;
        }
    }
}

extern "C" void kernel_launch(void* const* d_in, const int* in_sizes, int n_in,
                              void* d_out, int out_size)
{
    (void)in_sizes; (void)n_in; (void)out_size;
    const float* x      = (const float*)d_in[0];
    const float* qkv_w  = (const float*)d_in[1];
    const float* qkv_b  = (const float*)d_in[2];
    const float* proj_w = (const float*)d_in[3];
    const float* proj_b = (const float*)d_in[4];
    const float* rpb    = (const float*)d_in[5];
    float* out = (float*)d_out;

    cudaFuncSetAttribute(swin_attn_kernel,
                         cudaFuncAttributeMaxDynamicSharedMemorySize, AT_SMEM_BYTES);
    cudaFuncSetAttribute(swin_proj_kernel,
                         cudaFuncAttributeMaxDynamicSharedMemorySize, PJ_SMEM_BYTES);

    swin_prep_kernel<<<512, 256>>>(qkv_w, proj_w, rpb);
    swin_attn_kernel<<<BATCH * 64, 512, AT_SMEM_BYTES>>>(x, qkv_b);
    swin_proj_kernel<<<dim3(4, 784), 256, PJ_SMEM_BYTES>>>(proj_b, out);
}

// round 10
// speedup vs baseline: 5.2863x; 1.0651x over previous
#include <cuda_runtime.h>
#include <cuda_fp16.h>
#include <cstdint>

// ---------------------------------------------------------------------------
// SWMSA: B=32, H=W=56, E=256, NH=8, HD=32, WS=7, WD=49, NW=64, SS=3
// R10: attention split into 2 blocks/window (256 thr, 4 heads each) for
//      2-blocks/SM occupancy; per-head qkv means each block needs only its
//      half of X. Pipeline otherwise identical to R8. Proj = R8 (fp16 mma).
// ---------------------------------------------------------------------------

#define BATCH 32
#define HWPIX 3136
#define EDIM  256
#define WD    49
#define SCALE 0.17677669529663687f   // 1/sqrt(32)

__device__ __align__(16) __half g_mid[(size_t)BATCH * HWPIX * EDIM];
__device__ __align__(16) __half g_wpT[65536];    // proj_w^T fp16 [n][k]
__device__ __align__(16) __half g_qkvwT[3072];   // qkv_w^T fp16 [n][k]
__device__ __align__(16) __half g_bias[4 * 8 * 64 * 64];

__device__ __forceinline__ void mma_f16(float* c, const uint32_t* a, const uint32_t* b) {
    asm volatile(
        "mma.sync.aligned.m16n8k16.row.col.f32.f16.f16.f32 "
        "{%0,%1,%2,%3}, {%4,%5,%6,%7}, {%8,%9}, {%0,%1,%2,%3};\n"
        : "+f"(c[0]), "+f"(c[1]), "+f"(c[2]), "+f"(c[3])
        : "r"(a[0]), "r"(a[1]), "r"(a[2]), "r"(a[3]), "r"(b[0]), "r"(b[1]));
}
__device__ __forceinline__ uint32_t h2u(__half2 h) { return *(uint32_t*)&h; }
__device__ __forceinline__ uint32_t packh2(float x, float y) {
    return h2u(__floats2half2_rn(x, y));
}
__device__ __forceinline__ void ldsm4(uint32_t& r0, uint32_t& r1, uint32_t& r2,
                                      uint32_t& r3, uint32_t addr) {
    asm volatile("ldmatrix.sync.aligned.m8n8.x4.shared.b16 {%0,%1,%2,%3}, [%4];"
                 : "=r"(r0), "=r"(r1), "=r"(r2), "=r"(r3) : "r"(addr));
}
__device__ __forceinline__ void ldsm4t(uint32_t& r0, uint32_t& r1, uint32_t& r2,
                                       uint32_t& r3, uint32_t addr) {
    asm volatile("ldmatrix.sync.aligned.m8n8.x4.trans.shared.b16 {%0,%1,%2,%3}, [%4];"
                 : "=r"(r0), "=r"(r1), "=r"(r2), "=r"(r3) : "r"(addr));
}
__device__ __forceinline__ void cpasync16(uint32_t s, const void* g) {
    asm volatile("cp.async.cg.shared.global [%0], [%1], 16;\n"
                 :: "r"(s), "l"(g) : "memory");
}

// ---------------- prep kernel ----------------
__global__ void __launch_bounds__(256)
swin_prep_kernel(const float* __restrict__ qkv_w,
                 const float* __restrict__ proj_w,
                 const float* __restrict__ rpb_table)
{
    int idx = blockIdx.x * 256 + threadIdx.x;   // grid 512 -> 131072
    if (idx < 3072) {
        int n = idx >> 5, k = idx & 31;
        g_qkvwT[idx] = __float2half(qkv_w[k * 96 + n]);
    }
    if (idx < 65536) {
        int n = idx >> 8, k = idx & 255;
        g_wpT[idx] = __float2half(proj_w[k * 256 + n]);
    }
    {
        int cls = idx >> 15, h = (idx >> 12) & 7, i = (idx >> 6) & 63, j = idx & 63;
        float v = -30000.0f;
        if (i < WD && j < WD) {
            int tri = i / 7, tci = i - tri * 7;
            int trj = j / 7, tcj = j - trj * 7;
            int li = tri * 13 + tci, lj = trj * 13 + tcj;
            v = rpb_table[(li - lj + 84) * 8 + h];
            int bot = cls & 1, rgt = (cls >> 1) & 1;
            int ri = (bot ? (tri < 4 ? 1 : 2) : 0) * 3 + (rgt ? (tci < 4 ? 1 : 2) : 0);
            int rj = (bot ? (trj < 4 ? 1 : 2) : 0) * 3 + (rgt ? (tcj < 4 ? 1 : 2) : 0);
            if (ri != rj) v -= 100.0f;
        }
        g_bias[idx] = __float2half(v);
    }
}

// ---------------- attention kernel (4 heads per 256-thread block) ----------------
#define XROW    68                 // 64 rows x 68 words (128 fp16 cols + pad)
#define OFF_X   0                  // 4352 words
#define OFF_KV  4352               // 4 heads x 2560 words (K 64x20, V 64x20)
#define OFF_PIX 14592              // 64 ints
#define OFF_QB  14656              // 96 floats
#define OFF_W   14752              // 96 rows x 20 words
#define AT_SMEM_WORDS 16672
#define AT_SMEM_BYTES (AT_SMEM_WORDS * 4)

__global__ void __launch_bounds__(256, 2)
swin_attn_kernel(const float* __restrict__ x,
                 const float* __restrict__ qkv_b)
{
    extern __shared__ uint32_t smw[];
    const int tid  = threadIdx.x;
    const int warp = tid >> 5;
    const int lane = tid & 31;
    const int bi   = blockIdx.x;
    const int b    = bi >> 7;
    const int rem  = bi & 127;
    const int w    = rem >> 1;
    const int half = rem & 1;
    const int wr   = w >> 3, wc = w & 7;
    const int cls  = (wr == 7 ? 1 : 0) | (wc == 7 ? 2 : 0);

    const float* xb = x + (size_t)b * HWPIX * EDIM;
    __half*      ob = g_mid + (size_t)b * HWPIX * EDIM;

    float* qb   = (float*)(smw + OFF_QB);
    int*   pixs = (int*)(smw + OFF_PIX);
    const uint32_t sb = (uint32_t)__cvta_generic_to_shared(smw);

    // ---- stage qkv weights into smem via cp.async ----
    for (int i = tid; i < 384; i += 256) {
        int row = i >> 2, c = i & 3;
        cpasync16(sb + ((OFF_W + row * 20 + (c << 2)) << 2),
                  (const char*)g_qkvwT + row * 64 + c * 16);
    }
    asm volatile("cp.async.commit_group;\n" ::: "memory");

    // ---- init: qkv bias, pix LUT, X pad rows ----
    if (tid < 96) qb[tid] = qkv_b[tid];
    if (tid < 64) {
        int p = 0;
        if (tid < WD) {
            int tr = tid / 7, tc = tid - tr * 7;
            int sh = wr * 7 + tr + 3; if (sh >= 56) sh -= 56;
            int sw = wc * 7 + tc + 3; if (sw >= 56) sw -= 56;
            p = sh * 56 + sw;
        }
        pixs[tid] = p;
    }
    for (int i = tid; i < 15 * XROW; i += 256)
        smw[OFF_X + 49 * XROW + i] = 0u;        // zero X pad rows 49..63

    // ---- X load: 49 rows x 128 floats (this block's half) -> fp16 smem ----
    for (int i = tid; i < 1568; i += 256) {
        int t  = i >> 5;
        int c4 = (i & 31) << 2;
        int tr = t / 7, tc = t - tr * 7;
        int sh = wr * 7 + tr + 3; if (sh >= 56) sh -= 56;
        int sw = wc * 7 + tc + 3; if (sw >= 56) sw -= 56;
        float4 v = *(const float4*)&xb[(sh * 56 + sw) * EDIM + (half << 7) + c4];
        smw[OFF_X + t * XROW + (c4 >> 1)]     = packh2(v.x, v.y);
        smw[OFF_X + t * XROW + (c4 >> 1) + 1] = packh2(v.z, v.w);
    }
    asm volatile("cp.async.wait_group 0;\n" ::: "memory");
    __syncthreads();

    // ---- per-warp role: 4 head-pairs of 2 warps ----
    const int hl = warp >> 1;            // local head 0..3
    const int h  = (half << 2) + hl;     // global head 0..7
    const int wm = warp & 1;
    const int tb = wm << 5;
    const int r  = lane >> 2;
    const int cc = lane & 3;

    const uint32_t sbK = sb + ((OFF_KV + hl * 2560) << 2);
    const uint32_t sbV = sbK + (1280 << 2);
    const uint32_t sbW = sb + (OFF_W << 2);
    uint32_t* Ksm = smw + OFF_KV + hl * 2560;
    uint32_t* Vsm = Ksm + 1280;

    // ---- X A-frags (local head columns hl*32 -> word offset hl*16) ----
    uint32_t xa[2][2][4];
    #pragma unroll
    for (int mt = 0; mt < 2; mt++)
        #pragma unroll
        for (int kt = 0; kt < 2; kt++) {
            uint32_t addr = sb +
                (((tb + (mt << 4) + (lane & 15)) * XROW +
                  (hl << 4) + (kt << 3) + ((lane >> 4) << 2)) << 2);
            ldsm4(xa[mt][kt][0], xa[mt][kt][1], xa[mt][kt][2], xa[mt][kt][3], addr);
        }

    // ---- QKV via smem weights ----
    uint32_t qf[2][2][4];
    #pragma unroll
    for (int sec = 0; sec < 3; sec++) {
        uint32_t bf[2][2][4];
        #pragma unroll
        for (int g = 0; g < 2; g++)
            #pragma unroll
            for (int kt = 0; kt < 2; kt++) {
                uint32_t addr = sbW +
                    (((sec * 32 + (g << 4) + (lane & 15)) * 20 +
                      (kt << 3) + ((lane >> 4) << 2)) << 2);
                ldsm4(bf[g][kt][0], bf[g][kt][1], bf[g][kt][2], bf[g][kt][3], addr);
            }
        #pragma unroll
        for (int mt = 0; mt < 2; mt++) {
            int tok0 = tb + (mt << 4) + r;
            #pragma unroll
            for (int nt = 0; nt < 4; nt++) {
                int n0 = nt << 3;
                float b0 = qb[sec * 32 + n0 + (cc << 1)];
                float b1 = qb[sec * 32 + n0 + (cc << 1) + 1];
                float c[4] = {b0, b1, b0, b1};
                int g = nt >> 1, hi = nt & 1;
                #pragma unroll
                for (int kt = 0; kt < 2; kt++) {
                    uint32_t bb[2];
                    bb[0] = hi ? bf[g][kt][1] : bf[g][kt][0];
                    bb[1] = hi ? bf[g][kt][3] : bf[g][kt][2];
                    mma_f16(c, xa[mt][kt], bb);
                }
                if (sec == 0) {
                    int kt2 = nt >> 1;
                    if ((nt & 1) == 0) {
                        qf[mt][kt2][0] = packh2(c[0] * SCALE, c[1] * SCALE);
                        qf[mt][kt2][1] = packh2(c[2] * SCALE, c[3] * SCALE);
                    } else {
                        qf[mt][kt2][2] = packh2(c[0] * SCALE, c[1] * SCALE);
                        qf[mt][kt2][3] = packh2(c[2] * SCALE, c[3] * SCALE);
                    }
                } else if (sec == 1) {
                    Ksm[tok0 * 20 + (nt << 2) + cc]       = packh2(c[0], c[1]);
                    Ksm[(tok0 + 8) * 20 + (nt << 2) + cc] = packh2(c[2], c[3]);
                } else {
                    Vsm[tok0 * 20 + (nt << 2) + cc]       = packh2(c[0], c[1]);
                    Vsm[(tok0 + 8) * 20 + (nt << 2) + cc] = packh2(c[2], c[3]);
                }
            }
        }
    }

    asm volatile("bar.sync %0, 64;" :: "r"(hl + 8) : "memory");

    const __half2* tb2 = (const __half2*)g_bias;

    #pragma unroll
    for (int mt = 0; mt < 2; mt++) {
        int q0 = tb + (mt << 4) + r;
        int base0 = ((((cls << 3) + h) << 6) + q0) << 5;
        int base1 = base0 + (8 << 5);
        __half2 bias_lo[8], bias_hi[8];
        #pragma unroll
        for (int nt = 0; nt < 8; nt++) {
            bias_lo[nt] = tb2[base0 + (nt << 2) + cc];
            bias_hi[nt] = tb2[base1 + (nt << 2) + cc];
        }

        float sacc[8][4];
        #pragma unroll
        for (int nt = 0; nt < 8; nt++)
            #pragma unroll
            for (int i = 0; i < 4; i++) sacc[nt][i] = 0.f;

        #pragma unroll
        for (int g = 0; g < 4; g++)
            #pragma unroll
            for (int kt = 0; kt < 2; kt++) {
                uint32_t r0, r1, r2, r3;
                uint32_t addr = sbK +
                    ((((g << 4) + (lane & 15)) * 20 + (kt << 3) + ((lane >> 4) << 2)) << 2);
                ldsm4(r0, r1, r2, r3, addr);
                uint32_t blo[2] = {r0, r2};
                uint32_t bhi[2] = {r1, r3};
                mma_f16(sacc[(g << 1)],     qf[mt][kt], blo);
                mma_f16(sacc[(g << 1) + 1], qf[mt][kt], bhi);
            }

        #pragma unroll
        for (int nt = 0; nt < 8; nt++) {
            float2 b0 = __half22float2(bias_lo[nt]);
            float2 b1 = __half22float2(bias_hi[nt]);
            sacc[nt][0] += b0.x; sacc[nt][1] += b0.y;
            sacc[nt][2] += b1.x; sacc[nt][3] += b1.y;
        }
        float m0 = -1e30f, m1 = -1e30f;
        #pragma unroll
        for (int nt = 0; nt < 8; nt++) {
            m0 = fmaxf(m0, fmaxf(sacc[nt][0], sacc[nt][1]));
            m1 = fmaxf(m1, fmaxf(sacc[nt][2], sacc[nt][3]));
        }
        m0 = fmaxf(m0, __shfl_xor_sync(0xffffffffu, m0, 1));
        m0 = fmaxf(m0, __shfl_xor_sync(0xffffffffu, m0, 2));
        m1 = fmaxf(m1, __shfl_xor_sync(0xffffffffu, m1, 1));
        m1 = fmaxf(m1, __shfl_xor_sync(0xffffffffu, m1, 2));
        float s0 = 0.f, s1 = 0.f;
        #pragma unroll
        for (int nt = 0; nt < 8; nt++) {
            sacc[nt][0] = __expf(sacc[nt][0] - m0); s0 += sacc[nt][0];
            sacc[nt][1] = __expf(sacc[nt][1] - m0); s0 += sacc[nt][1];
            sacc[nt][2] = __expf(sacc[nt][2] - m1); s1 += sacc[nt][2];
            sacc[nt][3] = __expf(sacc[nt][3] - m1); s1 += sacc[nt][3];
        }
        s0 += __shfl_xor_sync(0xffffffffu, s0, 1);
        s0 += __shfl_xor_sync(0xffffffffu, s0, 2);
        s1 += __shfl_xor_sync(0xffffffffu, s1, 1);
        s1 += __shfl_xor_sync(0xffffffffu, s1, 2);
        float inv0 = __frcp_rn(s0), inv1 = __frcp_rn(s1);

        uint32_t pf[4][4];
        #pragma unroll
        for (int nt = 0; nt < 8; nt++) {
            int kt2 = nt >> 1;
            uint32_t plo = packh2(sacc[nt][0] * inv0, sacc[nt][1] * inv0);
            uint32_t phi = packh2(sacc[nt][2] * inv1, sacc[nt][3] * inv1);
            if ((nt & 1) == 0) { pf[kt2][0] = plo; pf[kt2][1] = phi; }
            else               { pf[kt2][2] = plo; pf[kt2][3] = phi; }
        }

        float oacc[4][4];
        #pragma unroll
        for (int nt = 0; nt < 4; nt++)
            #pragma unroll
            for (int i = 0; i < 4; i++) oacc[nt][i] = 0.f;

        #pragma unroll
        for (int kt2 = 0; kt2 < 4; kt2++)
            #pragma unroll
            for (int vh2 = 0; vh2 < 2; vh2++) {
                uint32_t r0, r1, r2, r3;
                uint32_t addr = sbV +
                    ((((kt2 << 4) + (lane & 15)) * 20 + (vh2 << 3) + ((lane >> 4) << 2)) << 2);
                ldsm4t(r0, r1, r2, r3, addr);
                uint32_t blo[2] = {r0, r1};
                uint32_t bhi[2] = {r2, r3};
                mma_f16(oacc[(vh2 << 1)],     pf[kt2], blo);
                mma_f16(oacc[(vh2 << 1) + 1], pf[kt2], bhi);
            }

        #pragma unroll
        for (int ntv = 0; ntv < 4; ntv++) {
            int col = (h << 5) + (ntv << 3) + (cc << 1);
            if (q0 < WD)
                *(uint32_t*)&ob[pixs[q0] * EDIM + col] = packh2(oacc[ntv][0], oacc[ntv][1]);
            if (q0 + 8 < WD)
                *(uint32_t*)&ob[pixs[q0 + 8] * EDIM + col] = packh2(oacc[ntv][2], oacc[ntv][3]);
        }
    }
}

// ---------------------------------------------------------------------------
// Projection (R8): out[M,N] = g_mid(fp16)[M,256] @ g_wpT^T + proj_b
// ---------------------------------------------------------------------------
#define PJ_BOFF 0
#define PJ_AOFF 8448
#define PJ_SMEM_WORDS (8448 + 2 * 4608)
#define PJ_SMEM_BYTES (PJ_SMEM_WORDS * 4)

__global__ void __launch_bounds__(256)
swin_proj_kernel(const float* __restrict__ pb,
                 float* __restrict__ out)
{
    extern __shared__ uint32_t pjw[];
    const int tid  = threadIdx.x;
    const int lane = tid & 31;
    const int warp = tid >> 5;
    const int mW = (warp >> 1) << 5;
    const int nW = (warp & 1) << 5;
    const int rowBase = blockIdx.y << 7;
    const int nBase   = blockIdx.x << 6;
    const __half* A16 = g_mid;
    const __half* B16 = g_wpT;
    const uint32_t sbase = (uint32_t)__cvta_generic_to_shared(pjw);

    float acc[2][4][4];
    #pragma unroll
    for (int mt = 0; mt < 2; mt++)
        #pragma unroll
        for (int nt = 0; nt < 4; nt++)
            #pragma unroll
            for (int i = 0; i < 4; i++)
                acc[mt][nt][i] = 0.f;

    #pragma unroll
    for (int l = 0; l < 8; l++) {
        int idx = tid + (l << 8);
        int row = idx >> 5, c16 = idx & 31;
        cpasync16(sbase + ((PJ_BOFF + row * 132 + (c16 << 2)) << 2),
                  &B16[(size_t)(nBase + row) * 256 + (c16 << 3)]);
    }
    #pragma unroll
    for (int l = 0; l < 4; l++) {
        int idx = tid + (l << 8);
        int row = idx >> 3, c16 = idx & 7;
        cpasync16(sbase + ((PJ_AOFF + row * 36 + (c16 << 2)) << 2),
                  &A16[(size_t)(rowBase + row) * 256 + (c16 << 3)]);
    }
    asm volatile("cp.async.commit_group;\n" ::: "memory");
    #pragma unroll
    for (int l = 0; l < 4; l++) {
        int idx = tid + (l << 8);
        int row = idx >> 3, c16 = idx & 7;
        cpasync16(sbase + ((PJ_AOFF + 4608 + row * 36 + (c16 << 2)) << 2),
                  &A16[(size_t)(rowBase + row) * 256 + 64 + (c16 << 3)]);
    }
    asm volatile("cp.async.commit_group;\n" ::: "memory");

    const int r  = lane >> 2;
    const int cc = lane & 3;

    for (int kc = 0; kc < 4; kc++) {
        int buf = kc & 1;
        if (kc < 3) asm volatile("cp.async.wait_group 1;\n" ::: "memory");
        else        asm volatile("cp.async.wait_group 0;\n" ::: "memory");
        __syncthreads();

        const uint32_t* As = pjw + PJ_AOFF + buf * 4608;
        const uint32_t* Bs = pjw + PJ_BOFF;
        #pragma unroll
        for (int kt = 0; kt < 4; kt++) {
            int bko = (kc << 5) + (kt << 3);
            uint32_t a[2][4], bb[4][2];
            #pragma unroll
            for (int mt2 = 0; mt2 < 2; mt2++) {
                int rb = mW + (mt2 << 4) + r;
                const uint32_t* ap = As + rb * 36 + (kt << 3) + cc;
                a[mt2][0] = ap[0];
                a[mt2][1] = ap[288];
                a[mt2][2] = ap[4];
                a[mt2][3] = ap[292];
            }
            #pragma unroll
            for (int nt = 0; nt < 4; nt++) {
                int n = nW + (nt << 3) + r;
                const uint32_t* bp = Bs + n * 132 + bko + cc;
                bb[nt][0] = bp[0];
                bb[nt][1] = bp[4];
            }
            #pragma unroll
            for (int mt2 = 0; mt2 < 2; mt2++)
                #pragma unroll
                for (int nt = 0; nt < 4; nt++)
                    mma_f16(acc[mt2][nt], a[mt2], bb[nt]);
        }
        __syncthreads();

        if (kc < 2) {
            int k0 = (kc + 2) << 6;
            #pragma unroll
            for (int l = 0; l < 4; l++) {
                int idx = tid + (l << 8);
                int row = idx >> 3, c16 = idx & 7;
                cpasync16(sbase + ((PJ_AOFF + buf * 4608 + row * 36 + (c16 << 2)) << 2),
                          &A16[(size_t)(rowBase + row) * 256 + k0 + (c16 << 3)]);
            }
            asm volatile("cp.async.commit_group;\n" ::: "memory");
        }
    }

    #pragma unroll
    for (int mt2 = 0; mt2 < 2; mt2++) {
        int row = rowBase + mW + (mt2 << 4) + (lane >> 2);
        #pragma unroll
        for (int nt = 0; nt < 4; nt++) {
            int col = nBase + nW + (nt << 3) + ((lane & 3) << 1);
            float b0 = pb[col], b1 = pb[col + 1];
            float2 v0 = make_float2(acc[mt2][nt][0] + b0, acc[mt2][nt][1] + b1);
            float2 v1 = make_float2(acc[mt2][nt][2] + b0, acc[mt2][nt][3] + b1);
            *(float2*)&out[(size_t)row * 256 + col]       = v0;
            *(float2*)&out[(size_t)(row + 8) * 256 + col] = v1;
        }
    }
}

extern "C" void kernel_launch(void* const* d_in, const int* in_sizes, int n_in,
                              void* d_out, int out_size)
{
    (void)in_sizes; (void)n_in; (void)out_size;
    const float* x      = (const float*)d_in[0];
    const float* qkv_w  = (const float*)d_in[1];
    const float* qkv_b  = (const float*)d_in[2];
    const float* proj_w = (const float*)d_in[3];
    const float* proj_b = (const float*)d_in[4];
    const float* rpb    = (const float*)d_in[5];
    float* out = (float*)d_out;

    cudaFuncSetAttribute(swin_attn_kernel,
                         cudaFuncAttributeMaxDynamicSharedMemorySize, AT_SMEM_BYTES);
    cudaFuncSetAttribute(swin_proj_kernel,
                         cudaFuncAttributeMaxDynamicSharedMemorySize, PJ_SMEM_BYTES);

    swin_prep_kernel<<<512, 256>>>(qkv_w, proj_w, rpb);
    swin_attn_kernel<<<BATCH * 128, 256, AT_SMEM_BYTES>>>(x, qkv_b);
    swin_proj_kernel<<<dim3(4, 784), 256, PJ_SMEM_BYTES>>>(proj_b, out);
}

// round 11
// speedup vs baseline: 6.0957x; 1.1531x over previous
#include <cuda_runtime.h>
#include <cuda_fp16.h>
#include <cstdint>

// ---------------------------------------------------------------------------
// SWMSA: B=32, H=W=56, E=256, NH=8, HD=32, WS=7, WD=49, NW=64, SS=3
// R11 = R10 with attention at 3 blocks/SM (__launch_bounds__(256,3)) and
//      bias loaded inline in softmax (frees 16 regs to fit the 84-reg cap).
// ---------------------------------------------------------------------------

#define BATCH 32
#define HWPIX 3136
#define EDIM  256
#define WD    49
#define SCALE 0.17677669529663687f   // 1/sqrt(32)

__device__ __align__(16) __half g_mid[(size_t)BATCH * HWPIX * EDIM];
__device__ __align__(16) __half g_wpT[65536];    // proj_w^T fp16 [n][k]
__device__ __align__(16) __half g_qkvwT[3072];   // qkv_w^T fp16 [n][k]
__device__ __align__(16) __half g_bias[4 * 8 * 64 * 64];

__device__ __forceinline__ void mma_f16(float* c, const uint32_t* a, const uint32_t* b) {
    asm volatile(
        "mma.sync.aligned.m16n8k16.row.col.f32.f16.f16.f32 "
        "{%0,%1,%2,%3}, {%4,%5,%6,%7}, {%8,%9}, {%0,%1,%2,%3};\n"
        : "+f"(c[0]), "+f"(c[1]), "+f"(c[2]), "+f"(c[3])
        : "r"(a[0]), "r"(a[1]), "r"(a[2]), "r"(a[3]), "r"(b[0]), "r"(b[1]));
}
__device__ __forceinline__ uint32_t h2u(__half2 h) { return *(uint32_t*)&h; }
__device__ __forceinline__ uint32_t packh2(float x, float y) {
    return h2u(__floats2half2_rn(x, y));
}
__device__ __forceinline__ void ldsm4(uint32_t& r0, uint32_t& r1, uint32_t& r2,
                                      uint32_t& r3, uint32_t addr) {
    asm volatile("ldmatrix.sync.aligned.m8n8.x4.shared.b16 {%0,%1,%2,%3}, [%4];"
                 : "=r"(r0), "=r"(r1), "=r"(r2), "=r"(r3) : "r"(addr));
}
__device__ __forceinline__ void ldsm4t(uint32_t& r0, uint32_t& r1, uint32_t& r2,
                                       uint32_t& r3, uint32_t addr) {
    asm volatile("ldmatrix.sync.aligned.m8n8.x4.trans.shared.b16 {%0,%1,%2,%3}, [%4];"
                 : "=r"(r0), "=r"(r1), "=r"(r2), "=r"(r3) : "r"(addr));
}
__device__ __forceinline__ void cpasync16(uint32_t s, const void* g) {
    asm volatile("cp.async.cg.shared.global [%0], [%1], 16;\n"
                 :: "r"(s), "l"(g) : "memory");
}

// ---------------- prep kernel ----------------
__global__ void __launch_bounds__(256)
swin_prep_kernel(const float* __restrict__ qkv_w,
                 const float* __restrict__ proj_w,
                 const float* __restrict__ rpb_table)
{
    int idx = blockIdx.x * 256 + threadIdx.x;   // grid 512 -> 131072
    if (idx < 3072) {
        int n = idx >> 5, k = idx & 31;
        g_qkvwT[idx] = __float2half(qkv_w[k * 96 + n]);
    }
    if (idx < 65536) {
        int n = idx >> 8, k = idx & 255;
        g_wpT[idx] = __float2half(proj_w[k * 256 + n]);
    }
    {
        int cls = idx >> 15, h = (idx >> 12) & 7, i = (idx >> 6) & 63, j = idx & 63;
        float v = -30000.0f;
        if (i < WD && j < WD) {
            int tri = i / 7, tci = i - tri * 7;
            int trj = j / 7, tcj = j - trj * 7;
            int li = tri * 13 + tci, lj = trj * 13 + tcj;
            v = rpb_table[(li - lj + 84) * 8 + h];
            int bot = cls & 1, rgt = (cls >> 1) & 1;
            int ri = (bot ? (tri < 4 ? 1 : 2) : 0) * 3 + (rgt ? (tci < 4 ? 1 : 2) : 0);
            int rj = (bot ? (trj < 4 ? 1 : 2) : 0) * 3 + (rgt ? (tcj < 4 ? 1 : 2) : 0);
            if (ri != rj) v -= 100.0f;
        }
        g_bias[idx] = __float2half(v);
    }
}

// ---------------- attention kernel (4 heads per 256-thread block) ----------------
#define XROW    68
#define OFF_X   0
#define OFF_KV  4352
#define OFF_PIX 14592
#define OFF_QB  14656
#define OFF_W   14752
#define AT_SMEM_WORDS 16672
#define AT_SMEM_BYTES (AT_SMEM_WORDS * 4)

__global__ void __launch_bounds__(256, 3)
swin_attn_kernel(const float* __restrict__ x,
                 const float* __restrict__ qkv_b)
{
    extern __shared__ uint32_t smw[];
    const int tid  = threadIdx.x;
    const int warp = tid >> 5;
    const int lane = tid & 31;
    const int bi   = blockIdx.x;
    const int b    = bi >> 7;
    const int rem  = bi & 127;
    const int w    = rem >> 1;
    const int half = rem & 1;
    const int wr   = w >> 3, wc = w & 7;
    const int cls  = (wr == 7 ? 1 : 0) | (wc == 7 ? 2 : 0);

    const float* xb = x + (size_t)b * HWPIX * EDIM;
    __half*      ob = g_mid + (size_t)b * HWPIX * EDIM;

    float* qb   = (float*)(smw + OFF_QB);
    int*   pixs = (int*)(smw + OFF_PIX);
    const uint32_t sb = (uint32_t)__cvta_generic_to_shared(smw);

    // ---- stage qkv weights into smem via cp.async ----
    for (int i = tid; i < 384; i += 256) {
        int row = i >> 2, c = i & 3;
        cpasync16(sb + ((OFF_W + row * 20 + (c << 2)) << 2),
                  (const char*)g_qkvwT + row * 64 + c * 16);
    }
    asm volatile("cp.async.commit_group;\n" ::: "memory");

    // ---- init ----
    if (tid < 96) qb[tid] = qkv_b[tid];
    if (tid < 64) {
        int p = 0;
        if (tid < WD) {
            int tr = tid / 7, tc = tid - tr * 7;
            int sh = wr * 7 + tr + 3; if (sh >= 56) sh -= 56;
            int sw = wc * 7 + tc + 3; if (sw >= 56) sw -= 56;
            p = sh * 56 + sw;
        }
        pixs[tid] = p;
    }
    for (int i = tid; i < 15 * XROW; i += 256)
        smw[OFF_X + 49 * XROW + i] = 0u;

    // ---- X load: 49 rows x 128 floats (this block's half) ----
    for (int i = tid; i < 1568; i += 256) {
        int t  = i >> 5;
        int c4 = (i & 31) << 2;
        int tr = t / 7, tc = t - tr * 7;
        int sh = wr * 7 + tr + 3; if (sh >= 56) sh -= 56;
        int sw = wc * 7 + tc + 3; if (sw >= 56) sw -= 56;
        float4 v = *(const float4*)&xb[(sh * 56 + sw) * EDIM + (half << 7) + c4];
        smw[OFF_X + t * XROW + (c4 >> 1)]     = packh2(v.x, v.y);
        smw[OFF_X + t * XROW + (c4 >> 1) + 1] = packh2(v.z, v.w);
    }
    asm volatile("cp.async.wait_group 0;\n" ::: "memory");
    __syncthreads();

    // ---- per-warp role ----
    const int hl = warp >> 1;
    const int h  = (half << 2) + hl;
    const int wm = warp & 1;
    const int tb = wm << 5;
    const int r  = lane >> 2;
    const int cc = lane & 3;

    const uint32_t sbK = sb + ((OFF_KV + hl * 2560) << 2);
    const uint32_t sbV = sbK + (1280 << 2);
    const uint32_t sbW = sb + (OFF_W << 2);
    uint32_t* Ksm = smw + OFF_KV + hl * 2560;
    uint32_t* Vsm = Ksm + 1280;

    // ---- X A-frags ----
    uint32_t xa[2][2][4];
    #pragma unroll
    for (int mt = 0; mt < 2; mt++)
        #pragma unroll
        for (int kt = 0; kt < 2; kt++) {
            uint32_t addr = sb +
                (((tb + (mt << 4) + (lane & 15)) * XROW +
                  (hl << 4) + (kt << 3) + ((lane >> 4) << 2)) << 2);
            ldsm4(xa[mt][kt][0], xa[mt][kt][1], xa[mt][kt][2], xa[mt][kt][3], addr);
        }

    // ---- QKV via smem weights ----
    uint32_t qf[2][2][4];
    #pragma unroll
    for (int sec = 0; sec < 3; sec++) {
        uint32_t bf[2][2][4];
        #pragma unroll
        for (int g = 0; g < 2; g++)
            #pragma unroll
            for (int kt = 0; kt < 2; kt++) {
                uint32_t addr = sbW +
                    (((sec * 32 + (g << 4) + (lane & 15)) * 20 +
                      (kt << 3) + ((lane >> 4) << 2)) << 2);
                ldsm4(bf[g][kt][0], bf[g][kt][1], bf[g][kt][2], bf[g][kt][3], addr);
            }
        #pragma unroll
        for (int mt = 0; mt < 2; mt++) {
            int tok0 = tb + (mt << 4) + r;
            #pragma unroll
            for (int nt = 0; nt < 4; nt++) {
                int n0 = nt << 3;
                float b0 = qb[sec * 32 + n0 + (cc << 1)];
                float b1 = qb[sec * 32 + n0 + (cc << 1) + 1];
                float c[4] = {b0, b1, b0, b1};
                int g = nt >> 1, hi = nt & 1;
                #pragma unroll
                for (int kt = 0; kt < 2; kt++) {
                    uint32_t bb[2];
                    bb[0] = hi ? bf[g][kt][1] : bf[g][kt][0];
                    bb[1] = hi ? bf[g][kt][3] : bf[g][kt][2];
                    mma_f16(c, xa[mt][kt], bb);
                }
                if (sec == 0) {
                    int kt2 = nt >> 1;
                    if ((nt & 1) == 0) {
                        qf[mt][kt2][0] = packh2(c[0] * SCALE, c[1] * SCALE);
                        qf[mt][kt2][1] = packh2(c[2] * SCALE, c[3] * SCALE);
                    } else {
                        qf[mt][kt2][2] = packh2(c[0] * SCALE, c[1] * SCALE);
                        qf[mt][kt2][3] = packh2(c[2] * SCALE, c[3] * SCALE);
                    }
                } else if (sec == 1) {
                    Ksm[tok0 * 20 + (nt << 2) + cc]       = packh2(c[0], c[1]);
                    Ksm[(tok0 + 8) * 20 + (nt << 2) + cc] = packh2(c[2], c[3]);
                } else {
                    Vsm[tok0 * 20 + (nt << 2) + cc]       = packh2(c[0], c[1]);
                    Vsm[(tok0 + 8) * 20 + (nt << 2) + cc] = packh2(c[2], c[3]);
                }
            }
        }
    }

    asm volatile("bar.sync %0, 64;" :: "r"(hl + 8) : "memory");

    const __half2* tb2 = (const __half2*)g_bias;

    #pragma unroll
    for (int mt = 0; mt < 2; mt++) {
        int q0 = tb + (mt << 4) + r;
        int base0 = ((((cls << 3) + h) << 6) + q0) << 5;
        int base1 = base0 + (8 << 5);

        // ---- S = Q K^T ----
        float sacc[8][4];
        #pragma unroll
        for (int nt = 0; nt < 8; nt++)
            #pragma unroll
            for (int i = 0; i < 4; i++) sacc[nt][i] = 0.f;

        #pragma unroll
        for (int g = 0; g < 4; g++)
            #pragma unroll
            for (int kt = 0; kt < 2; kt++) {
                uint32_t r0, r1, r2, r3;
                uint32_t addr = sbK +
                    ((((g << 4) + (lane & 15)) * 20 + (kt << 3) + ((lane >> 4) << 2)) << 2);
                ldsm4(r0, r1, r2, r3, addr);
                uint32_t blo[2] = {r0, r2};
                uint32_t bhi[2] = {r1, r3};
                mma_f16(sacc[(g << 1)],     qf[mt][kt], blo);
                mma_f16(sacc[(g << 1) + 1], qf[mt][kt], bhi);
            }

        // ---- softmax (bias loaded inline; L1-resident table) ----
        #pragma unroll
        for (int nt = 0; nt < 8; nt++) {
            float2 b0 = __half22float2(tb2[base0 + (nt << 2) + cc]);
            float2 b1 = __half22float2(tb2[base1 + (nt << 2) + cc]);
            sacc[nt][0] += b0.x; sacc[nt][1] += b0.y;
            sacc[nt][2] += b1.x; sacc[nt][3] += b1.y;
        }
        float m0 = -1e30f, m1 = -1e30f;
        #pragma unroll
        for (int nt = 0; nt < 8; nt++) {
            m0 = fmaxf(m0, fmaxf(sacc[nt][0], sacc[nt][1]));
            m1 = fmaxf(m1, fmaxf(sacc[nt][2], sacc[nt][3]));
        }
        m0 = fmaxf(m0, __shfl_xor_sync(0xffffffffu, m0, 1));
        m0 = fmaxf(m0, __shfl_xor_sync(0xffffffffu, m0, 2));
        m1 = fmaxf(m1, __shfl_xor_sync(0xffffffffu, m1, 1));
        m1 = fmaxf(m1, __shfl_xor_sync(0xffffffffu, m1, 2));
        float s0 = 0.f, s1 = 0.f;
        #pragma unroll
        for (int nt = 0; nt < 8; nt++) {
            sacc[nt][0] = __expf(sacc[nt][0] - m0); s0 += sacc[nt][0];
            sacc[nt][1] = __expf(sacc[nt][1] - m0); s0 += sacc[nt][1];
            sacc[nt][2] = __expf(sacc[nt][2] - m1); s1 += sacc[nt][2];
            sacc[nt][3] = __expf(sacc[nt][3] - m1); s1 += sacc[nt][3];
        }
        s0 += __shfl_xor_sync(0xffffffffu, s0, 1);
        s0 += __shfl_xor_sync(0xffffffffu, s0, 2);
        s1 += __shfl_xor_sync(0xffffffffu, s1, 1);
        s1 += __shfl_xor_sync(0xffffffffu, s1, 2);
        float inv0 = __frcp_rn(s0), inv1 = __frcp_rn(s1);

        uint32_t pf[4][4];
        #pragma unroll
        for (int nt = 0; nt < 8; nt++) {
            int kt2 = nt >> 1;
            uint32_t plo = packh2(sacc[nt][0] * inv0, sacc[nt][1] * inv0);
            uint32_t phi = packh2(sacc[nt][2] * inv1, sacc[nt][3] * inv1);
            if ((nt & 1) == 0) { pf[kt2][0] = plo; pf[kt2][1] = phi; }
            else               { pf[kt2][2] = plo; pf[kt2][3] = phi; }
        }

        // ---- O = P V ----
        float oacc[4][4];
        #pragma unroll
        for (int nt = 0; nt < 4; nt++)
            #pragma unroll
            for (int i = 0; i < 4; i++) oacc[nt][i] = 0.f;

        #pragma unroll
        for (int kt2 = 0; kt2 < 4; kt2++)
            #pragma unroll
            for (int vh2 = 0; vh2 < 2; vh2++) {
                uint32_t r0, r1, r2, r3;
                uint32_t addr = sbV +
                    ((((kt2 << 4) + (lane & 15)) * 20 + (vh2 << 3) + ((lane >> 4) << 2)) << 2);
                ldsm4t(r0, r1, r2, r3, addr);
                uint32_t blo[2] = {r0, r1};
                uint32_t bhi[2] = {r2, r3};
                mma_f16(oacc[(vh2 << 1)],     pf[kt2], blo);
                mma_f16(oacc[(vh2 << 1) + 1], pf[kt2], bhi);
            }

        // ---- store shift-reversed ----
        #pragma unroll
        for (int ntv = 0; ntv < 4; ntv++) {
            int col = (h << 5) + (ntv << 3) + (cc << 1);
            if (q0 < WD)
                *(uint32_t*)&ob[pixs[q0] * EDIM + col] = packh2(oacc[ntv][0], oacc[ntv][1]);
            if (q0 + 8 < WD)
                *(uint32_t*)&ob[pixs[q0 + 8] * EDIM + col] = packh2(oacc[ntv][2], oacc[ntv][3]);
        }
    }
}

// ---------------------------------------------------------------------------
// Projection (R8): out[M,N] = g_mid(fp16)[M,256] @ g_wpT^T + proj_b
// ---------------------------------------------------------------------------
#define PJ_BOFF 0
#define PJ_AOFF 8448
#define PJ_SMEM_WORDS (8448 + 2 * 4608)
#define PJ_SMEM_BYTES (PJ_SMEM_WORDS * 4)

__global__ void __launch_bounds__(256)
swin_proj_kernel(const float* __restrict__ pb,
                 float* __restrict__ out)
{
    extern __shared__ uint32_t pjw[];
    const int tid  = threadIdx.x;
    const int lane = tid & 31;
    const int warp = tid >> 5;
    const int mW = (warp >> 1) << 5;
    const int nW = (warp & 1) << 5;
    const int rowBase = blockIdx.y << 7;
    const int nBase   = blockIdx.x << 6;
    const __half* A16 = g_mid;
    const __half* B16 = g_wpT;
    const uint32_t sbase = (uint32_t)__cvta_generic_to_shared(pjw);

    float acc[2][4][4];
    #pragma unroll
    for (int mt = 0; mt < 2; mt++)
        #pragma unroll
        for (int nt = 0; nt < 4; nt++)
            #pragma unroll
            for (int i = 0; i < 4; i++)
                acc[mt][nt][i] = 0.f;

    #pragma unroll
    for (int l = 0; l < 8; l++) {
        int idx = tid + (l << 8);
        int row = idx >> 5, c16 = idx & 31;
        cpasync16(sbase + ((PJ_BOFF + row * 132 + (c16 << 2)) << 2),
                  &B16[(size_t)(nBase + row) * 256 + (c16 << 3)]);
    }
    #pragma unroll
    for (int l = 0; l < 4; l++) {
        int idx = tid + (l << 8);
        int row = idx >> 3, c16 = idx & 7;
        cpasync16(sbase + ((PJ_AOFF + row * 36 + (c16 << 2)) << 2),
                  &A16[(size_t)(rowBase + row) * 256 + (c16 << 3)]);
    }
    asm volatile("cp.async.commit_group;\n" ::: "memory");
    #pragma unroll
    for (int l = 0; l < 4; l++) {
        int idx = tid + (l << 8);
        int row = idx >> 3, c16 = idx & 7;
        cpasync16(sbase + ((PJ_AOFF + 4608 + row * 36 + (c16 << 2)) << 2),
                  &A16[(size_t)(rowBase + row) * 256 + 64 + (c16 << 3)]);
    }
    asm volatile("cp.async.commit_group;\n" ::: "memory");

    const int r  = lane >> 2;
    const int cc = lane & 3;

    for (int kc = 0; kc < 4; kc++) {
        int buf = kc & 1;
        if (kc < 3) asm volatile("cp.async.wait_group 1;\n" ::: "memory");
        else        asm volatile("cp.async.wait_group 0;\n" ::: "memory");
        __syncthreads();

        const uint32_t* As = pjw + PJ_AOFF + buf * 4608;
        const uint32_t* Bs = pjw + PJ_BOFF;
        #pragma unroll
        for (int kt = 0; kt < 4; kt++) {
            int bko = (kc << 5) + (kt << 3);
            uint32_t a[2][4], bb[4][2];
            #pragma unroll
            for (int mt2 = 0; mt2 < 2; mt2++) {
                int rb = mW + (mt2 << 4) + r;
                const uint32_t* ap = As + rb * 36 + (kt << 3) + cc;
                a[mt2][0] = ap[0];
                a[mt2][1] = ap[288];
                a[mt2][2] = ap[4];
                a[mt2][3] = ap[292];
            }
            #pragma unroll
            for (int nt = 0; nt < 4; nt++) {
                int n = nW + (nt << 3) + r;
                const uint32_t* bp = Bs + n * 132 + bko + cc;
                bb[nt][0] = bp[0];
                bb[nt][1] = bp[4];
            }
            #pragma unroll
            for (int mt2 = 0; mt2 < 2; mt2++)
                #pragma unroll
                for (int nt = 0; nt < 4; nt++)
                    mma_f16(acc[mt2][nt], a[mt2], bb[nt]);
        }
        __syncthreads();

        if (kc < 2) {
            int k0 = (kc + 2) << 6;
            #pragma unroll
            for (int l = 0; l < 4; l++) {
                int idx = tid + (l << 8);
                int row = idx >> 3, c16 = idx & 7;
                cpasync16(sbase + ((PJ_AOFF + buf * 4608 + row * 36 + (c16 << 2)) << 2),
                          &A16[(size_t)(rowBase + row) * 256 + k0 + (c16 << 3)]);
            }
            asm volatile("cp.async.commit_group;\n" ::: "memory");
        }
    }

    #pragma unroll
    for (int mt2 = 0; mt2 < 2; mt2++) {
        int row = rowBase + mW + (mt2 << 4) + (lane >> 2);
        #pragma unroll
        for (int nt = 0; nt < 4; nt++) {
            int col = nBase + nW + (nt << 3) + ((lane & 3) << 1);
            float b0 = pb[col], b1 = pb[col + 1];
            float2 v0 = make_float2(acc[mt2][nt][0] + b0, acc[mt2][nt][1] + b1);
            float2 v1 = make_float2(acc[mt2][nt][2] + b0, acc[mt2][nt][3] + b1);
            *(float2*)&out[(size_t)row * 256 + col]       = v0;
            *(float2*)&out[(size_t)(row + 8) * 256 + col] = v1;
        }
    }
}

extern "C" void kernel_launch(void* const* d_in, const int* in_sizes, int n_in,
                              void* d_out, int out_size)
{
    (void)in_sizes; (void)n_in; (void)out_size;
    const float* x      = (const float*)d_in[0];
    const float* qkv_w  = (const float*)d_in[1];
    const float* qkv_b  = (const float*)d_in[2];
    const float* proj_w = (const float*)d_in[3];
    const float* proj_b = (const float*)d_in[4];
    const float* rpb    = (const float*)d_in[5];
    float* out = (float*)d_out;

    cudaFuncSetAttribute(swin_attn_kernel,
                         cudaFuncAttributeMaxDynamicSharedMemorySize, AT_SMEM_BYTES);
    cudaFuncSetAttribute(swin_proj_kernel,
                         cudaFuncAttributeMaxDynamicSharedMemorySize, PJ_SMEM_BYTES);

    swin_prep_kernel<<<512, 256>>>(qkv_w, proj_w, rpb);
    swin_attn_kernel<<<BATCH * 128, 256, AT_SMEM_BYTES>>>(x, qkv_b);
    swin_proj_kernel<<<dim3(4, 784), 256, PJ_SMEM_BYTES>>>(proj_b, out);
}

// round 12
// speedup vs baseline: 6.1091x; 1.0022x over previous
#include <cuda_runtime.h>
#include <cuda_fp16.h>
#include <cstdint>

// ---------------------------------------------------------------------------
// SWMSA: B=32, H=W=56, E=256, NH=8, HD=32, WS=7, WD=49, NW=64, SS=3
// R12 = R11 attention (3 blocks/SM) + proj shrunk to 54.3KB smem
//       (K-chunks of 32, stride-20 A tiles) with __launch_bounds__(256,3).
// ---------------------------------------------------------------------------

#define BATCH 32
#define HWPIX 3136
#define EDIM  256
#define WD    49
#define SCALE 0.17677669529663687f   // 1/sqrt(32)

__device__ __align__(16) __half g_mid[(size_t)BATCH * HWPIX * EDIM];
__device__ __align__(16) __half g_wpT[65536];    // proj_w^T fp16 [n][k]
__device__ __align__(16) __half g_qkvwT[3072];   // qkv_w^T fp16 [n][k]
__device__ __align__(16) __half g_bias[4 * 8 * 64 * 64];

__device__ __forceinline__ void mma_f16(float* c, const uint32_t* a, const uint32_t* b) {
    asm volatile(
        "mma.sync.aligned.m16n8k16.row.col.f32.f16.f16.f32 "
        "{%0,%1,%2,%3}, {%4,%5,%6,%7}, {%8,%9}, {%0,%1,%2,%3};\n"
        : "+f"(c[0]), "+f"(c[1]), "+f"(c[2]), "+f"(c[3])
        : "r"(a[0]), "r"(a[1]), "r"(a[2]), "r"(a[3]), "r"(b[0]), "r"(b[1]));
}
__device__ __forceinline__ uint32_t h2u(__half2 h) { return *(uint32_t*)&h; }
__device__ __forceinline__ uint32_t packh2(float x, float y) {
    return h2u(__floats2half2_rn(x, y));
}
__device__ __forceinline__ void ldsm4(uint32_t& r0, uint32_t& r1, uint32_t& r2,
                                      uint32_t& r3, uint32_t addr) {
    asm volatile("ldmatrix.sync.aligned.m8n8.x4.shared.b16 {%0,%1,%2,%3}, [%4];"
                 : "=r"(r0), "=r"(r1), "=r"(r2), "=r"(r3) : "r"(addr));
}
__device__ __forceinline__ void ldsm4t(uint32_t& r0, uint32_t& r1, uint32_t& r2,
                                       uint32_t& r3, uint32_t addr) {
    asm volatile("ldmatrix.sync.aligned.m8n8.x4.trans.shared.b16 {%0,%1,%2,%3}, [%4];"
                 : "=r"(r0), "=r"(r1), "=r"(r2), "=r"(r3) : "r"(addr));
}
__device__ __forceinline__ void cpasync16(uint32_t s, const void* g) {
    asm volatile("cp.async.cg.shared.global [%0], [%1], 16;\n"
                 :: "r"(s), "l"(g) : "memory");
}

// ---------------- prep kernel ----------------
__global__ void __launch_bounds__(256)
swin_prep_kernel(const float* __restrict__ qkv_w,
                 const float* __restrict__ proj_w,
                 const float* __restrict__ rpb_table)
{
    int idx = blockIdx.x * 256 + threadIdx.x;   // grid 512 -> 131072
    if (idx < 3072) {
        int n = idx >> 5, k = idx & 31;
        g_qkvwT[idx] = __float2half(qkv_w[k * 96 + n]);
    }
    if (idx < 65536) {
        int n = idx >> 8, k = idx & 255;
        g_wpT[idx] = __float2half(proj_w[k * 256 + n]);
    }
    {
        int cls = idx >> 15, h = (idx >> 12) & 7, i = (idx >> 6) & 63, j = idx & 63;
        float v = -30000.0f;
        if (i < WD && j < WD) {
            int tri = i / 7, tci = i - tri * 7;
            int trj = j / 7, tcj = j - trj * 7;
            int li = tri * 13 + tci, lj = trj * 13 + tcj;
            v = rpb_table[(li - lj + 84) * 8 + h];
            int bot = cls & 1, rgt = (cls >> 1) & 1;
            int ri = (bot ? (tri < 4 ? 1 : 2) : 0) * 3 + (rgt ? (tci < 4 ? 1 : 2) : 0);
            int rj = (bot ? (trj < 4 ? 1 : 2) : 0) * 3 + (rgt ? (tcj < 4 ? 1 : 2) : 0);
            if (ri != rj) v -= 100.0f;
        }
        g_bias[idx] = __float2half(v);
    }
}

// ---------------- attention kernel (R11, unchanged) ----------------
#define XROW    68
#define OFF_X   0
#define OFF_KV  4352
#define OFF_PIX 14592
#define OFF_QB  14656
#define OFF_W   14752
#define AT_SMEM_WORDS 16672
#define AT_SMEM_BYTES (AT_SMEM_WORDS * 4)

__global__ void __launch_bounds__(256, 3)
swin_attn_kernel(const float* __restrict__ x,
                 const float* __restrict__ qkv_b)
{
    extern __shared__ uint32_t smw[];
    const int tid  = threadIdx.x;
    const int warp = tid >> 5;
    const int lane = tid & 31;
    const int bi   = blockIdx.x;
    const int b    = bi >> 7;
    const int rem  = bi & 127;
    const int w    = rem >> 1;
    const int half = rem & 1;
    const int wr   = w >> 3, wc = w & 7;
    const int cls  = (wr == 7 ? 1 : 0) | (wc == 7 ? 2 : 0);

    const float* xb = x + (size_t)b * HWPIX * EDIM;
    __half*      ob = g_mid + (size_t)b * HWPIX * EDIM;

    float* qb   = (float*)(smw + OFF_QB);
    int*   pixs = (int*)(smw + OFF_PIX);
    const uint32_t sb = (uint32_t)__cvta_generic_to_shared(smw);

    for (int i = tid; i < 384; i += 256) {
        int row = i >> 2, c = i & 3;
        cpasync16(sb + ((OFF_W + row * 20 + (c << 2)) << 2),
                  (const char*)g_qkvwT + row * 64 + c * 16);
    }
    asm volatile("cp.async.commit_group;\n" ::: "memory");

    if (tid < 96) qb[tid] = qkv_b[tid];
    if (tid < 64) {
        int p = 0;
        if (tid < WD) {
            int tr = tid / 7, tc = tid - tr * 7;
            int sh = wr * 7 + tr + 3; if (sh >= 56) sh -= 56;
            int sw = wc * 7 + tc + 3; if (sw >= 56) sw -= 56;
            p = sh * 56 + sw;
        }
        pixs[tid] = p;
    }
    for (int i = tid; i < 15 * XROW; i += 256)
        smw[OFF_X + 49 * XROW + i] = 0u;

    for (int i = tid; i < 1568; i += 256) {
        int t  = i >> 5;
        int c4 = (i & 31) << 2;
        int tr = t / 7, tc = t - tr * 7;
        int sh = wr * 7 + tr + 3; if (sh >= 56) sh -= 56;
        int sw = wc * 7 + tc + 3; if (sw >= 56) sw -= 56;
        float4 v = *(const float4*)&xb[(sh * 56 + sw) * EDIM + (half << 7) + c4];
        smw[OFF_X + t * XROW + (c4 >> 1)]     = packh2(v.x, v.y);
        smw[OFF_X + t * XROW + (c4 >> 1) + 1] = packh2(v.z, v.w);
    }
    asm volatile("cp.async.wait_group 0;\n" ::: "memory");
    __syncthreads();

    const int hl = warp >> 1;
    const int h  = (half << 2) + hl;
    const int wm = warp & 1;
    const int tb = wm << 5;
    const int r  = lane >> 2;
    const int cc = lane & 3;

    const uint32_t sbK = sb + ((OFF_KV + hl * 2560) << 2);
    const uint32_t sbV = sbK + (1280 << 2);
    const uint32_t sbW = sb + (OFF_W << 2);
    uint32_t* Ksm = smw + OFF_KV + hl * 2560;
    uint32_t* Vsm = Ksm + 1280;

    uint32_t xa[2][2][4];
    #pragma unroll
    for (int mt = 0; mt < 2; mt++)
        #pragma unroll
        for (int kt = 0; kt < 2; kt++) {
            uint32_t addr = sb +
                (((tb + (mt << 4) + (lane & 15)) * XROW +
                  (hl << 4) + (kt << 3) + ((lane >> 4) << 2)) << 2);
            ldsm4(xa[mt][kt][0], xa[mt][kt][1], xa[mt][kt][2], xa[mt][kt][3], addr);
        }

    uint32_t qf[2][2][4];
    #pragma unroll
    for (int sec = 0; sec < 3; sec++) {
        uint32_t bf[2][2][4];
        #pragma unroll
        for (int g = 0; g < 2; g++)
            #pragma unroll
            for (int kt = 0; kt < 2; kt++) {
                uint32_t addr = sbW +
                    (((sec * 32 + (g << 4) + (lane & 15)) * 20 +
                      (kt << 3) + ((lane >> 4) << 2)) << 2);
                ldsm4(bf[g][kt][0], bf[g][kt][1], bf[g][kt][2], bf[g][kt][3], addr);
            }
        #pragma unroll
        for (int mt = 0; mt < 2; mt++) {
            int tok0 = tb + (mt << 4) + r;
            #pragma unroll
            for (int nt = 0; nt < 4; nt++) {
                int n0 = nt << 3;
                float b0 = qb[sec * 32 + n0 + (cc << 1)];
                float b1 = qb[sec * 32 + n0 + (cc << 1) + 1];
                float c[4] = {b0, b1, b0, b1};
                int g = nt >> 1, hi = nt & 1;
                #pragma unroll
                for (int kt = 0; kt < 2; kt++) {
                    uint32_t bb[2];
                    bb[0] = hi ? bf[g][kt][1] : bf[g][kt][0];
                    bb[1] = hi ? bf[g][kt][3] : bf[g][kt][2];
                    mma_f16(c, xa[mt][kt], bb);
                }
                if (sec == 0) {
                    int kt2 = nt >> 1;
                    if ((nt & 1) == 0) {
                        qf[mt][kt2][0] = packh2(c[0] * SCALE, c[1] * SCALE);
                        qf[mt][kt2][1] = packh2(c[2] * SCALE, c[3] * SCALE);
                    } else {
                        qf[mt][kt2][2] = packh2(c[0] * SCALE, c[1] * SCALE);
                        qf[mt][kt2][3] = packh2(c[2] * SCALE, c[3] * SCALE);
                    }
                } else if (sec == 1) {
                    Ksm[tok0 * 20 + (nt << 2) + cc]       = packh2(c[0], c[1]);
                    Ksm[(tok0 + 8) * 20 + (nt << 2) + cc] = packh2(c[2], c[3]);
                } else {
                    Vsm[tok0 * 20 + (nt << 2) + cc]       = packh2(c[0], c[1]);
                    Vsm[(tok0 + 8) * 20 + (nt << 2) + cc] = packh2(c[2], c[3]);
                }
            }
        }
    }

    asm volatile("bar.sync %0, 64;" :: "r"(hl + 8) : "memory");

    const __half2* tb2 = (const __half2*)g_bias;

    #pragma unroll
    for (int mt = 0; mt < 2; mt++) {
        int q0 = tb + (mt << 4) + r;
        int base0 = ((((cls << 3) + h) << 6) + q0) << 5;
        int base1 = base0 + (8 << 5);

        float sacc[8][4];
        #pragma unroll
        for (int nt = 0; nt < 8; nt++)
            #pragma unroll
            for (int i = 0; i < 4; i++) sacc[nt][i] = 0.f;

        #pragma unroll
        for (int g = 0; g < 4; g++)
            #pragma unroll
            for (int kt = 0; kt < 2; kt++) {
                uint32_t r0, r1, r2, r3;
                uint32_t addr = sbK +
                    ((((g << 4) + (lane & 15)) * 20 + (kt << 3) + ((lane >> 4) << 2)) << 2);
                ldsm4(r0, r1, r2, r3, addr);
                uint32_t blo[2] = {r0, r2};
                uint32_t bhi[2] = {r1, r3};
                mma_f16(sacc[(g << 1)],     qf[mt][kt], blo);
                mma_f16(sacc[(g << 1) + 1], qf[mt][kt], bhi);
            }

        #pragma unroll
        for (int nt = 0; nt < 8; nt++) {
            float2 b0 = __half22float2(tb2[base0 + (nt << 2) + cc]);
            float2 b1 = __half22float2(tb2[base1 + (nt << 2) + cc]);
            sacc[nt][0] += b0.x; sacc[nt][1] += b0.y;
            sacc[nt][2] += b1.x; sacc[nt][3] += b1.y;
        }
        float m0 = -1e30f, m1 = -1e30f;
        #pragma unroll
        for (int nt = 0; nt < 8; nt++) {
            m0 = fmaxf(m0, fmaxf(sacc[nt][0], sacc[nt][1]));
            m1 = fmaxf(m1, fmaxf(sacc[nt][2], sacc[nt][3]));
        }
        m0 = fmaxf(m0, __shfl_xor_sync(0xffffffffu, m0, 1));
        m0 = fmaxf(m0, __shfl_xor_sync(0xffffffffu, m0, 2));
        m1 = fmaxf(m1, __shfl_xor_sync(0xffffffffu, m1, 1));
        m1 = fmaxf(m1, __shfl_xor_sync(0xffffffffu, m1, 2));
        float s0 = 0.f, s1 = 0.f;
        #pragma unroll
        for (int nt = 0; nt < 8; nt++) {
            sacc[nt][0] = __expf(sacc[nt][0] - m0); s0 += sacc[nt][0];
            sacc[nt][1] = __expf(sacc[nt][1] - m0); s0 += sacc[nt][1];
            sacc[nt][2] = __expf(sacc[nt][2] - m1); s1 += sacc[nt][2];
            sacc[nt][3] = __expf(sacc[nt][3] - m1); s1 += sacc[nt][3];
        }
        s0 += __shfl_xor_sync(0xffffffffu, s0, 1);
        s0 += __shfl_xor_sync(0xffffffffu, s0, 2);
        s1 += __shfl_xor_sync(0xffffffffu, s1, 1);
        s1 += __shfl_xor_sync(0xffffffffu, s1, 2);
        float inv0 = __frcp_rn(s0), inv1 = __frcp_rn(s1);

        uint32_t pf[4][4];
        #pragma unroll
        for (int nt = 0; nt < 8; nt++) {
            int kt2 = nt >> 1;
            uint32_t plo = packh2(sacc[nt][0] * inv0, sacc[nt][1] * inv0);
            uint32_t phi = packh2(sacc[nt][2] * inv1, sacc[nt][3] * inv1);
            if ((nt & 1) == 0) { pf[kt2][0] = plo; pf[kt2][1] = phi; }
            else               { pf[kt2][2] = plo; pf[kt2][3] = phi; }
        }

        float oacc[4][4];
        #pragma unroll
        for (int nt = 0; nt < 4; nt++)
            #pragma unroll
            for (int i = 0; i < 4; i++) oacc[nt][i] = 0.f;

        #pragma unroll
        for (int kt2 = 0; kt2 < 4; kt2++)
            #pragma unroll
            for (int vh2 = 0; vh2 < 2; vh2++) {
                uint32_t r0, r1, r2, r3;
                uint32_t addr = sbV +
                    ((((kt2 << 4) + (lane & 15)) * 20 + (vh2 << 3) + ((lane >> 4) << 2)) << 2);
                ldsm4t(r0, r1, r2, r3, addr);
                uint32_t blo[2] = {r0, r1};
                uint32_t bhi[2] = {r2, r3};
                mma_f16(oacc[(vh2 << 1)],     pf[kt2], blo);
                mma_f16(oacc[(vh2 << 1) + 1], pf[kt2], bhi);
            }

        #pragma unroll
        for (int ntv = 0; ntv < 4; ntv++) {
            int col = (h << 5) + (ntv << 3) + (cc << 1);
            if (q0 < WD)
                *(uint32_t*)&ob[pixs[q0] * EDIM + col] = packh2(oacc[ntv][0], oacc[ntv][1]);
            if (q0 + 8 < WD)
                *(uint32_t*)&ob[pixs[q0 + 8] * EDIM + col] = packh2(oacc[ntv][2], oacc[ntv][3]);
        }
    }
}

// ---------------------------------------------------------------------------
// Projection: out[M,N] = g_mid(fp16)[M,256] @ g_wpT^T + proj_b
// B tile (64x256) staged once; A in 8 K-chunks of 32 cols (stride-20 rows),
// double-buffered, 2-deep cp.async lookahead. 54.3KB smem -> 3 blocks/SM.
// ---------------------------------------------------------------------------
#define PJ_BOFF 0                        // 64 rows x 132 words
#define PJ_AOFF 8448                     // 2 bufs x (128 rows x 20 words)
#define PJ_SMEM_WORDS (8448 + 2 * 2560)  // 13568 words = 54.3KB
#define PJ_SMEM_BYTES (PJ_SMEM_WORDS * 4)

__global__ void __launch_bounds__(256, 3)
swin_proj_kernel(const float* __restrict__ pb,
                 float* __restrict__ out)
{
    extern __shared__ uint32_t pjw[];
    const int tid  = threadIdx.x;
    const int lane = tid & 31;
    const int warp = tid >> 5;
    const int mW = (warp >> 1) << 5;
    const int nW = (warp & 1) << 5;
    const int rowBase = blockIdx.y << 7;
    const int nBase   = blockIdx.x << 6;
    const __half* A16 = g_mid;
    const __half* B16 = g_wpT;
    const uint32_t sbase = (uint32_t)__cvta_generic_to_shared(pjw);

    float acc[2][4][4];
    #pragma unroll
    for (int mt = 0; mt < 2; mt++)
        #pragma unroll
        for (int nt = 0; nt < 4; nt++)
            #pragma unroll
            for (int i = 0; i < 4; i++)
                acc[mt][nt][i] = 0.f;

    // group 0: full B + A chunk 0
    #pragma unroll
    for (int l = 0; l < 8; l++) {
        int idx = tid + (l << 8);
        int row = idx >> 5, c16 = idx & 31;
        cpasync16(sbase + ((PJ_BOFF + row * 132 + (c16 << 2)) << 2),
                  &B16[(size_t)(nBase + row) * 256 + (c16 << 3)]);
    }
    #pragma unroll
    for (int l = 0; l < 2; l++) {
        int idx = tid + (l << 8);
        int row = idx >> 2, c = idx & 3;
        cpasync16(sbase + ((PJ_AOFF + row * 20 + (c << 2)) << 2),
                  &A16[(size_t)(rowBase + row) * 256 + (c << 3)]);
    }
    asm volatile("cp.async.commit_group;\n" ::: "memory");
    // group 1: A chunk 1
    #pragma unroll
    for (int l = 0; l < 2; l++) {
        int idx = tid + (l << 8);
        int row = idx >> 2, c = idx & 3;
        cpasync16(sbase + ((PJ_AOFF + 2560 + row * 20 + (c << 2)) << 2),
                  &A16[(size_t)(rowBase + row) * 256 + 32 + (c << 3)]);
    }
    asm volatile("cp.async.commit_group;\n" ::: "memory");

    const int r  = lane >> 2;
    const int cc = lane & 3;

    for (int kc = 0; kc < 8; kc++) {
        int buf = kc & 1;
        if (kc < 7) asm volatile("cp.async.wait_group 1;\n" ::: "memory");
        else        asm volatile("cp.async.wait_group 0;\n" ::: "memory");
        __syncthreads();

        const uint32_t* As = pjw + PJ_AOFF + buf * 2560;
        const uint32_t* Bs = pjw + PJ_BOFF;
        #pragma unroll
        for (int kt = 0; kt < 2; kt++) {
            int bko = (kc << 4) + (kt << 3);
            uint32_t a[2][4], bb[4][2];
            #pragma unroll
            for (int mt2 = 0; mt2 < 2; mt2++) {
                int rb = mW + (mt2 << 4) + r;
                const uint32_t* ap = As + rb * 20 + (kt << 3) + cc;
                a[mt2][0] = ap[0];
                a[mt2][1] = ap[160];
                a[mt2][2] = ap[4];
                a[mt2][3] = ap[164];
            }
            #pragma unroll
            for (int nt = 0; nt < 4; nt++) {
                int n = nW + (nt << 3) + r;
                const uint32_t* bp = Bs + n * 132 + bko + cc;
                bb[nt][0] = bp[0];
                bb[nt][1] = bp[4];
            }
            #pragma unroll
            for (int mt2 = 0; mt2 < 2; mt2++)
                #pragma unroll
                for (int nt = 0; nt < 4; nt++)
                    mma_f16(acc[mt2][nt], a[mt2], bb[nt]);
        }
        __syncthreads();

        if (kc < 6) {
            int k0 = (kc + 2) << 5;
            #pragma unroll
            for (int l = 0; l < 2; l++) {
                int idx = tid + (l << 8);
                int row = idx >> 2, c = idx & 3;
                cpasync16(sbase + ((PJ_AOFF + buf * 2560 + row * 20 + (c << 2)) << 2),
                          &A16[(size_t)(rowBase + row) * 256 + k0 + (c << 3)]);
            }
            asm volatile("cp.async.commit_group;\n" ::: "memory");
        }
    }

    #pragma unroll
    for (int mt2 = 0; mt2 < 2; mt2++) {
        int row = rowBase + mW + (mt2 << 4) + (lane >> 2);
        #pragma unroll
        for (int nt = 0; nt < 4; nt++) {
            int col = nBase + nW + (nt << 3) + ((lane & 3) << 1);
            float b0 = pb[col], b1 = pb[col + 1];
            float2 v0 = make_float2(acc[mt2][nt][0] + b0, acc[mt2][nt][1] + b1);
            float2 v1 = make_float2(acc[mt2][nt][2] + b0, acc[mt2][nt][3] + b1);
            *(float2*)&out[(size_t)row * 256 + col]       = v0;
            *(float2*)&out[(size_t)(row + 8) * 256 + col] = v1;
        }
    }
}

extern "C" void kernel_launch(void* const* d_in, const int* in_sizes, int n_in,
                              void* d_out, int out_size)
{
    (void)in_sizes; (void)n_in; (void)out_size;
    const float* x      = (const float*)d_in[0];
    const float* qkv_w  = (const float*)d_in[1];
    const float* qkv_b  = (const float*)d_in[2];
    const float* proj_w = (const float*)d_in[3];
    const float* proj_b = (const float*)d_in[4];
    const float* rpb    = (const float*)d_in[5];
    float* out = (float*)d_out;

    cudaFuncSetAttribute(swin_attn_kernel,
                         cudaFuncAttributeMaxDynamicSharedMemorySize, AT_SMEM_BYTES);
    cudaFuncSetAttribute(swin_proj_kernel,
                         cudaFuncAttributeMaxDynamicSharedMemorySize, PJ_SMEM_BYTES);

    swin_prep_kernel<<<512, 256>>>(qkv_w, proj_w, rpb);
    swin_attn_kernel<<<BATCH * 128, 256, AT_SMEM_BYTES>>>(x, qkv_b);
    swin_proj_kernel<<<dim3(4, 784), 256, PJ_SMEM_BYTES>>>(proj_b, out);
}

// round 13
// speedup vs baseline: 6.2513x; 1.0233x over previous
#include <cuda_runtime.h>
#include <cuda_fp16.h>
#include <cstdint>

// ---------------------------------------------------------------------------
// SWMSA: B=32, H=W=56, E=256, NH=8, HD=32, WS=7, WD=49, NW=64, SS=3
// R13 = R12 with proj fragment loads via ldmatrix (8 ldsm4/chunk instead of
//       32 scalar LDS). Attention unchanged (R11 champion).
// ---------------------------------------------------------------------------

#define BATCH 32
#define HWPIX 3136
#define EDIM  256
#define WD    49
#define SCALE 0.17677669529663687f   // 1/sqrt(32)

__device__ __align__(16) __half g_mid[(size_t)BATCH * HWPIX * EDIM];
__device__ __align__(16) __half g_wpT[65536];    // proj_w^T fp16 [n][k]
__device__ __align__(16) __half g_qkvwT[3072];   // qkv_w^T fp16 [n][k]
__device__ __align__(16) __half g_bias[4 * 8 * 64 * 64];

__device__ __forceinline__ void mma_f16(float* c, const uint32_t* a, const uint32_t* b) {
    asm volatile(
        "mma.sync.aligned.m16n8k16.row.col.f32.f16.f16.f32 "
        "{%0,%1,%2,%3}, {%4,%5,%6,%7}, {%8,%9}, {%0,%1,%2,%3};\n"
        : "+f"(c[0]), "+f"(c[1]), "+f"(c[2]), "+f"(c[3])
        : "r"(a[0]), "r"(a[1]), "r"(a[2]), "r"(a[3]), "r"(b[0]), "r"(b[1]));
}
__device__ __forceinline__ uint32_t h2u(__half2 h) { return *(uint32_t*)&h; }
__device__ __forceinline__ uint32_t packh2(float x, float y) {
    return h2u(__floats2half2_rn(x, y));
}
__device__ __forceinline__ void ldsm4(uint32_t& r0, uint32_t& r1, uint32_t& r2,
                                      uint32_t& r3, uint32_t addr) {
    asm volatile("ldmatrix.sync.aligned.m8n8.x4.shared.b16 {%0,%1,%2,%3}, [%4];"
                 : "=r"(r0), "=r"(r1), "=r"(r2), "=r"(r3) : "r"(addr));
}
__device__ __forceinline__ void ldsm4t(uint32_t& r0, uint32_t& r1, uint32_t& r2,
                                       uint32_t& r3, uint32_t addr) {
    asm volatile("ldmatrix.sync.aligned.m8n8.x4.trans.shared.b16 {%0,%1,%2,%3}, [%4];"
                 : "=r"(r0), "=r"(r1), "=r"(r2), "=r"(r3) : "r"(addr));
}
__device__ __forceinline__ void cpasync16(uint32_t s, const void* g) {
    asm volatile("cp.async.cg.shared.global [%0], [%1], 16;\n"
                 :: "r"(s), "l"(g) : "memory");
}

// ---------------- prep kernel ----------------
__global__ void __launch_bounds__(256)
swin_prep_kernel(const float* __restrict__ qkv_w,
                 const float* __restrict__ proj_w,
                 const float* __restrict__ rpb_table)
{
    int idx = blockIdx.x * 256 + threadIdx.x;   // grid 512 -> 131072
    if (idx < 3072) {
        int n = idx >> 5, k = idx & 31;
        g_qkvwT[idx] = __float2half(qkv_w[k * 96 + n]);
    }
    if (idx < 65536) {
        int n = idx >> 8, k = idx & 255;
        g_wpT[idx] = __float2half(proj_w[k * 256 + n]);
    }
    {
        int cls = idx >> 15, h = (idx >> 12) & 7, i = (idx >> 6) & 63, j = idx & 63;
        float v = -30000.0f;
        if (i < WD && j < WD) {
            int tri = i / 7, tci = i - tri * 7;
            int trj = j / 7, tcj = j - trj * 7;
            int li = tri * 13 + tci, lj = trj * 13 + tcj;
            v = rpb_table[(li - lj + 84) * 8 + h];
            int bot = cls & 1, rgt = (cls >> 1) & 1;
            int ri = (bot ? (tri < 4 ? 1 : 2) : 0) * 3 + (rgt ? (tci < 4 ? 1 : 2) : 0);
            int rj = (bot ? (trj < 4 ? 1 : 2) : 0) * 3 + (rgt ? (tcj < 4 ? 1 : 2) : 0);
            if (ri != rj) v -= 100.0f;
        }
        g_bias[idx] = __float2half(v);
    }
}

// ---------------- attention kernel (R11, unchanged) ----------------
#define XROW    68
#define OFF_X   0
#define OFF_KV  4352
#define OFF_PIX 14592
#define OFF_QB  14656
#define OFF_W   14752
#define AT_SMEM_WORDS 16672
#define AT_SMEM_BYTES (AT_SMEM_WORDS * 4)

__global__ void __launch_bounds__(256, 3)
swin_attn_kernel(const float* __restrict__ x,
                 const float* __restrict__ qkv_b)
{
    extern __shared__ uint32_t smw[];
    const int tid  = threadIdx.x;
    const int warp = tid >> 5;
    const int lane = tid & 31;
    const int bi   = blockIdx.x;
    const int b    = bi >> 7;
    const int rem  = bi & 127;
    const int w    = rem >> 1;
    const int half = rem & 1;
    const int wr   = w >> 3, wc = w & 7;
    const int cls  = (wr == 7 ? 1 : 0) | (wc == 7 ? 2 : 0);

    const float* xb = x + (size_t)b * HWPIX * EDIM;
    __half*      ob = g_mid + (size_t)b * HWPIX * EDIM;

    float* qb   = (float*)(smw + OFF_QB);
    int*   pixs = (int*)(smw + OFF_PIX);
    const uint32_t sb = (uint32_t)__cvta_generic_to_shared(smw);

    for (int i = tid; i < 384; i += 256) {
        int row = i >> 2, c = i & 3;
        cpasync16(sb + ((OFF_W + row * 20 + (c << 2)) << 2),
                  (const char*)g_qkvwT + row * 64 + c * 16);
    }
    asm volatile("cp.async.commit_group;\n" ::: "memory");

    if (tid < 96) qb[tid] = qkv_b[tid];
    if (tid < 64) {
        int p = 0;
        if (tid < WD) {
            int tr = tid / 7, tc = tid - tr * 7;
            int sh = wr * 7 + tr + 3; if (sh >= 56) sh -= 56;
            int sw = wc * 7 + tc + 3; if (sw >= 56) sw -= 56;
            p = sh * 56 + sw;
        }
        pixs[tid] = p;
    }
    for (int i = tid; i < 15 * XROW; i += 256)
        smw[OFF_X + 49 * XROW + i] = 0u;

    for (int i = tid; i < 1568; i += 256) {
        int t  = i >> 5;
        int c4 = (i & 31) << 2;
        int tr = t / 7, tc = t - tr * 7;
        int sh = wr * 7 + tr + 3; if (sh >= 56) sh -= 56;
        int sw = wc * 7 + tc + 3; if (sw >= 56) sw -= 56;
        float4 v = *(const float4*)&xb[(sh * 56 + sw) * EDIM + (half << 7) + c4];
        smw[OFF_X + t * XROW + (c4 >> 1)]     = packh2(v.x, v.y);
        smw[OFF_X + t * XROW + (c4 >> 1) + 1] = packh2(v.z, v.w);
    }
    asm volatile("cp.async.wait_group 0;\n" ::: "memory");
    __syncthreads();

    const int hl = warp >> 1;
    const int h  = (half << 2) + hl;
    const int wm = warp & 1;
    const int tb = wm << 5;
    const int r  = lane >> 2;
    const int cc = lane & 3;

    const uint32_t sbK = sb + ((OFF_KV + hl * 2560) << 2);
    const uint32_t sbV = sbK + (1280 << 2);
    const uint32_t sbW = sb + (OFF_W << 2);
    uint32_t* Ksm = smw + OFF_KV + hl * 2560;
    uint32_t* Vsm = Ksm + 1280;

    uint32_t xa[2][2][4];
    #pragma unroll
    for (int mt = 0; mt < 2; mt++)
        #pragma unroll
        for (int kt = 0; kt < 2; kt++) {
            uint32_t addr = sb +
                (((tb + (mt << 4) + (lane & 15)) * XROW +
                  (hl << 4) + (kt << 3) + ((lane >> 4) << 2)) << 2);
            ldsm4(xa[mt][kt][0], xa[mt][kt][1], xa[mt][kt][2], xa[mt][kt][3], addr);
        }

    uint32_t qf[2][2][4];
    #pragma unroll
    for (int sec = 0; sec < 3; sec++) {
        uint32_t bf[2][2][4];
        #pragma unroll
        for (int g = 0; g < 2; g++)
            #pragma unroll
            for (int kt = 0; kt < 2; kt++) {
                uint32_t addr = sbW +
                    (((sec * 32 + (g << 4) + (lane & 15)) * 20 +
                      (kt << 3) + ((lane >> 4) << 2)) << 2);
                ldsm4(bf[g][kt][0], bf[g][kt][1], bf[g][kt][2], bf[g][kt][3], addr);
            }
        #pragma unroll
        for (int mt = 0; mt < 2; mt++) {
            int tok0 = tb + (mt << 4) + r;
            #pragma unroll
            for (int nt = 0; nt < 4; nt++) {
                int n0 = nt << 3;
                float b0 = qb[sec * 32 + n0 + (cc << 1)];
                float b1 = qb[sec * 32 + n0 + (cc << 1) + 1];
                float c[4] = {b0, b1, b0, b1};
                int g = nt >> 1, hi = nt & 1;
                #pragma unroll
                for (int kt = 0; kt < 2; kt++) {
                    uint32_t bb[2];
                    bb[0] = hi ? bf[g][kt][1] : bf[g][kt][0];
                    bb[1] = hi ? bf[g][kt][3] : bf[g][kt][2];
                    mma_f16(c, xa[mt][kt], bb);
                }
                if (sec == 0) {
                    int kt2 = nt >> 1;
                    if ((nt & 1) == 0) {
                        qf[mt][kt2][0] = packh2(c[0] * SCALE, c[1] * SCALE);
                        qf[mt][kt2][1] = packh2(c[2] * SCALE, c[3] * SCALE);
                    } else {
                        qf[mt][kt2][2] = packh2(c[0] * SCALE, c[1] * SCALE);
                        qf[mt][kt2][3] = packh2(c[2] * SCALE, c[3] * SCALE);
                    }
                } else if (sec == 1) {
                    Ksm[tok0 * 20 + (nt << 2) + cc]       = packh2(c[0], c[1]);
                    Ksm[(tok0 + 8) * 20 + (nt << 2) + cc] = packh2(c[2], c[3]);
                } else {
                    Vsm[tok0 * 20 + (nt << 2) + cc]       = packh2(c[0], c[1]);
                    Vsm[(tok0 + 8) * 20 + (nt << 2) + cc] = packh2(c[2], c[3]);
                }
            }
        }
    }

    asm volatile("bar.sync %0, 64;" :: "r"(hl + 8) : "memory");

    const __half2* tb2 = (const __half2*)g_bias;

    #pragma unroll
    for (int mt = 0; mt < 2; mt++) {
        int q0 = tb + (mt << 4) + r;
        int base0 = ((((cls << 3) + h) << 6) + q0) << 5;
        int base1 = base0 + (8 << 5);

        float sacc[8][4];
        #pragma unroll
        for (int nt = 0; nt < 8; nt++)
            #pragma unroll
            for (int i = 0; i < 4; i++) sacc[nt][i] = 0.f;

        #pragma unroll
        for (int g = 0; g < 4; g++)
            #pragma unroll
            for (int kt = 0; kt < 2; kt++) {
                uint32_t r0, r1, r2, r3;
                uint32_t addr = sbK +
                    ((((g << 4) + (lane & 15)) * 20 + (kt << 3) + ((lane >> 4) << 2)) << 2);
                ldsm4(r0, r1, r2, r3, addr);
                uint32_t blo[2] = {r0, r2};
                uint32_t bhi[2] = {r1, r3};
                mma_f16(sacc[(g << 1)],     qf[mt][kt], blo);
                mma_f16(sacc[(g << 1) + 1], qf[mt][kt], bhi);
            }

        #pragma unroll
        for (int nt = 0; nt < 8; nt++) {
            float2 b0 = __half22float2(tb2[base0 + (nt << 2) + cc]);
            float2 b1 = __half22float2(tb2[base1 + (nt << 2) + cc]);
            sacc[nt][0] += b0.x; sacc[nt][1] += b0.y;
            sacc[nt][2] += b1.x; sacc[nt][3] += b1.y;
        }
        float m0 = -1e30f, m1 = -1e30f;
        #pragma unroll
        for (int nt = 0; nt < 8; nt++) {
            m0 = fmaxf(m0, fmaxf(sacc[nt][0], sacc[nt][1]));
            m1 = fmaxf(m1, fmaxf(sacc[nt][2], sacc[nt][3]));
        }
        m0 = fmaxf(m0, __shfl_xor_sync(0xffffffffu, m0, 1));
        m0 = fmaxf(m0, __shfl_xor_sync(0xffffffffu, m0, 2));
        m1 = fmaxf(m1, __shfl_xor_sync(0xffffffffu, m1, 1));
        m1 = fmaxf(m1, __shfl_xor_sync(0xffffffffu, m1, 2));
        float s0 = 0.f, s1 = 0.f;
        #pragma unroll
        for (int nt = 0; nt < 8; nt++) {
            sacc[nt][0] = __expf(sacc[nt][0] - m0); s0 += sacc[nt][0];
            sacc[nt][1] = __expf(sacc[nt][1] - m0); s0 += sacc[nt][1];
            sacc[nt][2] = __expf(sacc[nt][2] - m1); s1 += sacc[nt][2];
            sacc[nt][3] = __expf(sacc[nt][3] - m1); s1 += sacc[nt][3];
        }
        s0 += __shfl_xor_sync(0xffffffffu, s0, 1);
        s0 += __shfl_xor_sync(0xffffffffu, s0, 2);
        s1 += __shfl_xor_sync(0xffffffffu, s1, 1);
        s1 += __shfl_xor_sync(0xffffffffu, s1, 2);
        float inv0 = __frcp_rn(s0), inv1 = __frcp_rn(s1);

        uint32_t pf[4][4];
        #pragma unroll
        for (int nt = 0; nt < 8; nt++) {
            int kt2 = nt >> 1;
            uint32_t plo = packh2(sacc[nt][0] * inv0, sacc[nt][1] * inv0);
            uint32_t phi = packh2(sacc[nt][2] * inv1, sacc[nt][3] * inv1);
            if ((nt & 1) == 0) { pf[kt2][0] = plo; pf[kt2][1] = phi; }
            else               { pf[kt2][2] = plo; pf[kt2][3] = phi; }
        }

        float oacc[4][4];
        #pragma unroll
        for (int nt = 0; nt < 4; nt++)
            #pragma unroll
            for (int i = 0; i < 4; i++) oacc[nt][i] = 0.f;

        #pragma unroll
        for (int kt2 = 0; kt2 < 4; kt2++)
            #pragma unroll
            for (int vh2 = 0; vh2 < 2; vh2++) {
                uint32_t r0, r1, r2, r3;
                uint32_t addr = sbV +
                    ((((kt2 << 4) + (lane & 15)) * 20 + (vh2 << 3) + ((lane >> 4) << 2)) << 2);
                ldsm4t(r0, r1, r2, r3, addr);
                uint32_t blo[2] = {r0, r1};
                uint32_t bhi[2] = {r2, r3};
                mma_f16(oacc[(vh2 << 1)],     pf[kt2], blo);
                mma_f16(oacc[(vh2 << 1) + 1], pf[kt2], bhi);
            }

        #pragma unroll
        for (int ntv = 0; ntv < 4; ntv++) {
            int col = (h << 5) + (ntv << 3) + (cc << 1);
            if (q0 < WD)
                *(uint32_t*)&ob[pixs[q0] * EDIM + col] = packh2(oacc[ntv][0], oacc[ntv][1]);
            if (q0 + 8 < WD)
                *(uint32_t*)&ob[pixs[q0 + 8] * EDIM + col] = packh2(oacc[ntv][2], oacc[ntv][3]);
        }
    }
}

// ---------------------------------------------------------------------------
// Projection: out[M,N] = g_mid(fp16)[M,256] @ g_wpT^T + proj_b
// Fragment loads via ldmatrix (8 ldsm4/chunk). B staged once; A in 8 K-chunks
// of 32 (stride-20 rows), double-buffered, 2-deep lookahead. 3 blocks/SM.
// ---------------------------------------------------------------------------
#define PJ_BOFF 0                        // 64 rows x 132 words
#define PJ_AOFF 8448                     // 2 bufs x (128 rows x 20 words)
#define PJ_SMEM_WORDS (8448 + 2 * 2560)  // 13568 words = 54.3KB
#define PJ_SMEM_BYTES (PJ_SMEM_WORDS * 4)

__global__ void __launch_bounds__(256, 3)
swin_proj_kernel(const float* __restrict__ pb,
                 float* __restrict__ out)
{
    extern __shared__ uint32_t pjw[];
    const int tid  = threadIdx.x;
    const int lane = tid & 31;
    const int warp = tid >> 5;
    const int mW = (warp >> 1) << 5;
    const int nW = (warp & 1) << 5;
    const int rowBase = blockIdx.y << 7;
    const int nBase   = blockIdx.x << 6;
    const __half* A16 = g_mid;
    const __half* B16 = g_wpT;
    const uint32_t sbase = (uint32_t)__cvta_generic_to_shared(pjw);

    float acc[2][4][4];
    #pragma unroll
    for (int mt = 0; mt < 2; mt++)
        #pragma unroll
        for (int nt = 0; nt < 4; nt++)
            #pragma unroll
            for (int i = 0; i < 4; i++)
                acc[mt][nt][i] = 0.f;

    // group 0: full B + A chunk 0
    #pragma unroll
    for (int l = 0; l < 8; l++) {
        int idx = tid + (l << 8);
        int row = idx >> 5, c16 = idx & 31;
        cpasync16(sbase + ((PJ_BOFF + row * 132 + (c16 << 2)) << 2),
                  &B16[(size_t)(nBase + row) * 256 + (c16 << 3)]);
    }
    #pragma unroll
    for (int l = 0; l < 2; l++) {
        int idx = tid + (l << 8);
        int row = idx >> 2, c = idx & 3;
        cpasync16(sbase + ((PJ_AOFF + row * 20 + (c << 2)) << 2),
                  &A16[(size_t)(rowBase + row) * 256 + (c << 3)]);
    }
    asm volatile("cp.async.commit_group;\n" ::: "memory");
    // group 1: A chunk 1
    #pragma unroll
    for (int l = 0; l < 2; l++) {
        int idx = tid + (l << 8);
        int row = idx >> 2, c = idx & 3;
        cpasync16(sbase + ((PJ_AOFF + 2560 + row * 20 + (c << 2)) << 2),
                  &A16[(size_t)(rowBase + row) * 256 + 32 + (c << 3)]);
    }
    asm volatile("cp.async.commit_group;\n" ::: "memory");

    for (int kc = 0; kc < 8; kc++) {
        int buf = kc & 1;
        if (kc < 7) asm volatile("cp.async.wait_group 1;\n" ::: "memory");
        else        asm volatile("cp.async.wait_group 0;\n" ::: "memory");
        __syncthreads();

        const uint32_t sbA = sbase + ((PJ_AOFF + buf * 2560) << 2);
        const uint32_t sbB = sbase + (PJ_BOFF << 2);
        #pragma unroll
        for (int kt = 0; kt < 2; kt++) {
            int bko = (kc << 4) + (kt << 3);
            // A frags via ldmatrix (stride-20 rows, proven conflict-free)
            uint32_t a[2][4];
            #pragma unroll
            for (int mt2 = 0; mt2 < 2; mt2++) {
                uint32_t addr = sbA +
                    (((mW + (mt2 << 4) + (lane & 15)) * 20 +
                      (kt << 3) + ((lane >> 4) << 2)) << 2);
                ldsm4(a[mt2][0], a[mt2][1], a[mt2][2], a[mt2][3], addr);
            }
            // B frags via ldmatrix (stride-132 rows), split lo/hi per n-tile
            uint32_t bb[4][2];
            #pragma unroll
            for (int g = 0; g < 2; g++) {
                uint32_t r0, r1, r2, r3;
                uint32_t addr = sbB +
                    (((nW + (g << 4) + (lane & 15)) * 132 +
                      bko + ((lane >> 4) << 2)) << 2);
                ldsm4(r0, r1, r2, r3, addr);
                bb[(g << 1)][0]     = r0; bb[(g << 1)][1]     = r2;
                bb[(g << 1) + 1][0] = r1; bb[(g << 1) + 1][1] = r3;
            }
            #pragma unroll
            for (int mt2 = 0; mt2 < 2; mt2++)
                #pragma unroll
                for (int nt = 0; nt < 4; nt++)
                    mma_f16(acc[mt2][nt], a[mt2], bb[nt]);
        }
        __syncthreads();

        if (kc < 6) {
            int k0 = (kc + 2) << 5;
            #pragma unroll
            for (int l = 0; l < 2; l++) {
                int idx = tid + (l << 8);
                int row = idx >> 2, c = idx & 3;
                cpasync16(sbase + ((PJ_AOFF + buf * 2560 + row * 20 + (c << 2)) << 2),
                          &A16[(size_t)(rowBase + row) * 256 + k0 + (c << 3)]);
            }
            asm volatile("cp.async.commit_group;\n" ::: "memory");
        }
    }

    #pragma unroll
    for (int mt2 = 0; mt2 < 2; mt2++) {
        int row = rowBase + mW + (mt2 << 4) + (lane >> 2);
        #pragma unroll
        for (int nt = 0; nt < 4; nt++) {
            int col = nBase + nW + (nt << 3) + ((lane & 3) << 1);
            float b0 = pb[col], b1 = pb[col + 1];
            float2 v0 = make_float2(acc[mt2][nt][0] + b0, acc[mt2][nt][1] + b1);
            float2 v1 = make_float2(acc[mt2][nt][2] + b0, acc[mt2][nt][3] + b1);
            *(float2*)&out[(size_t)row * 256 + col]       = v0;
            *(float2*)&out[(size_t)(row + 8) * 256 + col] = v1;
        }
    }
}

extern "C" void kernel_launch(void* const* d_in, const int* in_sizes, int n_in,
                              void* d_out, int out_size)
{
    (void)in_sizes; (void)n_in; (void)out_size;
    const float* x      = (const float*)d_in[0];
    const float* qkv_w  = (const float*)d_in[1];
    const float* qkv_b  = (const float*)d_in[2];
    const float* proj_w = (const float*)d_in[3];
    const float* proj_b = (const float*)d_in[4];
    const float* rpb    = (const float*)d_in[5];
    float* out = (float*)d_out;

    cudaFuncSetAttribute(swin_attn_kernel,
                         cudaFuncAttributeMaxDynamicSharedMemorySize, AT_SMEM_BYTES);
    cudaFuncSetAttribute(swin_proj_kernel,
                         cudaFuncAttributeMaxDynamicSharedMemorySize, PJ_SMEM_BYTES);

    swin_prep_kernel<<<512, 256>>>(qkv_w, proj_w, rpb);
    swin_attn_kernel<<<BATCH * 128, 256, AT_SMEM_BYTES>>>(x, qkv_b);
    swin_proj_kernel<<<dim3(4, 784), 256, PJ_SMEM_BYTES>>>(proj_b, out);
}